// round 5
// baseline (speedup 1.0000x reference)
#include <cuda_runtime.h>

#define H_IMG 256
#define W_IMG 256
#define B_SZ 8
#define NPIX (B_SZ * H_IMG * W_IMG) /* 524288 */
#define BN_EPS 1e-5f

// -------- scratch (allocation-free: __device__ globals) --------
__device__ float g_y1[B_SZ * 32 * H_IMG * W_IMG];   // conv1 raw output (67 MB)
__device__ float g_y2[B_SZ * 64 * H_IMG * W_IMG];   // conv2 raw output (134 MB)
__device__ float g_w1t[3 * 9 * 32];                 // transposed weights [cin*9][cout]
__device__ float g_w2t[32 * 9 * 64];
__device__ float g_w3t[64 * 9 * 128];
__device__ float g_s1[2 * 32];                      // [sum(32), sumsq(32)]
__device__ float g_s2[2 * 64];
__device__ float g_s3[2 * 128];

__global__ void zero_stats_kernel() {
    int i = threadIdx.x;
    if (i < 64)  g_s1[i] = 0.f;
    if (i < 128) g_s2[i] = 0.f;
    if (i < 256) g_s3[i] = 0.f;
}

// w (OIHW) -> wt[(ci*9+t)*COUT + o]
template <int LAYER>
__global__ void transpose_w_kernel(const float* __restrict__ w) {
    constexpr int CIN  = (LAYER == 1) ? 3  : (LAYER == 2 ? 32 : 64);
    constexpr int COUT = (LAYER == 1) ? 32 : (LAYER == 2 ? 64 : 128);
    float* wt = (LAYER == 1) ? g_w1t : (LAYER == 2 ? g_w2t : g_w3t);
    int idx = blockIdx.x * blockDim.x + threadIdx.x;
    if (idx >= CIN * 9 * COUT) return;
    int o = idx % COUT;
    int r = idx / COUT;       // ci*9 + t
    int ci = r / 9, t = r % 9;
    wt[idx] = w[(o * CIN + ci) * 9 + t];
}

// Direct tiled conv: 16(w) x 64(h) spatial tile, 4 pixels per thread, 32 couts
// per block, CIN chunked in smem. Applies BN+leakyReLU of the previous layer on
// load (padding = 0 post-activation). Accumulates per-channel sum/sumsq of
// (conv + bias) into out_stats.
template <int LAYER, int CIN, int CHUNK, int COUT, bool HAS_BN, bool WRITE>
__global__ __launch_bounds__(256, 1) void conv_kernel(
    const float* __restrict__ image,      // only used when LAYER==1
    const float* __restrict__ in_gamma,   // BN params of previous layer
    const float* __restrict__ in_beta,
    const float* __restrict__ bias)       // this layer's conv bias
{
    const float* in = (LAYER == 1) ? image
                    : (LAYER == 2) ? (const float*)g_y1 : (const float*)g_y2;
    const float* wt = (LAYER == 1) ? (const float*)g_w1t
                    : (LAYER == 2) ? (const float*)g_w2t : (const float*)g_w3t;
    const float* in_stats = (LAYER == 2) ? (const float*)g_s1 : (const float*)g_s2;
    float* out       = (LAYER == 1) ? (float*)g_y1 : (float*)g_y2;
    float* out_stats = (LAYER == 1) ? g_s1 : (LAYER == 2 ? g_s2 : g_s3);

    constexpr int NG = COUT / 32;
    const int tx = threadIdx.x & 15;
    const int ty = threadIdx.x >> 4;
    const int tile_x = blockIdx.x * 16;
    const int tile_y = blockIdx.y * 64;          // 64-row tile
    const int g = blockIdx.z % NG;
    const int b = blockIdx.z / NG;

    __shared__ float s_in[CHUNK][66][18];        // 64+2 halo rows, 16+2 halo cols
    __shared__ float s_w[CHUNK * 9 * 32];
    __shared__ float s_scale[CHUNK], s_shift[CHUNK];

    float acc0[32], acc1[32], acc2[32], acc3[32];
#pragma unroll
    for (int o = 0; o < 32; o++) { acc0[o] = 0.f; acc1[o] = 0.f; acc2[o] = 0.f; acc3[o] = 0.f; }

    for (int c0 = 0; c0 < CIN; c0 += CHUNK) {
        __syncthreads();   // protect previous iteration's smem reads
        if (HAS_BN) {
            if (threadIdx.x < CHUNK) {
                int c = c0 + threadIdx.x;
                float mean = in_stats[c] * (1.f / NPIX);
                float var  = in_stats[CIN + c] * (1.f / NPIX) - mean * mean;
                float is   = rsqrtf(var + BN_EPS);
                float sc   = in_gamma[c] * is;
                s_scale[threadIdx.x] = sc;
                s_shift[threadIdx.x] = in_beta[c] - mean * sc;
            }
            __syncthreads();
        }
        // input tile: (CHUNK)x66x18, zero padded, BN+lrelu applied in-range
        for (int i = threadIdx.x; i < CHUNK * 66 * 18; i += 256) {
            int c  = i / (66 * 18);
            int r  = i - c * (66 * 18);
            int yy = r / 18;
            int xx = r - yy * 18;
            int gy = tile_y + yy - 1, gx = tile_x + xx - 1;
            float v = 0.f;
            if (gy >= 0 && gy < H_IMG && gx >= 0 && gx < W_IMG) {
                v = in[((b * CIN + c0 + c) * H_IMG + gy) * W_IMG + gx];
                if (HAS_BN) {
                    v = v * s_scale[c] + s_shift[c];
                    v = v > 0.f ? v : 0.01f * v;
                }
            }
            s_in[c][yy][xx] = v;
        }
        // weights: coalesced global (runs of 32 couts) + conflict-free smem store
        for (int i = threadIdx.x; i < CHUNK * 9 * 32; i += 256) {
            int rt = i >> 5;   // c*9 + t (relative)
            int o  = i & 31;
            s_w[i] = wt[(c0 * 9 + rt) * COUT + g * 32 + o];
        }
        __syncthreads();

#pragma unroll 1
        for (int c = 0; c < CHUNK; c++) {
#pragma unroll
            for (int t = 0; t < 9; t++) {
                float x0 = s_in[c][ty      + t / 3][tx + t % 3];
                float x1 = s_in[c][ty + 16 + t / 3][tx + t % 3];
                float x2 = s_in[c][ty + 32 + t / 3][tx + t % 3];
                float x3 = s_in[c][ty + 48 + t / 3][tx + t % 3];
                const float4* wv = (const float4*)&s_w[(c * 9 + t) * 32];
#pragma unroll
                for (int o4 = 0; o4 < 8; o4++) {
                    float4 w4 = wv[o4];
                    acc0[o4 * 4 + 0] = fmaf(x0, w4.x, acc0[o4 * 4 + 0]);
                    acc0[o4 * 4 + 1] = fmaf(x0, w4.y, acc0[o4 * 4 + 1]);
                    acc0[o4 * 4 + 2] = fmaf(x0, w4.z, acc0[o4 * 4 + 2]);
                    acc0[o4 * 4 + 3] = fmaf(x0, w4.w, acc0[o4 * 4 + 3]);
                    acc1[o4 * 4 + 0] = fmaf(x1, w4.x, acc1[o4 * 4 + 0]);
                    acc1[o4 * 4 + 1] = fmaf(x1, w4.y, acc1[o4 * 4 + 1]);
                    acc1[o4 * 4 + 2] = fmaf(x1, w4.z, acc1[o4 * 4 + 2]);
                    acc1[o4 * 4 + 3] = fmaf(x1, w4.w, acc1[o4 * 4 + 3]);
                    acc2[o4 * 4 + 0] = fmaf(x2, w4.x, acc2[o4 * 4 + 0]);
                    acc2[o4 * 4 + 1] = fmaf(x2, w4.y, acc2[o4 * 4 + 1]);
                    acc2[o4 * 4 + 2] = fmaf(x2, w4.z, acc2[o4 * 4 + 2]);
                    acc2[o4 * 4 + 3] = fmaf(x2, w4.w, acc2[o4 * 4 + 3]);
                    acc3[o4 * 4 + 0] = fmaf(x3, w4.x, acc3[o4 * 4 + 0]);
                    acc3[o4 * 4 + 1] = fmaf(x3, w4.y, acc3[o4 * 4 + 1]);
                    acc3[o4 * 4 + 2] = fmaf(x3, w4.z, acc3[o4 * 4 + 2]);
                    acc3[o4 * 4 + 3] = fmaf(x3, w4.w, acc3[o4 * 4 + 3]);
                }
            }
        }
    }

#pragma unroll
    for (int o = 0; o < 32; o++) {
        float bv = bias[g * 32 + o];
        acc0[o] += bv; acc1[o] += bv; acc2[o] += bv; acc3[o] += bv;
    }

    if (WRITE) {
        int gx = tile_x + tx;
        int base = ((b * COUT + g * 32) * H_IMG + tile_y + ty) * W_IMG + gx;
#pragma unroll
        for (int o = 0; o < 32; o++) {
            int p = base + o * (H_IMG * W_IMG);
            out[p]                 = acc0[o];
            out[p + 16 * W_IMG]    = acc1[o];
            out[p + 32 * W_IMG]    = acc2[o];
            out[p + 48 * W_IMG]    = acc3[o];
        }
    }

    // per-channel sum / sumsq over the 4 pixels: warp shuffle reduce,
    // one atomic per warp per channel
    int lane = threadIdx.x & 31;
#pragma unroll
    for (int o = 0; o < 32; o++) {
        float v  = acc0[o] + acc1[o] + acc2[o] + acc3[o];
        float v2 = acc0[o] * acc0[o] + acc1[o] * acc1[o]
                 + acc2[o] * acc2[o] + acc3[o] * acc3[o];
#pragma unroll
        for (int s = 16; s > 0; s >>= 1) {
            v  += __shfl_down_sync(0xffffffffu, v, s);
            v2 += __shfl_down_sync(0xffffffffu, v2, s);
        }
        if (lane == 0) {
            atomicAdd(&out_stats[g * 32 + o], v);
            atomicAdd(&out_stats[COUT + g * 32 + o], v2);
        }
    }
}

// Gather the three 7x7 patch sets (exact pixel copies). Output order:
// anchors [0,1176) | positives [1176,2352) | negatives [2352,3528)
__global__ void patch_kernel(const float* __restrict__ image,
                             const int* __restrict__ a_xy,
                             const int* __restrict__ p_xy,
                             const int* __restrict__ n_xy,
                             float* __restrict__ out)
{
    int idx = blockIdx.x * blockDim.x + threadIdx.x;
    if (idx >= 3 * B_SZ * 3 * 7 * 7) return;
    int which = idx / 1176;
    int r  = idx % 1176;
    int b  = r / 147;
    int r2 = r % 147;
    int c  = r2 / 49;
    int p  = r2 % 49;
    int dy = p / 7, dx = p % 7;
    const int* xy = (which == 0) ? a_xy : (which == 1 ? p_xy : n_xy);
    int row = xy[b * 64 + 62];   // [:, -1, 0]  (last of 32 patches)
    int col = xy[b * 64 + 63];   // [:, -1, 1]
    out[idx] = image[((b * 3 + c) * H_IMG + (row - 3 + dy)) * W_IMG + (col - 3 + dx)];
}

// Recompute z3 at the 8 gather points (reference uses n_xy here), apply BN3+lrelu.
__global__ void encode_kernel(const int* __restrict__ n_xy,
                              const float* __restrict__ bn2_g, const float* __restrict__ bn2_b,
                              const float* __restrict__ conv3_b,
                              const float* __restrict__ bn3_g, const float* __restrict__ bn3_b,
                              float* __restrict__ out)
{
    int b = blockIdx.x;
    int o = threadIdx.x;   // 128 threads = 128 output channels
    __shared__ float s_z2[64 * 9];
    int row = n_xy[b * 64 + 62];
    int col = n_xy[b * 64 + 63];
    // coords are in [3,252] -> the 3x3 neighborhood is interior, no padding needed
    for (int i = threadIdx.x; i < 576; i += 128) {
        int c = i / 9, p = i % 9;
        int ky = p / 3 - 1, kx = p % 3 - 1;
        float mean = g_s2[c] * (1.f / NPIX);
        float var  = g_s2[64 + c] * (1.f / NPIX) - mean * mean;
        float is   = rsqrtf(var + BN_EPS);
        float sc   = bn2_g[c] * is;
        float sh   = bn2_b[c] - mean * sc;
        float v = g_y2[((b * 64 + c) * H_IMG + row + ky) * W_IMG + col + kx];
        v = v * sc + sh;
        v = v > 0.f ? v : 0.01f * v;
        s_z2[i] = v;
    }
    __syncthreads();
    float acc = conv3_b[o];
    for (int i = 0; i < 576; i++)
        acc = fmaf(s_z2[i], g_w3t[i * 128 + o], acc);
    float mean = g_s3[o] * (1.f / NPIX);
    float var  = g_s3[128 + o] * (1.f / NPIX) - mean * mean;
    float is   = rsqrtf(var + BN_EPS);
    float v = (acc - mean) * is * bn3_g[o] + bn3_b[o];
    v = v > 0.f ? v : 0.01f * v;
    out[3528 + b * 128 + o] = v;
}

extern "C" void kernel_launch(void* const* d_in, const int* in_sizes, int n_in,
                              void* d_out, int out_size) {
    const float* image = (const float*)d_in[0];
    const int*   a_xy  = (const int*)d_in[1];
    const int*   p_xy  = (const int*)d_in[2];
    const int*   n_xy  = (const int*)d_in[3];
    const float* w1  = (const float*)d_in[4];
    const float* b1  = (const float*)d_in[5];
    const float* g1  = (const float*)d_in[6];
    const float* be1 = (const float*)d_in[7];
    const float* w2  = (const float*)d_in[8];
    const float* b2  = (const float*)d_in[9];
    const float* g2  = (const float*)d_in[10];
    const float* be2 = (const float*)d_in[11];
    const float* w3  = (const float*)d_in[12];
    const float* b3  = (const float*)d_in[13];
    const float* g3  = (const float*)d_in[14];
    const float* be3 = (const float*)d_in[15];
    // d_in[16]=recon_w, d_in[17]=recon_b : dead in the reference, unused.
    float* out = (float*)d_out;

    zero_stats_kernel<<<1, 256>>>();
    transpose_w_kernel<1><<<(3 * 9 * 32 + 255) / 256, 256>>>(w1);
    transpose_w_kernel<2><<<(32 * 9 * 64 + 255) / 256, 256>>>(w2);
    transpose_w_kernel<3><<<(64 * 9 * 128 + 255) / 256, 256>>>(w3);

    conv_kernel<1, 3, 3, 32, false, true><<<dim3(16, 4, 8), 256>>>(image, nullptr, nullptr, b1);
    conv_kernel<2, 32, 8, 64, true, true><<<dim3(16, 4, 16), 256>>>(nullptr, g1, be1, b2);
    conv_kernel<3, 64, 8, 128, true, false><<<dim3(16, 4, 32), 256>>>(nullptr, g2, be2, b3);

    patch_kernel<<<14, 256>>>(image, a_xy, p_xy, n_xy, out);
    encode_kernel<<<8, 128>>>(n_xy, g2, be2, b3, g3, be3, out);
}

// round 8
// speedup vs baseline: 1.4055x; 1.4055x over previous
#include <cuda_runtime.h>
#include <cuda_bf16.h>
#include <cstdint>

#define H_IMG 256
#define W_IMG 256
#define B_SZ 8
#define NPIX (B_SZ * H_IMG * W_IMG)
#define BN_EPS 1e-5f

// -------- scratch (allocation-free) --------
__device__ float g_y1[B_SZ * 32 * H_IMG * W_IMG];
__device__ float g_y2[B_SZ * 64 * H_IMG * W_IMG];
__device__ float g_w1t[3 * 9 * 32];
__device__ float g_w2t[32 * 9 * 64];
__device__ float g_w3t[64 * 9 * 128];
__device__ uint2 g_wb2[9 * 1 * 2 * 2 * 8 * 32];   // [tap][g][part][ks][nb][lane]
__device__ uint2 g_wb3[9 * 2 * 2 * 4 * 8 * 32];
__device__ float g_s1[2 * 32];
__device__ float g_s2[2 * 64];
__device__ float g_s3[2 * 128];

#define MMA_BF16(d, A0, A1, A2, A3, B0, B1) \
    asm volatile( \
        "mma.sync.aligned.m16n8k16.row.col.f32.bf16.bf16.f32 " \
        "{%0,%1,%2,%3}, {%4,%5,%6,%7}, {%8,%9}, {%0,%1,%2,%3};" \
        : "+f"(d[0]), "+f"(d[1]), "+f"(d[2]), "+f"(d[3]) \
        : "r"(A0), "r"(A1), "r"(A2), "r"(A3), "r"(B0), "r"(B1))

// ---------------- prep kernels ----------------
__global__ void zero_stats_kernel() {
    int i = threadIdx.x;
    if (i < 64)  g_s1[i] = 0.f;
    if (i < 128) g_s2[i] = 0.f;
    if (i < 256) g_s3[i] = 0.f;
}

// w (OIHW) -> wt[(ci*9+t)*COUT + o]
template <int LAYER>
__global__ void transpose_w_kernel(const float* __restrict__ w) {
    constexpr int CIN  = (LAYER == 1) ? 3  : (LAYER == 2 ? 32 : 64);
    constexpr int COUT = (LAYER == 1) ? 32 : (LAYER == 2 ? 64 : 128);
    float* wt = (LAYER == 1) ? g_w1t : (LAYER == 2 ? g_w2t : g_w3t);
    int idx = blockIdx.x * blockDim.x + threadIdx.x;
    if (idx >= CIN * 9 * COUT) return;
    int o = idx % COUT;
    int r = idx / COUT;
    int ci = r / 9, t = r % 9;
    wt[idx] = w[(o * CIN + ci) * 9 + t];
}

// Pack bf16 hi/lo weight fragments in exact m16n8k16 B-register order.
// Layout: [tap][g][part(0=hi,1=lo)][ks][nb][lane] of uint2 {b0,b1}.
// b0 = (k0,k0+1) at col n; b1 = (k0+8,k0+9); k0 = ks*16+2*(lane&3), n = nb*8+(lane>>2).
template <int CIN, int COUT>
__global__ void prep_wb_kernel(const float* __restrict__ w) {
    constexpr int KS = CIN / 16, NG = COUT / 64;
    uint2* wb = (CIN == 32) ? g_wb2 : g_wb3;
    int idx = blockIdx.x * blockDim.x + threadIdx.x;
    if (idx >= 9 * NG * 2 * KS * 8 * 32) return;
    int lane = idx & 31;
    int t = idx >> 5;
    int nb = t & 7; t >>= 3;
    int ks = t % KS; t /= KS;
    int part = t & 1; t >>= 1;
    int g = t % NG; int tap = t / NG;
    int o = g * 64 + nb * 8 + (lane >> 2);
    int k0 = ks * 16 + 2 * (lane & 3);

    auto enc = [&](int k) -> uint32_t {
        float x = w[(o * CIN + k) * 9 + tap];
        __nv_bfloat16 h = __float2bfloat16(x);
        __nv_bfloat16 v = h;
        if (part) v = __float2bfloat16(x - __bfloat162float(h));
        return (uint32_t)*reinterpret_cast<unsigned short*>(&v);
    };
    uint2 val;
    val.x = enc(k0) | (enc(k0 + 1) << 16);
    val.y = enc(k0 + 8) | (enc(k0 + 9) << 16);
    wb[idx] = val;
}

// ---------------- conv1: scalar (cin=3, tiny) ----------------
__global__ __launch_bounds__(256, 1) void conv1_kernel(const float* __restrict__ image,
                                                       const float* __restrict__ bias) {
    const int tx = threadIdx.x & 15, ty = threadIdx.x >> 4;
    const int tile_x = blockIdx.x * 16, tile_y = blockIdx.y * 64;
    const int b = blockIdx.z;
    __shared__ float s_in[3][66][18];
    __shared__ float s_w[3 * 9 * 32];
    float a0[32], a1[32], a2[32], a3[32];
#pragma unroll
    for (int o = 0; o < 32; o++) { a0[o] = a1[o] = a2[o] = a3[o] = 0.f; }
    for (int i = threadIdx.x; i < 3 * 66 * 18; i += 256) {
        int c = i / (66 * 18), r = i - c * (66 * 18);
        int yy = r / 18, xx = r - yy * 18;
        int gy = tile_y + yy - 1, gx = tile_x + xx - 1;
        float v = 0.f;
        if (gy >= 0 && gy < H_IMG && gx >= 0 && gx < W_IMG)
            v = image[((b * 3 + c) * H_IMG + gy) * W_IMG + gx];
        s_in[c][yy][xx] = v;
    }
    for (int i = threadIdx.x; i < 3 * 9 * 32; i += 256) s_w[i] = g_w1t[i];
    __syncthreads();
#pragma unroll 1
    for (int c = 0; c < 3; c++) {
#pragma unroll
        for (int t = 0; t < 9; t++) {
            float x0 = s_in[c][ty      + t / 3][tx + t % 3];
            float x1 = s_in[c][ty + 16 + t / 3][tx + t % 3];
            float x2 = s_in[c][ty + 32 + t / 3][tx + t % 3];
            float x3 = s_in[c][ty + 48 + t / 3][tx + t % 3];
            const float4* wv = (const float4*)&s_w[(c * 9 + t) * 32];
#pragma unroll
            for (int qq = 0; qq < 8; qq++) {
                float4 w4 = wv[qq];
                a0[qq*4+0]=fmaf(x0,w4.x,a0[qq*4+0]); a0[qq*4+1]=fmaf(x0,w4.y,a0[qq*4+1]);
                a0[qq*4+2]=fmaf(x0,w4.z,a0[qq*4+2]); a0[qq*4+3]=fmaf(x0,w4.w,a0[qq*4+3]);
                a1[qq*4+0]=fmaf(x1,w4.x,a1[qq*4+0]); a1[qq*4+1]=fmaf(x1,w4.y,a1[qq*4+1]);
                a1[qq*4+2]=fmaf(x1,w4.z,a1[qq*4+2]); a1[qq*4+3]=fmaf(x1,w4.w,a1[qq*4+3]);
                a2[qq*4+0]=fmaf(x2,w4.x,a2[qq*4+0]); a2[qq*4+1]=fmaf(x2,w4.y,a2[qq*4+1]);
                a2[qq*4+2]=fmaf(x2,w4.z,a2[qq*4+2]); a2[qq*4+3]=fmaf(x2,w4.w,a2[qq*4+3]);
                a3[qq*4+0]=fmaf(x3,w4.x,a3[qq*4+0]); a3[qq*4+1]=fmaf(x3,w4.y,a3[qq*4+1]);
                a3[qq*4+2]=fmaf(x3,w4.z,a3[qq*4+2]); a3[qq*4+3]=fmaf(x3,w4.w,a3[qq*4+3]);
            }
        }
    }
    int lane = threadIdx.x & 31;
#pragma unroll
    for (int o = 0; o < 32; o++) {
        float bv = bias[o];
        a0[o] += bv; a1[o] += bv; a2[o] += bv; a3[o] += bv;
        int p = ((b * 32 + o) * H_IMG + tile_y + ty) * W_IMG + tile_x + tx;
        g_y1[p] = a0[o]; g_y1[p + 16*W_IMG] = a1[o];
        g_y1[p + 32*W_IMG] = a2[o]; g_y1[p + 48*W_IMG] = a3[o];
        float v = a0[o]+a1[o]+a2[o]+a3[o];
        float v2 = a0[o]*a0[o]+a1[o]*a1[o]+a2[o]*a2[o]+a3[o]*a3[o];
#pragma unroll
        for (int s = 16; s > 0; s >>= 1) {
            v  += __shfl_down_sync(0xffffffffu, v, s);
            v2 += __shfl_down_sync(0xffffffffu, v2, s);
        }
        if (lane == 0) { atomicAdd(&g_s1[o], v); atomicAdd(&g_s1[32 + o], v2); }
    }
}

// ---------------- warp-MMA implicit-GEMM conv (conv2 / conv3) ----------------
// M=128 pixels (one row x 128 strip), N=64 couts. bf16 3-product split.
// dx handled by 3 accumulator sets; combined in epilogue via +-1 pixel shift.
template <int CIN, int COUT, bool WRITE>
__global__ __launch_bounds__(256, 1)
void conv_mma_kernel(const float* __restrict__ in_gamma,
                     const float* __restrict__ in_beta,
                     const float* __restrict__ bias)
{
    constexpr int KS   = CIN / 16;
    constexpr int NG   = COUT / 64;
    constexpr int AROW = CIN * 4 + 16;            // hi(CIN*2) | lo(CIN*2) | pad16
    constexpr int ADY  = 128 * AROW;
    constexpr int ASZ  = 3 * ADY;
    constexpr int BTAP = 2 * KS * 8 * 32 * 8;     // bytes per tap fragment tile
    constexpr int BSZ  = 3 * BTAP;
    constexpr int HW   = H_IMG * W_IMG;

    const float* in  = (CIN == 32) ? g_y1 : g_y2;
    const float* ist = (CIN == 32) ? g_s1 : g_s2;
    float* ost       = (CIN == 32) ? g_s2 : g_s3;
    const float* wt  = (CIN == 32) ? g_w2t : g_w3t;
    const uint2* wb  = (CIN == 32) ? g_wb2 : g_wb3;

    extern __shared__ char sm[];
    float* sScale = (float*)(sm + ASZ + BSZ);
    float* sShift = sScale + CIN;
    float* sEdge  = sShift + CIN;                 // [side][dy][c]
    float* sL     = sEdge + 6 * CIN;
    float* sR     = sL + 64;
    float* sBias  = sR + 64;

    const int tid = threadIdx.x, wid = tid >> 5, lane = tid & 31;
    const int g8 = lane >> 2, q = lane & 3;
    const int p0 = wid * 16;
    const int x0 = blockIdx.x * 128, y = blockIdx.y;
    const int b = blockIdx.z / NG, g = blockIdx.z % NG;

    if (tid < CIN) {
        float mean = ist[tid] * (1.f / NPIX);
        float var  = ist[CIN + tid] * (1.f / NPIX) - mean * mean;
        float is_  = rsqrtf(var + BN_EPS);
        float sc   = in_gamma[tid] * is_;
        sScale[tid] = sc; sShift[tid] = in_beta[tid] - mean * sc;
    }
    if (tid < 64) sBias[tid] = bias[g * 64 + tid];
    __syncthreads();

    // ---- stage A: 3 dy rows, BN+lrelu, bf16 hi/lo split ----
    for (int dy = 0; dy < 3; dy++) {
        char* aT = sm + dy * ADY;
        int ydy = y + dy - 1;
        if (ydy < 0 || ydy >= H_IMG) {
            for (int i = tid; i < ADY / 16; i += 256) ((uint4*)aT)[i] = make_uint4(0, 0, 0, 0);
        } else {
            const float* src = in + ((size_t)b * CIN * H_IMG + ydy) * W_IMG + x0;
            for (int i = tid; i < 128 * CIN; i += 256) {
                int p = i & 127, c = i >> 7;
                float v = src[(size_t)c * HW + p];
                v = fmaf(v, sScale[c], sShift[c]);
                v = v > 0.f ? v : 0.01f * v;
                __nv_bfloat16 h = __float2bfloat16(v);
                __nv_bfloat16 l = __float2bfloat16(v - __bfloat162float(h));
                __nv_bfloat16* row = (__nv_bfloat16*)(aT + p * AROW);
                row[c] = h;
                row[CIN + c] = l;
            }
        }
    }
    // ---- stage edge activations for exact strip-boundary fixup ----
    for (int i = tid; i < 6 * CIN; i += 256) {
        int side = i / (3 * CIN), rem = i % (3 * CIN);
        int dyy = rem / CIN, c = rem % CIN;
        int ydy = y + dyy - 1;
        int xx = side ? x0 + 128 : x0 - 1;
        float v = 0.f;
        if (ydy >= 0 && ydy < H_IMG && xx >= 0 && xx < W_IMG) {
            v = in[((size_t)b * CIN + c) * HW + (size_t)ydy * W_IMG + xx];
            v = fmaf(v, sScale[c], sShift[c]);
            v = v > 0.f ? v : 0.01f * v;
        }
        sEdge[i] = v;
    }
    __syncthreads();
    // fixup dot products (fp32 exact): thread t<128 -> (side, cout o)
    if (tid < 128) {
        int o = tid & 63, side = tid >> 6;
        float accf = 0.f;
        for (int dyy = 0; dyy < 3; dyy++)
            for (int c = 0; c < CIN; c++)
                accf = fmaf(sEdge[side * 3 * CIN + dyy * CIN + c],
                            wt[(c * 9 + dyy * 3 + (side ? 2 : 0)) * COUT + g * 64 + o], accf);
        (side ? sR : sL)[o] = accf;
    }

    float acc[3][8][4];
#pragma unroll
    for (int dx = 0; dx < 3; dx++)
#pragma unroll
        for (int nb = 0; nb < 8; nb++)
#pragma unroll
            for (int r = 0; r < 4; r++) acc[dx][nb][r] = 0.f;

    for (int dy = 0; dy < 3; dy++) {
        __syncthreads();
        // stage B fragments: taps dy*3 .. dy*3+2
        for (int i = tid; i < BSZ / 16; i += 256) {
            int t3 = i / (BTAP / 16), j = i % (BTAP / 16);
            const uint4* s = (const uint4*)((const char*)wb +
                             (size_t)((dy * 3 + t3) * NG + g) * BTAP);
            ((uint4*)(sm + ASZ + t3 * BTAP))[j] = s[j];
        }
        __syncthreads();

        const char* aBase = sm + dy * ADY + (p0 + g8) * AROW + 4 * q;
#pragma unroll
        for (int ks = 0; ks < KS; ks++) {
            uint32_t ah0 = *(const uint32_t*)(aBase + 32 * ks);
            uint32_t ah1 = *(const uint32_t*)(aBase + 32 * ks + 8 * AROW);
            uint32_t ah2 = *(const uint32_t*)(aBase + 32 * ks + 16);
            uint32_t ah3 = *(const uint32_t*)(aBase + 32 * ks + 8 * AROW + 16);
            uint32_t al0 = *(const uint32_t*)(aBase + 2 * CIN + 32 * ks);
            uint32_t al1 = *(const uint32_t*)(aBase + 2 * CIN + 32 * ks + 8 * AROW);
            uint32_t al2 = *(const uint32_t*)(aBase + 2 * CIN + 32 * ks + 16);
            uint32_t al3 = *(const uint32_t*)(aBase + 2 * CIN + 32 * ks + 8 * AROW + 16);
#pragma unroll
            for (int dx = 0; dx < 3; dx++) {
                const uint2* sB = (const uint2*)(sm + ASZ + dx * BTAP);
#pragma unroll
                for (int nb = 0; nb < 8; nb++) {
                    uint2 bh = sB[(ks * 8 + nb) * 32 + lane];
                    uint2 bl = sB[((KS + ks) * 8 + nb) * 32 + lane];
                    MMA_BF16(acc[dx][nb], ah0, ah1, ah2, ah3, bh.x, bh.y);
                    MMA_BF16(acc[dx][nb], ah0, ah1, ah2, ah3, bl.x, bl.y);
                    MMA_BF16(acc[dx][nb], al0, al1, al2, al3, bh.x, bh.y);
                }
            }
        }
    }
    __syncthreads();

    // ---- epilogue: out[p] = D0[p-1] + D1[p] + D2[p+1] + bias; stats fused ----
    float* S0 = (float*)sm;
    float* S2 = (float*)(sm + 128 * 65 * 4);
#pragma unroll
    for (int nb = 0; nb < 8; nb++)
#pragma unroll
        for (int r = 0; r < 4; r++) {
            int p = p0 + g8 + ((r >= 2) ? 8 : 0);
            int n = nb * 8 + 2 * q + (r & 1);
            S0[p * 65 + n] = acc[0][nb][r];
            S2[p * 65 + n] = acc[2][nb][r];
        }
    __syncthreads();

#pragma unroll
    for (int nb = 0; nb < 8; nb++) {
        float v[4];
#pragma unroll
        for (int r = 0; r < 4; r++) {
            int p = p0 + g8 + ((r >= 2) ? 8 : 0);
            int n = nb * 8 + 2 * q + (r & 1);
            float t = acc[1][nb][r];
            t += (p > 0)   ? S0[(p - 1) * 65 + n] : sL[n];
            t += (p < 127) ? S2[(p + 1) * 65 + n] : sR[n];
            t += sBias[n];
            v[r] = t;
            if (WRITE)
                g_y2[(((size_t)b * COUT + g * 64 + n) * H_IMG + y) * W_IMG + x0 + p] = t;
        }
        float se = v[0] + v[2], so = v[1] + v[3];
        float qe = v[0]*v[0] + v[2]*v[2], qo = v[1]*v[1] + v[3]*v[3];
#pragma unroll
        for (int sh = 4; sh <= 16; sh <<= 1) {
            se += __shfl_xor_sync(0xffffffffu, se, sh);
            so += __shfl_xor_sync(0xffffffffu, so, sh);
            qe += __shfl_xor_sync(0xffffffffu, qe, sh);
            qo += __shfl_xor_sync(0xffffffffu, qo, sh);
        }
        if (lane < 4) {
            int ne = nb * 8 + 2 * lane;
            atomicAdd(&ost[g * 64 + ne], se);
            atomicAdd(&ost[COUT + g * 64 + ne], qe);
            atomicAdd(&ost[g * 64 + ne + 1], so);
            atomicAdd(&ost[COUT + g * 64 + ne + 1], qo);
        }
    }
}

// ---------------- patch gather + encode ----------------
__global__ void patch_kernel(const float* __restrict__ image,
                             const int* __restrict__ a_xy, const int* __restrict__ p_xy,
                             const int* __restrict__ n_xy, float* __restrict__ out)
{
    int idx = blockIdx.x * blockDim.x + threadIdx.x;
    if (idx >= 3528) return;
    int which = idx / 1176;
    int r  = idx % 1176;
    int b  = r / 147, r2 = r % 147;
    int c  = r2 / 49, p = r2 % 49;
    int dy = p / 7, dx = p % 7;
    const int* xy = (which == 0) ? a_xy : (which == 1 ? p_xy : n_xy);
    int row = xy[b * 64 + 62], col = xy[b * 64 + 63];
    out[idx] = image[((b * 3 + c) * H_IMG + (row - 3 + dy)) * W_IMG + (col - 3 + dx)];
}

__global__ void encode_kernel(const int* __restrict__ n_xy,
                              const float* __restrict__ bn2_g, const float* __restrict__ bn2_b,
                              const float* __restrict__ conv3_b,
                              const float* __restrict__ bn3_g, const float* __restrict__ bn3_b,
                              float* __restrict__ out)
{
    int b = blockIdx.x, o = threadIdx.x;
    __shared__ float s_z2[576];
    int row = n_xy[b * 64 + 62], col = n_xy[b * 64 + 63];
    for (int i = threadIdx.x; i < 576; i += 128) {
        int c = i / 9, p = i % 9;
        int ky = p / 3 - 1, kx = p % 3 - 1;
        float mean = g_s2[c] * (1.f / NPIX);
        float var  = g_s2[64 + c] * (1.f / NPIX) - mean * mean;
        float is   = rsqrtf(var + BN_EPS);
        float sc   = bn2_g[c] * is;
        float sh   = bn2_b[c] - mean * sc;
        float v = g_y2[((b * 64 + c) * H_IMG + row + ky) * W_IMG + col + kx];
        v = v * sc + sh;
        v = v > 0.f ? v : 0.01f * v;
        s_z2[i] = v;
    }
    __syncthreads();
    float acc = conv3_b[o];
    for (int i = 0; i < 576; i++) acc = fmaf(s_z2[i], g_w3t[i * 128 + o], acc);
    float mean = g_s3[o] * (1.f / NPIX);
    float var  = g_s3[128 + o] * (1.f / NPIX) - mean * mean;
    float is   = rsqrtf(var + BN_EPS);
    float v = (acc - mean) * is * bn3_g[o] + bn3_b[o];
    v = v > 0.f ? v : 0.01f * v;
    out[3528 + b * 128 + o] = v;
}

extern "C" void kernel_launch(void* const* d_in, const int* in_sizes, int n_in,
                              void* d_out, int out_size) {
    const float* image = (const float*)d_in[0];
    const int*   a_xy  = (const int*)d_in[1];
    const int*   p_xy  = (const int*)d_in[2];
    const int*   n_xy  = (const int*)d_in[3];
    const float* w1  = (const float*)d_in[4];
    const float* b1  = (const float*)d_in[5];
    const float* g1  = (const float*)d_in[6];
    const float* be1 = (const float*)d_in[7];
    const float* w2  = (const float*)d_in[8];
    const float* b2  = (const float*)d_in[9];
    const float* g2  = (const float*)d_in[10];
    const float* be2 = (const float*)d_in[11];
    const float* w3  = (const float*)d_in[12];
    const float* b3  = (const float*)d_in[13];
    const float* g3  = (const float*)d_in[14];
    const float* be3 = (const float*)d_in[15];
    float* out = (float*)d_out;

    // smem: A(3*128*(CIN*4+16)) + B(3*2*KS*2048) + extras((8*CIN+192)*4)
    const int SM2 = 3*128*(32*4+16) + 3*2*2*2048 + (8*32+192)*4;     // 81,664
    const int SM3 = 3*128*(64*4+16) + 3*2*4*2048 + (8*64+192)*4;     // 156,416
    cudaFuncSetAttribute(conv_mma_kernel<32, 64, true>,
                         cudaFuncAttributeMaxDynamicSharedMemorySize, SM2);
    cudaFuncSetAttribute(conv_mma_kernel<64, 128, false>,
                         cudaFuncAttributeMaxDynamicSharedMemorySize, SM3);

    zero_stats_kernel<<<1, 256>>>();
    transpose_w_kernel<1><<<4, 256>>>(w1);
    transpose_w_kernel<2><<<72, 256>>>(w2);
    transpose_w_kernel<3><<<288, 256>>>(w3);
    prep_wb_kernel<32, 64><<<36, 256>>>(w2);
    prep_wb_kernel<64, 128><<<144, 256>>>(w3);

    conv1_kernel<<<dim3(16, 4, 8), 256>>>(image, b1);
    conv_mma_kernel<32, 64, true><<<dim3(2, 256, 8), 256, SM2>>>(g1, be1, b2);
    conv_mma_kernel<64, 128, false><<<dim3(2, 256, 16), 256, SM3>>>(g2, be2, b3);

    patch_kernel<<<14, 256>>>(image, a_xy, p_xy, n_xy, out);
    encode_kernel<<<8, 128>>>(n_xy, g2, be2, b3, g3, be3, out);
}

// round 9
// speedup vs baseline: 1.5113x; 1.0753x over previous
#include <cuda_runtime.h>
#include <cuda_bf16.h>
#include <cstdint>

#define H_IMG 256
#define W_IMG 256
#define B_SZ 8
#define NPIX (B_SZ * H_IMG * W_IMG)
#define BN_EPS 1e-5f

// -------- scratch (allocation-free) --------
__device__ float g_y1[B_SZ * 32 * H_IMG * W_IMG];
__device__ float g_y2[B_SZ * 64 * H_IMG * W_IMG];
__device__ float g_w1t[3 * 9 * 32];
__device__ float g_w2t[32 * 9 * 64];
__device__ float g_w3t[64 * 9 * 128];
__device__ uint2 g_wb2[9 * 1 * 2 * 2 * 8 * 32];   // [tap][g][part][ks][nb][lane]
__device__ uint2 g_wb3[9 * 2 * 2 * 4 * 8 * 32];
__device__ float g_s1[2 * 32];
__device__ float g_s2[2 * 64];
__device__ float g_s3[2 * 128];

#define MMA_BF16(d, A0, A1, A2, A3, B0, B1) \
    asm volatile( \
        "mma.sync.aligned.m16n8k16.row.col.f32.bf16.bf16.f32 " \
        "{%0,%1,%2,%3}, {%4,%5,%6,%7}, {%8,%9}, {%0,%1,%2,%3};" \
        : "+f"(d[0]), "+f"(d[1]), "+f"(d[2]), "+f"(d[3]) \
        : "r"(A0), "r"(A1), "r"(A2), "r"(A3), "r"(B0), "r"(B1))

// ---------------- fused prep (one launch: zero stats + transposes + B packing) ----------------
template <int CIN, int COUT>
__device__ __forceinline__ void prep_wb_one(const float* __restrict__ w, int idx) {
    constexpr int KS = CIN / 16, NG = COUT / 64;
    uint2* wb = (CIN == 32) ? g_wb2 : g_wb3;
    int lane = idx & 31;
    int t = idx >> 5;
    int nb = t & 7; t >>= 3;
    int ks = t % KS; t /= KS;
    int part = t & 1; t >>= 1;
    int g = t % NG; int tap = t / NG;
    int o = g * 64 + nb * 8 + (lane >> 2);
    int k0 = ks * 16 + 2 * (lane & 3);
    auto enc = [&](int k) -> uint32_t {
        float x = w[(o * CIN + k) * 9 + tap];
        __nv_bfloat16 h = __float2bfloat16(x);
        __nv_bfloat16 v = h;
        if (part) v = __float2bfloat16(x - __bfloat162float(h));
        return (uint32_t)*reinterpret_cast<unsigned short*>(&v);
    };
    uint2 val;
    val.x = enc(k0) | (enc(k0 + 1) << 16);
    val.y = enc(k0 + 8) | (enc(k0 + 9) << 16);
    wb[idx] = val;
}

template <int CIN, int COUT>
__device__ __forceinline__ void transpose_one(const float* __restrict__ w, float* wt, int idx) {
    int o = idx % COUT;
    int r = idx / COUT;
    int ci = r / 9, t = r % 9;
    wt[idx] = w[(o * CIN + ci) * 9 + t];
}

__global__ void prep_all_kernel(const float* __restrict__ w1,
                                const float* __restrict__ w2,
                                const float* __restrict__ w3) {
    int idx = blockIdx.x * 256 + threadIdx.x;
    if (idx < 448) {
        if (idx < 64) g_s1[idx] = 0.f;
        else if (idx < 192) g_s2[idx - 64] = 0.f;
        else g_s3[idx - 192] = 0.f;
        return;
    }
    idx -= 448;
    if (idx < 864)  { transpose_one<3, 32>(w1, g_w1t, idx); return; }
    idx -= 864;
    if (idx < 18432) { transpose_one<32, 64>(w2, g_w2t, idx); return; }
    idx -= 18432;
    if (idx < 73728) { transpose_one<64, 128>(w3, g_w3t, idx); return; }
    idx -= 73728;
    if (idx < 9216)  { prep_wb_one<32, 64>(w2, idx); return; }
    idx -= 9216;
    if (idx < 36864) { prep_wb_one<64, 128>(w3, idx); return; }
}

// ---------------- conv1: scalar (cin=3, tiny) ----------------
__global__ __launch_bounds__(256, 1) void conv1_kernel(const float* __restrict__ image,
                                                       const float* __restrict__ bias) {
    const int tx = threadIdx.x & 15, ty = threadIdx.x >> 4;
    const int tile_x = blockIdx.x * 16, tile_y = blockIdx.y * 64;
    const int b = blockIdx.z;
    __shared__ float s_in[3][66][18];
    __shared__ float s_w[3 * 9 * 32];
    float a0[32], a1[32], a2[32], a3[32];
#pragma unroll
    for (int o = 0; o < 32; o++) { a0[o] = a1[o] = a2[o] = a3[o] = 0.f; }
    for (int i = threadIdx.x; i < 3 * 66 * 18; i += 256) {
        int c = i / (66 * 18), r = i - c * (66 * 18);
        int yy = r / 18, xx = r - yy * 18;
        int gy = tile_y + yy - 1, gx = tile_x + xx - 1;
        float v = 0.f;
        if (gy >= 0 && gy < H_IMG && gx >= 0 && gx < W_IMG)
            v = image[((b * 3 + c) * H_IMG + gy) * W_IMG + gx];
        s_in[c][yy][xx] = v;
    }
    for (int i = threadIdx.x; i < 3 * 9 * 32; i += 256) s_w[i] = g_w1t[i];
    __syncthreads();
#pragma unroll 1
    for (int c = 0; c < 3; c++) {
#pragma unroll
        for (int t = 0; t < 9; t++) {
            float x0 = s_in[c][ty      + t / 3][tx + t % 3];
            float x1 = s_in[c][ty + 16 + t / 3][tx + t % 3];
            float x2 = s_in[c][ty + 32 + t / 3][tx + t % 3];
            float x3 = s_in[c][ty + 48 + t / 3][tx + t % 3];
            const float4* wv = (const float4*)&s_w[(c * 9 + t) * 32];
#pragma unroll
            for (int qq = 0; qq < 8; qq++) {
                float4 w4 = wv[qq];
                a0[qq*4+0]=fmaf(x0,w4.x,a0[qq*4+0]); a0[qq*4+1]=fmaf(x0,w4.y,a0[qq*4+1]);
                a0[qq*4+2]=fmaf(x0,w4.z,a0[qq*4+2]); a0[qq*4+3]=fmaf(x0,w4.w,a0[qq*4+3]);
                a1[qq*4+0]=fmaf(x1,w4.x,a1[qq*4+0]); a1[qq*4+1]=fmaf(x1,w4.y,a1[qq*4+1]);
                a1[qq*4+2]=fmaf(x1,w4.z,a1[qq*4+2]); a1[qq*4+3]=fmaf(x1,w4.w,a1[qq*4+3]);
                a2[qq*4+0]=fmaf(x2,w4.x,a2[qq*4+0]); a2[qq*4+1]=fmaf(x2,w4.y,a2[qq*4+1]);
                a2[qq*4+2]=fmaf(x2,w4.z,a2[qq*4+2]); a2[qq*4+3]=fmaf(x2,w4.w,a2[qq*4+3]);
                a3[qq*4+0]=fmaf(x3,w4.x,a3[qq*4+0]); a3[qq*4+1]=fmaf(x3,w4.y,a3[qq*4+1]);
                a3[qq*4+2]=fmaf(x3,w4.z,a3[qq*4+2]); a3[qq*4+3]=fmaf(x3,w4.w,a3[qq*4+3]);
            }
        }
    }
    int lane = threadIdx.x & 31;
#pragma unroll
    for (int o = 0; o < 32; o++) {
        float bv = bias[o];
        a0[o] += bv; a1[o] += bv; a2[o] += bv; a3[o] += bv;
        int p = ((b * 32 + o) * H_IMG + tile_y + ty) * W_IMG + tile_x + tx;
        g_y1[p] = a0[o]; g_y1[p + 16*W_IMG] = a1[o];
        g_y1[p + 32*W_IMG] = a2[o]; g_y1[p + 48*W_IMG] = a3[o];
        float v = a0[o]+a1[o]+a2[o]+a3[o];
        float v2 = a0[o]*a0[o]+a1[o]*a1[o]+a2[o]*a2[o]+a3[o]*a3[o];
#pragma unroll
        for (int s = 16; s > 0; s >>= 1) {
            v  += __shfl_down_sync(0xffffffffu, v, s);
            v2 += __shfl_down_sync(0xffffffffu, v2, s);
        }
        if (lane == 0) { atomicAdd(&g_s1[o], v); atomicAdd(&g_s1[32 + o], v2); }
    }
}

// ---------------- warp-MMA implicit-GEMM conv (conv2 / conv3) ----------------
// M=128 pixels (row strip) x N=64 couts. Warp = 32M x 32N (2 M-tiles, 4 nb groups):
// halves B fragment LDS per MMA vs 16Mx64N mapping. bf16 3-product split.
template <int CIN, int COUT, bool WRITE>
__global__ __launch_bounds__(256, 1)
void conv_mma_kernel(const float* __restrict__ in_gamma,
                     const float* __restrict__ in_beta,
                     const float* __restrict__ bias)
{
    constexpr int KS   = CIN / 16;
    constexpr int NG   = COUT / 64;
    constexpr int AROW = CIN * 4 + 16;            // hi(CIN*2) | lo(CIN*2) | pad16
    constexpr int ADY  = 128 * AROW;
    constexpr int ASZ  = 3 * ADY;
    constexpr int BTAP = 2 * KS * 8 * 32 * 8;     // bytes per tap fragment tile
    constexpr int BSZ  = 3 * BTAP;
    constexpr int HW   = H_IMG * W_IMG;

    const float* in  = (CIN == 32) ? g_y1 : g_y2;
    const float* ist = (CIN == 32) ? g_s1 : g_s2;
    float* ost       = (CIN == 32) ? g_s2 : g_s3;
    const float* wt  = (CIN == 32) ? g_w2t : g_w3t;
    const uint2* wb  = (CIN == 32) ? g_wb2 : g_wb3;

    extern __shared__ char sm[];
    float* sScale = (float*)(sm + ASZ + BSZ);
    float* sShift = sScale + CIN;
    float* sEdge  = sShift + CIN;                 // [side][dy][c]
    float* sL     = sEdge + 6 * CIN;
    float* sR     = sL + 64;
    float* sBias  = sR + 64;

    const int tid = threadIdx.x, wid = tid >> 5, lane = tid & 31;
    const int g8 = lane >> 2, q = lane & 3;
    const int mc = wid >> 1, nh = wid & 1;        // warp -> (M chunk of 32, N half of 32)
    const int p0 = mc * 32;
    const int x0 = blockIdx.x * 128, y = blockIdx.y;
    const int b = blockIdx.z / NG, g = blockIdx.z % NG;

    if (tid < CIN) {
        float mean = ist[tid] * (1.f / NPIX);
        float var  = ist[CIN + tid] * (1.f / NPIX) - mean * mean;
        float is_  = rsqrtf(var + BN_EPS);
        float sc   = in_gamma[tid] * is_;
        sScale[tid] = sc; sShift[tid] = in_beta[tid] - mean * sc;
    }
    if (tid < 64) sBias[tid] = bias[g * 64 + tid];
    __syncthreads();

    // ---- stage A: 3 dy rows, BN+lrelu, bf16 hi/lo split ----
    for (int dy = 0; dy < 3; dy++) {
        char* aT = sm + dy * ADY;
        int ydy = y + dy - 1;
        if (ydy < 0 || ydy >= H_IMG) {
            for (int i = tid; i < ADY / 16; i += 256) ((uint4*)aT)[i] = make_uint4(0, 0, 0, 0);
        } else {
            const float* src = in + ((size_t)b * CIN * H_IMG + ydy) * W_IMG + x0;
            for (int i = tid; i < 128 * CIN; i += 256) {
                int p = i & 127, c = i >> 7;
                float v = src[(size_t)c * HW + p];
                v = fmaf(v, sScale[c], sShift[c]);
                v = v > 0.f ? v : 0.01f * v;
                __nv_bfloat16 h = __float2bfloat16(v);
                __nv_bfloat16 l = __float2bfloat16(v - __bfloat162float(h));
                __nv_bfloat16* row = (__nv_bfloat16*)(aT + p * AROW);
                row[c] = h;
                row[CIN + c] = l;
            }
        }
    }
    // ---- edge activations for exact strip-boundary fixup ----
    for (int i = tid; i < 6 * CIN; i += 256) {
        int side = i / (3 * CIN), rem = i % (3 * CIN);
        int dyy = rem / CIN, c = rem % CIN;
        int ydy = y + dyy - 1;
        int xx = side ? x0 + 128 : x0 - 1;
        float v = 0.f;
        if (ydy >= 0 && ydy < H_IMG && xx >= 0 && xx < W_IMG) {
            v = in[((size_t)b * CIN + c) * HW + (size_t)ydy * W_IMG + xx];
            v = fmaf(v, sScale[c], sShift[c]);
            v = v > 0.f ? v : 0.01f * v;
        }
        sEdge[i] = v;
    }
    __syncthreads();
    if (tid < 128) {
        int o = tid & 63, side = tid >> 6;
        float accf = 0.f;
        for (int dyy = 0; dyy < 3; dyy++)
            for (int c = 0; c < CIN; c++)
                accf = fmaf(sEdge[side * 3 * CIN + dyy * CIN + c],
                            wt[(c * 9 + dyy * 3 + (side ? 2 : 0)) * COUT + g * 64 + o], accf);
        (side ? sR : sL)[o] = accf;
    }

    float acc[2][3][4][4];
#pragma unroll
    for (int mt = 0; mt < 2; mt++)
#pragma unroll
        for (int dx = 0; dx < 3; dx++)
#pragma unroll
            for (int nb = 0; nb < 4; nb++)
#pragma unroll
                for (int r = 0; r < 4; r++) acc[mt][dx][nb][r] = 0.f;

    for (int dy = 0; dy < 3; dy++) {
        __syncthreads();
        for (int i = tid; i < BSZ / 16; i += 256) {
            int t3 = i / (BTAP / 16), j = i % (BTAP / 16);
            const uint4* s = (const uint4*)((const char*)wb +
                             (size_t)((dy * 3 + t3) * NG + g) * BTAP);
            ((uint4*)(sm + ASZ + t3 * BTAP))[j] = s[j];
        }
        __syncthreads();

        const char* aB = sm + dy * ADY + (p0 + g8) * AROW + 4 * q;
#pragma unroll
        for (int ks = 0; ks < KS; ks++) {
            uint32_t ah[2][4], al[2][4];
#pragma unroll
            for (int mt = 0; mt < 2; mt++) {
                const char* base = aB + mt * 16 * AROW + 32 * ks;
                ah[mt][0] = *(const uint32_t*)(base);
                ah[mt][1] = *(const uint32_t*)(base + 8 * AROW);
                ah[mt][2] = *(const uint32_t*)(base + 16);
                ah[mt][3] = *(const uint32_t*)(base + 8 * AROW + 16);
                al[mt][0] = *(const uint32_t*)(base + 2 * CIN);
                al[mt][1] = *(const uint32_t*)(base + 2 * CIN + 8 * AROW);
                al[mt][2] = *(const uint32_t*)(base + 2 * CIN + 16);
                al[mt][3] = *(const uint32_t*)(base + 2 * CIN + 8 * AROW + 16);
            }
#pragma unroll
            for (int dx = 0; dx < 3; dx++) {
                const uint2* sB = (const uint2*)(sm + ASZ + dx * BTAP);
#pragma unroll
                for (int nb = 0; nb < 4; nb++) {
                    int nbg = nh * 4 + nb;
                    uint2 bh = sB[(ks * 8 + nbg) * 32 + lane];
                    uint2 bl = sB[((KS + ks) * 8 + nbg) * 32 + lane];
#pragma unroll
                    for (int mt = 0; mt < 2; mt++) {
                        MMA_BF16(acc[mt][dx][nb], ah[mt][0], ah[mt][1], ah[mt][2], ah[mt][3], bh.x, bh.y);
                        MMA_BF16(acc[mt][dx][nb], ah[mt][0], ah[mt][1], ah[mt][2], ah[mt][3], bl.x, bl.y);
                        MMA_BF16(acc[mt][dx][nb], al[mt][0], al[mt][1], al[mt][2], al[mt][3], bh.x, bh.y);
                    }
                }
            }
        }
    }
    __syncthreads();

    // ---- epilogue: out[p] = D0[p-1] + D1[p] + D2[p+1] + bias; stats fused ----
    float* S0 = (float*)sm;
    float* S2 = (float*)(sm + 128 * 65 * 4);
#pragma unroll
    for (int mt = 0; mt < 2; mt++)
#pragma unroll
        for (int nb = 0; nb < 4; nb++)
#pragma unroll
            for (int r = 0; r < 4; r++) {
                int p = p0 + mt * 16 + g8 + ((r >= 2) ? 8 : 0);
                int n = nh * 32 + nb * 8 + 2 * q + (r & 1);
                S0[p * 65 + n] = acc[mt][0][nb][r];
                S2[p * 65 + n] = acc[mt][2][nb][r];
            }
    __syncthreads();

#pragma unroll
    for (int nb = 0; nb < 4; nb++) {
        float se = 0.f, so = 0.f, qe = 0.f, qo = 0.f;
#pragma unroll
        for (int mt = 0; mt < 2; mt++) {
            float v[4];
#pragma unroll
            for (int r = 0; r < 4; r++) {
                int p = p0 + mt * 16 + g8 + ((r >= 2) ? 8 : 0);
                int n = nh * 32 + nb * 8 + 2 * q + (r & 1);
                float t = acc[mt][1][nb][r];
                t += (p > 0)   ? S0[(p - 1) * 65 + n] : sL[n];
                t += (p < 127) ? S2[(p + 1) * 65 + n] : sR[n];
                t += sBias[n];
                v[r] = t;
                if (WRITE)
                    g_y2[(((size_t)b * COUT + g * 64 + n) * H_IMG + y) * W_IMG + x0 + p] = t;
            }
            se += v[0] + v[2]; so += v[1] + v[3];
            qe += v[0]*v[0] + v[2]*v[2]; qo += v[1]*v[1] + v[3]*v[3];
        }
#pragma unroll
        for (int sh = 4; sh <= 16; sh <<= 1) {
            se += __shfl_xor_sync(0xffffffffu, se, sh);
            so += __shfl_xor_sync(0xffffffffu, so, sh);
            qe += __shfl_xor_sync(0xffffffffu, qe, sh);
            qo += __shfl_xor_sync(0xffffffffu, qo, sh);
        }
        if (lane < 4) {
            int ne = nh * 32 + nb * 8 + 2 * lane;
            atomicAdd(&ost[g * 64 + ne], se);
            atomicAdd(&ost[COUT + g * 64 + ne], qe);
            atomicAdd(&ost[g * 64 + ne + 1], so);
            atomicAdd(&ost[COUT + g * 64 + ne + 1], qo);
        }
    }
}

// ---------------- patch gather + encode ----------------
__global__ void patch_kernel(const float* __restrict__ image,
                             const int* __restrict__ a_xy, const int* __restrict__ p_xy,
                             const int* __restrict__ n_xy, float* __restrict__ out)
{
    int idx = blockIdx.x * blockDim.x + threadIdx.x;
    if (idx >= 3528) return;
    int which = idx / 1176;
    int r  = idx % 1176;
    int b  = r / 147, r2 = r % 147;
    int c  = r2 / 49, p = r2 % 49;
    int dy = p / 7, dx = p % 7;
    const int* xy = (which == 0) ? a_xy : (which == 1 ? p_xy : n_xy);
    int row = xy[b * 64 + 62], col = xy[b * 64 + 63];
    out[idx] = image[((b * 3 + c) * H_IMG + (row - 3 + dy)) * W_IMG + (col - 3 + dx)];
}

__global__ void encode_kernel(const int* __restrict__ n_xy,
                              const float* __restrict__ bn2_g, const float* __restrict__ bn2_b,
                              const float* __restrict__ conv3_b,
                              const float* __restrict__ bn3_g, const float* __restrict__ bn3_b,
                              float* __restrict__ out)
{
    int b = blockIdx.x, o = threadIdx.x;
    __shared__ float s_z2[576];
    int row = n_xy[b * 64 + 62], col = n_xy[b * 64 + 63];
    for (int i = threadIdx.x; i < 576; i += 128) {
        int c = i / 9, p = i % 9;
        int ky = p / 3 - 1, kx = p % 3 - 1;
        float mean = g_s2[c] * (1.f / NPIX);
        float var  = g_s2[64 + c] * (1.f / NPIX) - mean * mean;
        float is   = rsqrtf(var + BN_EPS);
        float sc   = bn2_g[c] * is;
        float sh   = bn2_b[c] - mean * sc;
        float v = g_y2[((b * 64 + c) * H_IMG + row + ky) * W_IMG + col + kx];
        v = v * sc + sh;
        v = v > 0.f ? v : 0.01f * v;
        s_z2[i] = v;
    }
    __syncthreads();
    float acc = conv3_b[o];
    for (int i = 0; i < 576; i++) acc = fmaf(s_z2[i], g_w3t[i * 128 + o], acc);
    float mean = g_s3[o] * (1.f / NPIX);
    float var  = g_s3[128 + o] * (1.f / NPIX) - mean * mean;
    float is   = rsqrtf(var + BN_EPS);
    float v = (acc - mean) * is * bn3_g[o] + bn3_b[o];
    v = v > 0.f ? v : 0.01f * v;
    out[3528 + b * 128 + o] = v;
}

extern "C" void kernel_launch(void* const* d_in, const int* in_sizes, int n_in,
                              void* d_out, int out_size) {
    const float* image = (const float*)d_in[0];
    const int*   a_xy  = (const int*)d_in[1];
    const int*   p_xy  = (const int*)d_in[2];
    const int*   n_xy  = (const int*)d_in[3];
    const float* w1  = (const float*)d_in[4];
    const float* b1  = (const float*)d_in[5];
    const float* g1  = (const float*)d_in[6];
    const float* be1 = (const float*)d_in[7];
    const float* w2  = (const float*)d_in[8];
    const float* b2  = (const float*)d_in[9];
    const float* g2  = (const float*)d_in[10];
    const float* be2 = (const float*)d_in[11];
    const float* w3  = (const float*)d_in[12];
    const float* b3  = (const float*)d_in[13];
    const float* g3  = (const float*)d_in[14];
    const float* be3 = (const float*)d_in[15];
    float* out = (float*)d_out;

    const int SM2 = 3*128*(32*4+16) + 3*2*2*2048 + (8*32+192)*4;     // 81,664
    const int SM3 = 3*128*(64*4+16) + 3*2*4*2048 + (8*64+192)*4;     // 156,416
    cudaFuncSetAttribute(conv_mma_kernel<32, 64, true>,
                         cudaFuncAttributeMaxDynamicSharedMemorySize, SM2);
    cudaFuncSetAttribute(conv_mma_kernel<64, 128, false>,
                         cudaFuncAttributeMaxDynamicSharedMemorySize, SM3);

    // Launch order puts conv_mma kernels at indices 3 and 5 so the fixed-slot
    // ncu capture lands on a hot kernel (patch repeated as harmless filler).
    prep_all_kernel<<<546, 256>>>(w1, w2, w3);                                    // 0
    conv1_kernel<<<dim3(16, 4, 8), 256>>>(image, b1);                             // 1
    patch_kernel<<<14, 256>>>(image, a_xy, p_xy, n_xy, out);                      // 2
    conv_mma_kernel<32, 64, true><<<dim3(2, 256, 8), 256, SM2>>>(g1, be1, b2);    // 3
    patch_kernel<<<14, 256>>>(image, a_xy, p_xy, n_xy, out);                      // 4
    conv_mma_kernel<64, 128, false><<<dim3(2, 256, 16), 256, SM3>>>(g2, be2, b3); // 5
    encode_kernel<<<8, 128>>>(n_xy, g2, be2, b3, g3, be3, out);                   // 6
}

// round 10
// speedup vs baseline: 2.1330x; 1.4113x over previous
#include <cuda_runtime.h>
#include <cuda_bf16.h>
#include <cstdint>

#define H_IMG 256
#define W_IMG 256
#define B_SZ 8
#define NPIX (B_SZ * H_IMG * W_IMG)
#define BN_EPS 1e-5f

// -------- scratch (allocation-free) --------
__device__ float g_y1[B_SZ * 32 * H_IMG * W_IMG];
__device__ float g_y2[B_SZ * 64 * H_IMG * W_IMG];
__device__ float g_w1t[3 * 9 * 32];
__device__ float g_w2t[32 * 9 * 64];
__device__ float g_w3t[64 * 9 * 128];
__device__ uint2 g_wb2[9 * 1 * 2 * 2 * 8 * 32];   // [tap][g][part][ks][nb][lane]
__device__ uint2 g_wb3[9 * 2 * 2 * 4 * 8 * 32];
__device__ float g_s1[2 * 32];
__device__ float g_s2[2 * 64];
__device__ float g_s3[2 * 128];

#define MMA_BF16(d, A0, A1, A2, A3, B0, B1) \
    asm volatile( \
        "mma.sync.aligned.m16n8k16.row.col.f32.bf16.bf16.f32 " \
        "{%0,%1,%2,%3}, {%4,%5,%6,%7}, {%8,%9}, {%0,%1,%2,%3};" \
        : "+f"(d[0]), "+f"(d[1]), "+f"(d[2]), "+f"(d[3]) \
        : "r"(A0), "r"(A1), "r"(A2), "r"(A3), "r"(B0), "r"(B1))

__device__ __forceinline__ uint32_t smem_u32(const void* p) {
    uint32_t a;
    asm("{ .reg .u64 t; cvta.to.shared.u64 t, %1; cvt.u32.u64 %0, t; }" : "=r"(a) : "l"(p));
    return a;
}
#define CP_ASYNC16(smaddr, gptr) \
    asm volatile("cp.async.cg.shared.global [%0], [%1], 16;" :: "r"(smaddr), "l"(gptr))
#define CP_COMMIT()  asm volatile("cp.async.commit_group;" ::: "memory")
#define CP_WAIT0()   asm volatile("cp.async.wait_group 0;" ::: "memory")

// ---------------- fused prep ----------------
template <int CIN, int COUT>
__device__ __forceinline__ void prep_wb_one(const float* __restrict__ w, int idx) {
    constexpr int KS = CIN / 16, NG = COUT / 64;
    uint2* wb = (CIN == 32) ? g_wb2 : g_wb3;
    int lane = idx & 31;
    int t = idx >> 5;
    int nb = t & 7; t >>= 3;
    int ks = t % KS; t /= KS;
    int part = t & 1; t >>= 1;
    int g = t % NG; int tap = t / NG;
    int o = g * 64 + nb * 8 + (lane >> 2);
    int k0 = ks * 16 + 2 * (lane & 3);
    auto enc = [&](int k) -> uint32_t {
        float x = w[(o * CIN + k) * 9 + tap];
        __nv_bfloat16 h = __float2bfloat16(x);
        __nv_bfloat16 v = h;
        if (part) v = __float2bfloat16(x - __bfloat162float(h));
        return (uint32_t)*reinterpret_cast<unsigned short*>(&v);
    };
    uint2 val;
    val.x = enc(k0) | (enc(k0 + 1) << 16);
    val.y = enc(k0 + 8) | (enc(k0 + 9) << 16);
    wb[idx] = val;
}

template <int CIN, int COUT>
__device__ __forceinline__ void transpose_one(const float* __restrict__ w, float* wt, int idx) {
    int o = idx % COUT;
    int r = idx / COUT;
    int ci = r / 9, t = r % 9;
    wt[idx] = w[(o * CIN + ci) * 9 + t];
}

__global__ void prep_all_kernel(const float* __restrict__ w1,
                                const float* __restrict__ w2,
                                const float* __restrict__ w3) {
    int idx = blockIdx.x * 256 + threadIdx.x;
    if (idx < 448) {
        if (idx < 64) g_s1[idx] = 0.f;
        else if (idx < 192) g_s2[idx - 64] = 0.f;
        else g_s3[idx - 192] = 0.f;
        return;
    }
    idx -= 448;
    if (idx < 864)  { transpose_one<3, 32>(w1, g_w1t, idx); return; }
    idx -= 864;
    if (idx < 18432) { transpose_one<32, 64>(w2, g_w2t, idx); return; }
    idx -= 18432;
    if (idx < 73728) { transpose_one<64, 128>(w3, g_w3t, idx); return; }
    idx -= 73728;
    if (idx < 9216)  { prep_wb_one<32, 64>(w2, idx); return; }
    idx -= 9216;
    if (idx < 36864) { prep_wb_one<64, 128>(w3, idx); return; }
}

// ---------------- conv1: scalar (cin=3, tiny) ----------------
__global__ __launch_bounds__(256, 1) void conv1_kernel(const float* __restrict__ image,
                                                       const float* __restrict__ bias) {
    const int tx = threadIdx.x & 15, ty = threadIdx.x >> 4;
    const int tile_x = blockIdx.x * 16, tile_y = blockIdx.y * 64;
    const int b = blockIdx.z;
    __shared__ float s_in[3][66][18];
    __shared__ float s_w[3 * 9 * 32];
    float a0[32], a1[32], a2[32], a3[32];
#pragma unroll
    for (int o = 0; o < 32; o++) { a0[o] = a1[o] = a2[o] = a3[o] = 0.f; }
    for (int i = threadIdx.x; i < 3 * 66 * 18; i += 256) {
        int c = i / (66 * 18), r = i - c * (66 * 18);
        int yy = r / 18, xx = r - yy * 18;
        int gy = tile_y + yy - 1, gx = tile_x + xx - 1;
        float v = 0.f;
        if (gy >= 0 && gy < H_IMG && gx >= 0 && gx < W_IMG)
            v = image[((b * 3 + c) * H_IMG + gy) * W_IMG + gx];
        s_in[c][yy][xx] = v;
    }
    for (int i = threadIdx.x; i < 3 * 9 * 32; i += 256) s_w[i] = g_w1t[i];
    __syncthreads();
#pragma unroll 1
    for (int c = 0; c < 3; c++) {
#pragma unroll
        for (int t = 0; t < 9; t++) {
            float x0 = s_in[c][ty      + t / 3][tx + t % 3];
            float x1 = s_in[c][ty + 16 + t / 3][tx + t % 3];
            float x2 = s_in[c][ty + 32 + t / 3][tx + t % 3];
            float x3 = s_in[c][ty + 48 + t / 3][tx + t % 3];
            const float4* wv = (const float4*)&s_w[(c * 9 + t) * 32];
#pragma unroll
            for (int qq = 0; qq < 8; qq++) {
                float4 w4 = wv[qq];
                a0[qq*4+0]=fmaf(x0,w4.x,a0[qq*4+0]); a0[qq*4+1]=fmaf(x0,w4.y,a0[qq*4+1]);
                a0[qq*4+2]=fmaf(x0,w4.z,a0[qq*4+2]); a0[qq*4+3]=fmaf(x0,w4.w,a0[qq*4+3]);
                a1[qq*4+0]=fmaf(x1,w4.x,a1[qq*4+0]); a1[qq*4+1]=fmaf(x1,w4.y,a1[qq*4+1]);
                a1[qq*4+2]=fmaf(x1,w4.z,a1[qq*4+2]); a1[qq*4+3]=fmaf(x1,w4.w,a1[qq*4+3]);
                a2[qq*4+0]=fmaf(x2,w4.x,a2[qq*4+0]); a2[qq*4+1]=fmaf(x2,w4.y,a2[qq*4+1]);
                a2[qq*4+2]=fmaf(x2,w4.z,a2[qq*4+2]); a2[qq*4+3]=fmaf(x2,w4.w,a2[qq*4+3]);
                a3[qq*4+0]=fmaf(x3,w4.x,a3[qq*4+0]); a3[qq*4+1]=fmaf(x3,w4.y,a3[qq*4+1]);
                a3[qq*4+2]=fmaf(x3,w4.z,a3[qq*4+2]); a3[qq*4+3]=fmaf(x3,w4.w,a3[qq*4+3]);
            }
        }
    }
    int lane = threadIdx.x & 31;
#pragma unroll
    for (int o = 0; o < 32; o++) {
        float bv = bias[o];
        a0[o] += bv; a1[o] += bv; a2[o] += bv; a3[o] += bv;
        int p = ((b * 32 + o) * H_IMG + tile_y + ty) * W_IMG + tile_x + tx;
        g_y1[p] = a0[o]; g_y1[p + 16*W_IMG] = a1[o];
        g_y1[p + 32*W_IMG] = a2[o]; g_y1[p + 48*W_IMG] = a3[o];
        float v = a0[o]+a1[o]+a2[o]+a3[o];
        float v2 = a0[o]*a0[o]+a1[o]*a1[o]+a2[o]*a2[o]+a3[o]*a3[o];
#pragma unroll
        for (int s = 16; s > 0; s >>= 1) {
            v  += __shfl_down_sync(0xffffffffu, v, s);
            v2 += __shfl_down_sync(0xffffffffu, v2, s);
        }
        if (lane == 0) { atomicAdd(&g_s1[o], v); atomicAdd(&g_s1[32 + o], v2); }
    }
}

// ---------------- warp-MMA implicit-GEMM conv (conv2 / conv3) ----------------
// 128-thread CTA, M=64 pixel strip x N=64 couts; 3 CTAs/SM for latency hiding.
// A restaged per dy (single row); B tiles prefetched with cp.async.
template <int CIN, int COUT, bool WRITE>
__global__ __launch_bounds__(128, 3)
void conv_mma_kernel(const float* __restrict__ in_gamma,
                     const float* __restrict__ in_beta,
                     const float* __restrict__ bias)
{
    constexpr int KS   = CIN / 16;
    constexpr int NG   = COUT / 64;
    constexpr int AROW = CIN * 4 + 16;            // hi(CIN*2) | lo(CIN*2) | pad16
    constexpr int ABUF = 64 * AROW;               // one dy row, 64 pixels
    constexpr int BTAP = 2 * KS * 8 * 32 * 8;     // bytes per tap fragment tile
    constexpr int BBUF = 3 * BTAP;                // 3 dx taps per dy
    constexpr int HW   = H_IMG * W_IMG;

    const float* in  = (CIN == 32) ? g_y1 : g_y2;
    const float* ist = (CIN == 32) ? g_s1 : g_s2;
    float* ost       = (CIN == 32) ? g_s2 : g_s3;
    const float* wt  = (CIN == 32) ? g_w2t : g_w3t;
    const uint2* wb  = (CIN == 32) ? g_wb2 : g_wb3;

    extern __shared__ char sm[];
    float* sScale = (float*)(sm + ABUF + BBUF);
    float* sShift = sScale + CIN;
    float* sEdge  = sShift + CIN;                 // [side][dy][c]
    float* sL     = sEdge + 6 * CIN;
    float* sR     = sL + 64;
    float* sBias  = sR + 64;

    const int tid = threadIdx.x, wid = tid >> 5, lane = tid & 31;
    const int g8 = lane >> 2, q = lane & 3;
    const int mc = wid >> 1, nh = wid & 1;        // warp -> (M chunk of 32, N half of 32)
    const int p0 = mc * 32;
    const int x0 = blockIdx.x * 64, y = blockIdx.y;
    const int b = blockIdx.z / NG, g = blockIdx.z % NG;

    if (tid < CIN) {
        float mean = ist[tid] * (1.f / NPIX);
        float var  = ist[CIN + tid] * (1.f / NPIX) - mean * mean;
        float is_  = rsqrtf(var + BN_EPS);
        float sc   = in_gamma[tid] * is_;
        sScale[tid] = sc; sShift[tid] = in_beta[tid] - mean * sc;
    }
    if (tid < 64) sBias[tid] = bias[g * 64 + tid];
    __syncthreads();

    // ---- edge activations + exact strip-boundary fixup (reads global) ----
    for (int i = tid; i < 6 * CIN; i += 128) {
        int side = i / (3 * CIN), rem = i % (3 * CIN);
        int dyy = rem / CIN, c = rem % CIN;
        int ydy = y + dyy - 1;
        int xx = side ? x0 + 64 : x0 - 1;
        float v = 0.f;
        if (ydy >= 0 && ydy < H_IMG && xx >= 0 && xx < W_IMG) {
            v = in[((size_t)b * CIN + c) * HW + (size_t)ydy * W_IMG + xx];
            v = fmaf(v, sScale[c], sShift[c]);
            v = v > 0.f ? v : 0.01f * v;
        }
        sEdge[i] = v;
    }
    __syncthreads();
    {
        int o = tid & 63, side = tid >> 6;
        float accf = 0.f;
        for (int dyy = 0; dyy < 3; dyy++)
            for (int c = 0; c < CIN; c++)
                accf = fmaf(sEdge[side * 3 * CIN + dyy * CIN + c],
                            wt[(c * 9 + dyy * 3 + (side ? 2 : 0)) * COUT + g * 64 + o], accf);
        (side ? sR : sL)[o] = accf;
    }

    float acc[2][3][4][4];
#pragma unroll
    for (int mt = 0; mt < 2; mt++)
#pragma unroll
        for (int dx = 0; dx < 3; dx++)
#pragma unroll
            for (int nb = 0; nb < 4; nb++)
#pragma unroll
                for (int r = 0; r < 4; r++) acc[mt][dx][nb][r] = 0.f;

    for (int dy = 0; dy < 3; dy++) {
        __syncthreads();   // WAR: previous MMA done before restaging
        // B tiles (3 dx taps) via cp.async — overlaps with A transform below
        {
            const char* gB = (const char*)wb + (size_t)(dy * 3 * NG + g) * BTAP;
            // note layout index is (tap*NG + g); taps dy*3..dy*3+2 are NG apart
            for (int t3 = 0; t3 < 3; t3++) {
                const char* gsrc = (const char*)wb + (size_t)((dy * 3 + t3) * NG + g) * BTAP;
                uint32_t dst = smem_u32(sm + ABUF + t3 * BTAP);
                for (int i = tid; i < BTAP / 16; i += 128)
                    CP_ASYNC16(dst + i * 16, gsrc + i * 16);
            }
            CP_COMMIT();
            (void)gB;
        }
        // A row: BN+lrelu, bf16 hi/lo split
        int ydy = y + dy - 1;
        if (ydy < 0 || ydy >= H_IMG) {
            for (int i = tid; i < ABUF / 16; i += 128) ((uint4*)sm)[i] = make_uint4(0, 0, 0, 0);
        } else {
            const float* src = in + ((size_t)b * CIN * H_IMG + ydy) * W_IMG + x0;
            for (int i = tid; i < 64 * CIN; i += 128) {
                int p = i & 63, c = i >> 6;
                float v = src[(size_t)c * HW + p];
                v = fmaf(v, sScale[c], sShift[c]);
                v = v > 0.f ? v : 0.01f * v;
                __nv_bfloat16 h = __float2bfloat16(v);
                __nv_bfloat16 l = __float2bfloat16(v - __bfloat162float(h));
                __nv_bfloat16* row = (__nv_bfloat16*)(sm + p * AROW);
                row[c] = h;
                row[CIN + c] = l;
            }
        }
        CP_WAIT0();
        __syncthreads();

        const char* aB = sm + (p0 + g8) * AROW + 4 * q;
#pragma unroll
        for (int ks = 0; ks < KS; ks++) {
            uint32_t ah[2][4], al[2][4];
#pragma unroll
            for (int mt = 0; mt < 2; mt++) {
                const char* base = aB + mt * 16 * AROW + 32 * ks;
                ah[mt][0] = *(const uint32_t*)(base);
                ah[mt][1] = *(const uint32_t*)(base + 8 * AROW);
                ah[mt][2] = *(const uint32_t*)(base + 16);
                ah[mt][3] = *(const uint32_t*)(base + 8 * AROW + 16);
                al[mt][0] = *(const uint32_t*)(base + 2 * CIN);
                al[mt][1] = *(const uint32_t*)(base + 2 * CIN + 8 * AROW);
                al[mt][2] = *(const uint32_t*)(base + 2 * CIN + 16);
                al[mt][3] = *(const uint32_t*)(base + 2 * CIN + 8 * AROW + 16);
            }
#pragma unroll
            for (int dx = 0; dx < 3; dx++) {
                const uint2* sB = (const uint2*)(sm + ABUF + dx * BTAP);
#pragma unroll
                for (int nb = 0; nb < 4; nb++) {
                    int nbg = nh * 4 + nb;
                    uint2 bh = sB[(ks * 8 + nbg) * 32 + lane];
                    uint2 bl = sB[((KS + ks) * 8 + nbg) * 32 + lane];
#pragma unroll
                    for (int mt = 0; mt < 2; mt++) {
                        MMA_BF16(acc[mt][dx][nb], ah[mt][0], ah[mt][1], ah[mt][2], ah[mt][3], bh.x, bh.y);
                        MMA_BF16(acc[mt][dx][nb], ah[mt][0], ah[mt][1], ah[mt][2], ah[mt][3], bl.x, bl.y);
                        MMA_BF16(acc[mt][dx][nb], al[mt][0], al[mt][1], al[mt][2], al[mt][3], bh.x, bh.y);
                    }
                }
            }
        }
    }
    __syncthreads();

    // ---- epilogue: out[p] = D0[p-1] + D1[p] + D2[p+1] + bias; stats fused ----
    float* S0 = (float*)sm;
    float* S2 = (float*)(sm + 64 * 65 * 4);
#pragma unroll
    for (int mt = 0; mt < 2; mt++)
#pragma unroll
        for (int nb = 0; nb < 4; nb++)
#pragma unroll
            for (int r = 0; r < 4; r++) {
                int p = p0 + mt * 16 + g8 + ((r >= 2) ? 8 : 0);
                int n = nh * 32 + nb * 8 + 2 * q + (r & 1);
                S0[p * 65 + n] = acc[mt][0][nb][r];
                S2[p * 65 + n] = acc[mt][2][nb][r];
            }
    __syncthreads();

#pragma unroll
    for (int nb = 0; nb < 4; nb++) {
        float se = 0.f, so = 0.f, qe = 0.f, qo = 0.f;
#pragma unroll
        for (int mt = 0; mt < 2; mt++) {
            float v[4];
#pragma unroll
            for (int r = 0; r < 4; r++) {
                int p = p0 + mt * 16 + g8 + ((r >= 2) ? 8 : 0);
                int n = nh * 32 + nb * 8 + 2 * q + (r & 1);
                float t = acc[mt][1][nb][r];
                t += (p > 0)  ? S0[(p - 1) * 65 + n] : sL[n];
                t += (p < 63) ? S2[(p + 1) * 65 + n] : sR[n];
                t += sBias[n];
                v[r] = t;
                if (WRITE)
                    g_y2[(((size_t)b * COUT + g * 64 + n) * H_IMG + y) * W_IMG + x0 + p] = t;
            }
            se += v[0] + v[2]; so += v[1] + v[3];
            qe += v[0]*v[0] + v[2]*v[2]; qo += v[1]*v[1] + v[3]*v[3];
        }
#pragma unroll
        for (int sh = 4; sh <= 16; sh <<= 1) {
            se += __shfl_xor_sync(0xffffffffu, se, sh);
            so += __shfl_xor_sync(0xffffffffu, so, sh);
            qe += __shfl_xor_sync(0xffffffffu, qe, sh);
            qo += __shfl_xor_sync(0xffffffffu, qo, sh);
        }
        if (lane < 4) {
            int ne = nh * 32 + nb * 8 + 2 * lane;
            atomicAdd(&ost[g * 64 + ne], se);
            atomicAdd(&ost[COUT + g * 64 + ne], qe);
            atomicAdd(&ost[g * 64 + ne + 1], so);
            atomicAdd(&ost[COUT + g * 64 + ne + 1], qo);
        }
    }
}

// ---------------- patch gather + encode ----------------
__global__ void patch_kernel(const float* __restrict__ image,
                             const int* __restrict__ a_xy, const int* __restrict__ p_xy,
                             const int* __restrict__ n_xy, float* __restrict__ out)
{
    int idx = blockIdx.x * blockDim.x + threadIdx.x;
    if (idx >= 3528) return;
    int which = idx / 1176;
    int r  = idx % 1176;
    int b  = r / 147, r2 = r % 147;
    int c  = r2 / 49, p = r2 % 49;
    int dy = p / 7, dx = p % 7;
    const int* xy = (which == 0) ? a_xy : (which == 1 ? p_xy : n_xy);
    int row = xy[b * 64 + 62], col = xy[b * 64 + 63];
    out[idx] = image[((b * 3 + c) * H_IMG + (row - 3 + dy)) * W_IMG + (col - 3 + dx)];
}

__global__ void encode_kernel(const int* __restrict__ n_xy,
                              const float* __restrict__ bn2_g, const float* __restrict__ bn2_b,
                              const float* __restrict__ conv3_b,
                              const float* __restrict__ bn3_g, const float* __restrict__ bn3_b,
                              float* __restrict__ out)
{
    int b = blockIdx.x, o = threadIdx.x;
    __shared__ float s_z2[576];
    int row = n_xy[b * 64 + 62], col = n_xy[b * 64 + 63];
    for (int i = threadIdx.x; i < 576; i += 128) {
        int c = i / 9, p = i % 9;
        int ky = p / 3 - 1, kx = p % 3 - 1;
        float mean = g_s2[c] * (1.f / NPIX);
        float var  = g_s2[64 + c] * (1.f / NPIX) - mean * mean;
        float is   = rsqrtf(var + BN_EPS);
        float sc   = bn2_g[c] * is;
        float sh   = bn2_b[c] - mean * sc;
        float v = g_y2[((b * 64 + c) * H_IMG + row + ky) * W_IMG + col + kx];
        v = v * sc + sh;
        v = v > 0.f ? v : 0.01f * v;
        s_z2[i] = v;
    }
    __syncthreads();
    float acc = conv3_b[o];
    for (int i = 0; i < 576; i++) acc = fmaf(s_z2[i], g_w3t[i * 128 + o], acc);
    float mean = g_s3[o] * (1.f / NPIX);
    float var  = g_s3[128 + o] * (1.f / NPIX) - mean * mean;
    float is   = rsqrtf(var + BN_EPS);
    float v = (acc - mean) * is * bn3_g[o] + bn3_b[o];
    v = v > 0.f ? v : 0.01f * v;
    out[3528 + b * 128 + o] = v;
}

extern "C" void kernel_launch(void* const* d_in, const int* in_sizes, int n_in,
                              void* d_out, int out_size) {
    const float* image = (const float*)d_in[0];
    const int*   a_xy  = (const int*)d_in[1];
    const int*   p_xy  = (const int*)d_in[2];
    const int*   n_xy  = (const int*)d_in[3];
    const float* w1  = (const float*)d_in[4];
    const float* b1  = (const float*)d_in[5];
    const float* g1  = (const float*)d_in[6];
    const float* be1 = (const float*)d_in[7];
    const float* w2  = (const float*)d_in[8];
    const float* b2  = (const float*)d_in[9];
    const float* g2  = (const float*)d_in[10];
    const float* be2 = (const float*)d_in[11];
    const float* w3  = (const float*)d_in[12];
    const float* b3  = (const float*)d_in[13];
    const float* g3  = (const float*)d_in[14];
    const float* be3 = (const float*)d_in[15];
    float* out = (float*)d_out;

    // smem: A(64*AROW) + B(3*BTAP) + extras((8*CIN+192)*4)
    const int SM2 = 64*(32*4+16) + 3*(2*2*2048) + (8*32+192)*4;     // 35,584
    const int SM3 = 64*(64*4+16) + 3*(2*4*2048) + (8*64+192)*4;     // 69,376
    cudaFuncSetAttribute(conv_mma_kernel<32, 64, true>,
                         cudaFuncAttributeMaxDynamicSharedMemorySize, SM2);
    cudaFuncSetAttribute(conv_mma_kernel<64, 128, false>,
                         cudaFuncAttributeMaxDynamicSharedMemorySize, SM3);

    // conv_mma kernels at ncu-capture slots 3 and 5.
    prep_all_kernel<<<546, 256>>>(w1, w2, w3);                                    // 0
    conv1_kernel<<<dim3(16, 4, 8), 256>>>(image, b1);                             // 1
    patch_kernel<<<14, 256>>>(image, a_xy, p_xy, n_xy, out);                      // 2
    conv_mma_kernel<32, 64, true><<<dim3(4, 256, 8), 128, SM2>>>(g1, be1, b2);    // 3
    patch_kernel<<<14, 256>>>(image, a_xy, p_xy, n_xy, out);                      // 4
    conv_mma_kernel<64, 128, false><<<dim3(4, 256, 16), 128, SM3>>>(g2, be2, b3); // 5
    encode_kernel<<<8, 128>>>(n_xy, g2, be2, b3, g3, be3, out);                   // 6
}

// round 12
// speedup vs baseline: 2.1705x; 1.0176x over previous
#include <cuda_runtime.h>
#include <cuda_bf16.h>
#include <cstdint>

#define H_IMG 256
#define W_IMG 256
#define B_SZ 8
#define NPIX (B_SZ * H_IMG * W_IMG)
#define BN_EPS 1e-5f

// -------- scratch (allocation-free) --------
__device__ float g_y1[B_SZ * 32 * H_IMG * W_IMG];
__device__ float g_y2[B_SZ * 64 * H_IMG * W_IMG];
__device__ float g_w1t[3 * 9 * 32];
__device__ float g_w2t[32 * 9 * 64];
__device__ float g_w3t[64 * 9 * 128];
__device__ uint2 g_wb2[9 * 1 * 2 * 2 * 8 * 32];   // [tap][g][part] blocks; paired-nb uint4 order inside
__device__ uint2 g_wb3[9 * 2 * 2 * 4 * 8 * 32];
__device__ float g_s1[2 * 32];
__device__ float g_s2[2 * 64];
__device__ float g_s3[2 * 128];

#define MMA_BF16(d, A0, A1, A2, A3, B0, B1) \
    asm volatile( \
        "mma.sync.aligned.m16n8k16.row.col.f32.bf16.bf16.f32 " \
        "{%0,%1,%2,%3}, {%4,%5,%6,%7}, {%8,%9}, {%0,%1,%2,%3};" \
        : "+f"(d[0]), "+f"(d[1]), "+f"(d[2]), "+f"(d[3]) \
        : "r"(A0), "r"(A1), "r"(A2), "r"(A3), "r"(B0), "r"(B1))

#define LDSM_X4(r0, r1, r2, r3, addr) \
    asm volatile("ldmatrix.sync.aligned.m8n8.x4.shared.b16 {%0,%1,%2,%3}, [%4];" \
        : "=r"(r0), "=r"(r1), "=r"(r2), "=r"(r3) : "r"(addr))

__device__ __forceinline__ uint32_t smem_u32(const void* p) {
    uint32_t a;
    asm("{ .reg .u64 t; cvta.to.shared.u64 t, %1; cvt.u32.u64 %0, t; }" : "=r"(a) : "l"(p));
    return a;
}
#define CP_ASYNC16(smaddr, gptr) \
    asm volatile("cp.async.cg.shared.global [%0], [%1], 16;" :: "r"(smaddr), "l"(gptr))
#define CP_COMMIT()  asm volatile("cp.async.commit_group;" ::: "memory")
#define CP_WAIT0()   asm volatile("cp.async.wait_group 0;" ::: "memory")

// ---------------- fused prep ----------------
// B fragments, paired-nb layout: per (tap,g,part) block of KS*256 uint2;
// uint2 slot = ((ks*4 + (nb>>1))*32 + lane)*2 + (nb&1)  -> kernel reads uint4 pairs.
template <int CIN, int COUT>
__device__ __forceinline__ void prep_wb_one(const float* __restrict__ w, int idx) {
    constexpr int KS = CIN / 16, NG = COUT / 64;
    uint2* wb = (CIN == 32) ? g_wb2 : g_wb3;
    int lane = idx & 31;
    int t = idx >> 5;
    int nb = t & 7; t >>= 3;
    int ks = t % KS; t /= KS;
    int part = t & 1; t >>= 1;
    int g = t % NG; int tap = t / NG;
    int o = g * 64 + nb * 8 + (lane >> 2);
    int k0 = ks * 16 + 2 * (lane & 3);
    auto enc = [&](int k) -> uint32_t {
        float x = w[(o * CIN + k) * 9 + tap];
        __nv_bfloat16 h = __float2bfloat16(x);
        __nv_bfloat16 v = h;
        if (part) v = __float2bfloat16(x - __bfloat162float(h));
        return (uint32_t)*reinterpret_cast<unsigned short*>(&v);
    };
    uint2 val;
    val.x = enc(k0) | (enc(k0 + 1) << 16);
    val.y = enc(k0 + 8) | (enc(k0 + 9) << 16);
    size_t BI = (size_t)((tap * NG + g) * 2 + part);
    wb[BI * (KS * 256) + (size_t)((ks * 4 + (nb >> 1)) * 32 + lane) * 2 + (nb & 1)] = val;
}

template <int CIN, int COUT>
__device__ __forceinline__ void transpose_one(const float* __restrict__ w, float* wt, int idx) {
    int o = idx % COUT;
    int r = idx / COUT;
    int ci = r / 9, t = r % 9;
    wt[idx] = w[(o * CIN + ci) * 9 + t];
}

__global__ void prep_all_kernel(const float* __restrict__ w1,
                                const float* __restrict__ w2,
                                const float* __restrict__ w3) {
    int idx = blockIdx.x * 256 + threadIdx.x;
    if (idx < 448) {
        if (idx < 64) g_s1[idx] = 0.f;
        else if (idx < 192) g_s2[idx - 64] = 0.f;
        else g_s3[idx - 192] = 0.f;
        return;
    }
    idx -= 448;
    if (idx < 864)  { transpose_one<3, 32>(w1, g_w1t, idx); return; }
    idx -= 864;
    if (idx < 18432) { transpose_one<32, 64>(w2, g_w2t, idx); return; }
    idx -= 18432;
    if (idx < 73728) { transpose_one<64, 128>(w3, g_w3t, idx); return; }
    idx -= 73728;
    if (idx < 9216)  { prep_wb_one<32, 64>(w2, idx); return; }
    idx -= 9216;
    if (idx < 36864) { prep_wb_one<64, 128>(w3, idx); return; }
}

// ---------------- conv1: scalar (cin=3, tiny) ----------------
__global__ __launch_bounds__(256, 1) void conv1_kernel(const float* __restrict__ image,
                                                       const float* __restrict__ bias) {
    const int tx = threadIdx.x & 15, ty = threadIdx.x >> 4;
    const int tile_x = blockIdx.x * 16, tile_y = blockIdx.y * 64;
    const int b = blockIdx.z;
    __shared__ float s_in[3][66][18];
    __shared__ float s_w[3 * 9 * 32];
    float a0[32], a1[32], a2[32], a3[32];
#pragma unroll
    for (int o = 0; o < 32; o++) { a0[o] = a1[o] = a2[o] = a3[o] = 0.f; }
    for (int i = threadIdx.x; i < 3 * 66 * 18; i += 256) {
        int c = i / (66 * 18), r = i - c * (66 * 18);
        int yy = r / 18, xx = r - yy * 18;
        int gy = tile_y + yy - 1, gx = tile_x + xx - 1;
        float v = 0.f;
        if (gy >= 0 && gy < H_IMG && gx >= 0 && gx < W_IMG)
            v = image[((b * 3 + c) * H_IMG + gy) * W_IMG + gx];
        s_in[c][yy][xx] = v;
    }
    for (int i = threadIdx.x; i < 3 * 9 * 32; i += 256) s_w[i] = g_w1t[i];
    __syncthreads();
#pragma unroll 1
    for (int c = 0; c < 3; c++) {
#pragma unroll
        for (int t = 0; t < 9; t++) {
            float x0 = s_in[c][ty      + t / 3][tx + t % 3];
            float x1 = s_in[c][ty + 16 + t / 3][tx + t % 3];
            float x2 = s_in[c][ty + 32 + t / 3][tx + t % 3];
            float x3 = s_in[c][ty + 48 + t / 3][tx + t % 3];
            const float4* wv = (const float4*)&s_w[(c * 9 + t) * 32];
#pragma unroll
            for (int qq = 0; qq < 8; qq++) {
                float4 w4 = wv[qq];
                a0[qq*4+0]=fmaf(x0,w4.x,a0[qq*4+0]); a0[qq*4+1]=fmaf(x0,w4.y,a0[qq*4+1]);
                a0[qq*4+2]=fmaf(x0,w4.z,a0[qq*4+2]); a0[qq*4+3]=fmaf(x0,w4.w,a0[qq*4+3]);
                a1[qq*4+0]=fmaf(x1,w4.x,a1[qq*4+0]); a1[qq*4+1]=fmaf(x1,w4.y,a1[qq*4+1]);
                a1[qq*4+2]=fmaf(x1,w4.z,a1[qq*4+2]); a1[qq*4+3]=fmaf(x1,w4.w,a1[qq*4+3]);
                a2[qq*4+0]=fmaf(x2,w4.x,a2[qq*4+0]); a2[qq*4+1]=fmaf(x2,w4.y,a2[qq*4+1]);
                a2[qq*4+2]=fmaf(x2,w4.z,a2[qq*4+2]); a2[qq*4+3]=fmaf(x2,w4.w,a2[qq*4+3]);
                a3[qq*4+0]=fmaf(x3,w4.x,a3[qq*4+0]); a3[qq*4+1]=fmaf(x3,w4.y,a3[qq*4+1]);
                a3[qq*4+2]=fmaf(x3,w4.z,a3[qq*4+2]); a3[qq*4+3]=fmaf(x3,w4.w,a3[qq*4+3]);
            }
        }
    }
    int lane = threadIdx.x & 31;
#pragma unroll
    for (int o = 0; o < 32; o++) {
        float bv = bias[o];
        a0[o] += bv; a1[o] += bv; a2[o] += bv; a3[o] += bv;
        int p = ((b * 32 + o) * H_IMG + tile_y + ty) * W_IMG + tile_x + tx;
        g_y1[p] = a0[o]; g_y1[p + 16*W_IMG] = a1[o];
        g_y1[p + 32*W_IMG] = a2[o]; g_y1[p + 48*W_IMG] = a3[o];
        float v = a0[o]+a1[o]+a2[o]+a3[o];
        float v2 = a0[o]*a0[o]+a1[o]*a1[o]+a2[o]*a2[o]+a3[o]*a3[o];
#pragma unroll
        for (int s = 16; s > 0; s >>= 1) {
            v  += __shfl_down_sync(0xffffffffu, v, s);
            v2 += __shfl_down_sync(0xffffffffu, v2, s);
        }
        if (lane == 0) { atomicAdd(&g_s1[o], v); atomicAdd(&g_s1[32 + o], v2); }
    }
}

// ---------------- warp-MMA implicit-GEMM conv (conv2 / conv3) ----------------
// 128-thread CTA, M=64 strip x N=64 couts, 3 CTAs/SM. A frags via ldmatrix.x4,
// B frags via paired LDS.128. bf16 3-product split; dx via 3 accumulator sets.
template <int CIN, int COUT, bool WRITE>
__global__ __launch_bounds__(128, 3)
void conv_mma_kernel(const float* __restrict__ in_gamma,
                     const float* __restrict__ in_beta,
                     const float* __restrict__ bias)
{
    constexpr int KS   = CIN / 16;
    constexpr int NG   = COUT / 64;
    constexpr int AROW = CIN * 4 + 16;
    constexpr int ABUF = 64 * AROW;
    constexpr int BTAP = 2 * KS * 8 * 32 * 8;
    constexpr int BBUF = 3 * BTAP;
    constexpr int HW   = H_IMG * W_IMG;

    const float* in  = (CIN == 32) ? g_y1 : g_y2;
    const float* ist = (CIN == 32) ? g_s1 : g_s2;
    float* ost       = (CIN == 32) ? g_s2 : g_s3;
    const float* wt  = (CIN == 32) ? g_w2t : g_w3t;
    const uint2* wb  = (CIN == 32) ? g_wb2 : g_wb3;

    extern __shared__ char sm[];
    float* sScale = (float*)(sm + ABUF + BBUF);
    float* sShift = sScale + CIN;
    float* sEdge  = sShift + CIN;
    float* sL     = sEdge + 6 * CIN;
    float* sR     = sL + 64;
    float* sBias  = sR + 64;

    const int tid = threadIdx.x, wid = tid >> 5, lane = tid & 31;
    const int g8 = lane >> 2, q = lane & 3;
    const int mc = wid >> 1, nh = wid & 1;
    const int p0 = mc * 32;
    const int x0 = blockIdx.x * 64, y = blockIdx.y;
    const int b = blockIdx.z / NG, g = blockIdx.z % NG;

    if (tid < CIN) {
        float mean = ist[tid] * (1.f / NPIX);
        float var  = ist[CIN + tid] * (1.f / NPIX) - mean * mean;
        float is_  = rsqrtf(var + BN_EPS);
        float sc   = in_gamma[tid] * is_;
        sScale[tid] = sc; sShift[tid] = in_beta[tid] - mean * sc;
    }
    if (tid < 64) sBias[tid] = bias[g * 64 + tid];
    __syncthreads();

    // ---- edge activations + exact strip-boundary fixup ----
    for (int i = tid; i < 6 * CIN; i += 128) {
        int side = i / (3 * CIN), rem = i % (3 * CIN);
        int dyy = rem / CIN, c = rem % CIN;
        int ydy = y + dyy - 1;
        int xx = side ? x0 + 64 : x0 - 1;
        float v = 0.f;
        if (ydy >= 0 && ydy < H_IMG && xx >= 0 && xx < W_IMG) {
            v = in[((size_t)b * CIN + c) * HW + (size_t)ydy * W_IMG + xx];
            v = fmaf(v, sScale[c], sShift[c]);
            v = v > 0.f ? v : 0.01f * v;
        }
        sEdge[i] = v;
    }
    __syncthreads();
    {
        int o = tid & 63, side = tid >> 6;
        float accf = 0.f;
        for (int dyy = 0; dyy < 3; dyy++)
            for (int c = 0; c < CIN; c++)
                accf = fmaf(sEdge[side * 3 * CIN + dyy * CIN + c],
                            wt[(c * 9 + dyy * 3 + (side ? 2 : 0)) * COUT + g * 64 + o], accf);
        (side ? sR : sL)[o] = accf;
    }

    float acc[2][3][4][4];
#pragma unroll
    for (int mt = 0; mt < 2; mt++)
#pragma unroll
        for (int dx = 0; dx < 3; dx++)
#pragma unroll
            for (int nb = 0; nb < 4; nb++)
#pragma unroll
                for (int r = 0; r < 4; r++) acc[mt][dx][nb][r] = 0.f;

    // per-lane ldmatrix base address (rows by lane group, +16B col half)
    const int lrow = ((lane >> 3) & 1) * 8 + (lane & 7);
    const uint32_t aAddr0 = smem_u32(sm) + (uint32_t)(p0 + lrow) * AROW
                          + ((lane >> 4) & 1) * 16;

    for (int dy = 0; dy < 3; dy++) {
        __syncthreads();
        for (int t3 = 0; t3 < 3; t3++) {
            const char* gsrc = (const char*)wb + (size_t)((dy * 3 + t3) * NG + g) * BTAP;
            uint32_t dst = smem_u32(sm + ABUF + t3 * BTAP);
            for (int i = tid; i < BTAP / 16; i += 128)
                CP_ASYNC16(dst + i * 16, gsrc + i * 16);
        }
        CP_COMMIT();
        int ydy = y + dy - 1;
        if (ydy < 0 || ydy >= H_IMG) {
            for (int i = tid; i < ABUF / 16; i += 128) ((uint4*)sm)[i] = make_uint4(0, 0, 0, 0);
        } else {
            const float* src = in + ((size_t)b * CIN * H_IMG + ydy) * W_IMG + x0;
            for (int i = tid; i < 64 * CIN; i += 128) {
                int p = i & 63, c = i >> 6;
                float v = src[(size_t)c * HW + p];
                v = fmaf(v, sScale[c], sShift[c]);
                v = v > 0.f ? v : 0.01f * v;
                __nv_bfloat16 h = __float2bfloat16(v);
                __nv_bfloat16 l = __float2bfloat16(v - __bfloat162float(h));
                __nv_bfloat16* row = (__nv_bfloat16*)(sm + p * AROW);
                row[c] = h;
                row[CIN + c] = l;
            }
        }
        CP_WAIT0();
        __syncthreads();

#pragma unroll
        for (int ks = 0; ks < KS; ks++) {
            uint32_t ah[2][4], al[2][4];
#pragma unroll
            for (int mt = 0; mt < 2; mt++) {
                uint32_t ad = aAddr0 + mt * 16 * AROW + 32 * ks;
                LDSM_X4(ah[mt][0], ah[mt][1], ah[mt][2], ah[mt][3], ad);
                LDSM_X4(al[mt][0], al[mt][1], al[mt][2], al[mt][3], ad + 2 * CIN);
            }
#pragma unroll
            for (int dx = 0; dx < 3; dx++) {
                const uint4* sB4 = (const uint4*)(sm + ABUF + dx * BTAP);
#pragma unroll
                for (int nbp = 0; nbp < 2; nbp++) {
                    uint4 bh = sB4[(ks * 4 + nh * 2 + nbp) * 32 + lane];
                    uint4 bl = sB4[(ks * 4 + nh * 2 + nbp) * 32 + lane + KS * 128];
#pragma unroll
                    for (int mt = 0; mt < 2; mt++) {
                        MMA_BF16(acc[mt][dx][2*nbp],   ah[mt][0], ah[mt][1], ah[mt][2], ah[mt][3], bh.x, bh.y);
                        MMA_BF16(acc[mt][dx][2*nbp],   ah[mt][0], ah[mt][1], ah[mt][2], ah[mt][3], bl.x, bl.y);
                        MMA_BF16(acc[mt][dx][2*nbp],   al[mt][0], al[mt][1], al[mt][2], al[mt][3], bh.x, bh.y);
                        MMA_BF16(acc[mt][dx][2*nbp+1], ah[mt][0], ah[mt][1], ah[mt][2], ah[mt][3], bh.z, bh.w);
                        MMA_BF16(acc[mt][dx][2*nbp+1], ah[mt][0], ah[mt][1], ah[mt][2], ah[mt][3], bl.z, bl.w);
                        MMA_BF16(acc[mt][dx][2*nbp+1], al[mt][0], al[mt][1], al[mt][2], al[mt][3], bh.z, bh.w);
                    }
                }
            }
        }
    }
    __syncthreads();

    // ---- epilogue: out[p] = D0[p-1] + D1[p] + D2[p+1] + bias; stats fused ----
    float* S0 = (float*)sm;
    float* S2 = (float*)(sm + 64 * 65 * 4);
#pragma unroll
    for (int mt = 0; mt < 2; mt++)
#pragma unroll
        for (int nb = 0; nb < 4; nb++)
#pragma unroll
            for (int r = 0; r < 4; r++) {
                int p = p0 + mt * 16 + g8 + ((r >= 2) ? 8 : 0);
                int n = nh * 32 + nb * 8 + 2 * q + (r & 1);
                S0[p * 65 + n] = acc[mt][0][nb][r];
                S2[p * 65 + n] = acc[mt][2][nb][r];
            }
    __syncthreads();

#pragma unroll
    for (int nb = 0; nb < 4; nb++) {
        float se = 0.f, so = 0.f, qe = 0.f, qo = 0.f;
#pragma unroll
        for (int mt = 0; mt < 2; mt++) {
            float v[4];
#pragma unroll
            for (int r = 0; r < 4; r++) {
                int p = p0 + mt * 16 + g8 + ((r >= 2) ? 8 : 0);
                int n = nh * 32 + nb * 8 + 2 * q + (r & 1);
                float t = acc[mt][1][nb][r];
                t += (p > 0)  ? S0[(p - 1) * 65 + n] : sL[n];
                t += (p < 63) ? S2[(p + 1) * 65 + n] : sR[n];
                t += sBias[n];
                v[r] = t;
                if (WRITE)
                    g_y2[(((size_t)b * COUT + g * 64 + n) * H_IMG + y) * W_IMG + x0 + p] = t;
            }
            se += v[0] + v[2]; so += v[1] + v[3];
            qe += v[0]*v[0] + v[2]*v[2]; qo += v[1]*v[1] + v[3]*v[3];
        }
#pragma unroll
        for (int sh = 4; sh <= 16; sh <<= 1) {
            se += __shfl_xor_sync(0xffffffffu, se, sh);
            so += __shfl_xor_sync(0xffffffffu, so, sh);
            qe += __shfl_xor_sync(0xffffffffu, qe, sh);
            qo += __shfl_xor_sync(0xffffffffu, qo, sh);
        }
        if (lane < 4) {
            int ne = nh * 32 + nb * 8 + 2 * lane;
            atomicAdd(&ost[g * 64 + ne], se);
            atomicAdd(&ost[COUT + g * 64 + ne], qe);
            atomicAdd(&ost[g * 64 + ne + 1], so);
            atomicAdd(&ost[COUT + g * 64 + ne + 1], qo);
        }
    }
}

// ---------------- patch gather + encode ----------------
__global__ void patch_kernel(const float* __restrict__ image,
                             const int* __restrict__ a_xy, const int* __restrict__ p_xy,
                             const int* __restrict__ n_xy, float* __restrict__ out)
{
    int idx = blockIdx.x * blockDim.x + threadIdx.x;
    if (idx >= 3528) return;
    int which = idx / 1176;
    int r  = idx % 1176;
    int b  = r / 147, r2 = r % 147;
    int c  = r2 / 49, p = r2 % 49;
    int dy = p / 7, dx = p % 7;
    const int* xy = (which == 0) ? a_xy : (which == 1 ? p_xy : n_xy);
    int row = xy[b * 64 + 62], col = xy[b * 64 + 63];
    out[idx] = image[((b * 3 + c) * H_IMG + (row - 3 + dy)) * W_IMG + (col - 3 + dx)];
}

__global__ void encode_kernel(const int* __restrict__ n_xy,
                              const float* __restrict__ bn2_g, const float* __restrict__ bn2_b,
                              const float* __restrict__ conv3_b,
                              const float* __restrict__ bn3_g, const float* __restrict__ bn3_b,
                              float* __restrict__ out)
{
    int b = blockIdx.x, o = threadIdx.x;
    __shared__ float s_z2[576];
    int row = n_xy[b * 64 + 62], col = n_xy[b * 64 + 63];
    for (int i = threadIdx.x; i < 576; i += 128) {
        int c = i / 9, p = i % 9;
        int ky = p / 3 - 1, kx = p % 3 - 1;
        float mean = g_s2[c] * (1.f / NPIX);
        float var  = g_s2[64 + c] * (1.f / NPIX) - mean * mean;
        float is   = rsqrtf(var + BN_EPS);
        float sc   = bn2_g[c] * is;
        float sh   = bn2_b[c] - mean * sc;
        float v = g_y2[((b * 64 + c) * H_IMG + row + ky) * W_IMG + col + kx];
        v = v * sc + sh;
        v = v > 0.f ? v : 0.01f * v;
        s_z2[i] = v;
    }
    __syncthreads();
    float acc = conv3_b[o];
    for (int i = 0; i < 576; i++) acc = fmaf(s_z2[i], g_w3t[i * 128 + o], acc);
    float mean = g_s3[o] * (1.f / NPIX);
    float var  = g_s3[128 + o] * (1.f / NPIX) - mean * mean;
    float is   = rsqrtf(var + BN_EPS);
    float v = (acc - mean) * is * bn3_g[o] + bn3_b[o];
    v = v > 0.f ? v : 0.01f * v;
    out[3528 + b * 128 + o] = v;
}

extern "C" void kernel_launch(void* const* d_in, const int* in_sizes, int n_in,
                              void* d_out, int out_size) {
    const float* image = (const float*)d_in[0];
    const int*   a_xy  = (const int*)d_in[1];
    const int*   p_xy  = (const int*)d_in[2];
    const int*   n_xy  = (const int*)d_in[3];
    const float* w1  = (const float*)d_in[4];
    const float* b1  = (const float*)d_in[5];
    const float* g1  = (const float*)d_in[6];
    const float* be1 = (const float*)d_in[7];
    const float* w2  = (const float*)d_in[8];
    const float* b2  = (const float*)d_in[9];
    const float* g2  = (const float*)d_in[10];
    const float* be2 = (const float*)d_in[11];
    const float* w3  = (const float*)d_in[12];
    const float* b3  = (const float*)d_in[13];
    const float* g3  = (const float*)d_in[14];
    const float* be3 = (const float*)d_in[15];
    float* out = (float*)d_out;

    const int SM2 = 64*(32*4+16) + 3*(2*2*2048) + (8*32+192)*4;     // 35,584
    const int SM3 = 64*(64*4+16) + 3*(2*4*2048) + (8*64+192)*4;     // 69,376
    cudaFuncSetAttribute(conv_mma_kernel<32, 64, true>,
                         cudaFuncAttributeMaxDynamicSharedMemorySize, SM2);
    cudaFuncSetAttribute(conv_mma_kernel<64, 128, false>,
                         cudaFuncAttributeMaxDynamicSharedMemorySize, SM3);

    // conv_mma kernels at ncu-capture slots 3 and 5.
    prep_all_kernel<<<546, 256>>>(w1, w2, w3);                                    // 0
    conv1_kernel<<<dim3(16, 4, 8), 256>>>(image, b1);                             // 1
    patch_kernel<<<14, 256>>>(image, a_xy, p_xy, n_xy, out);                      // 2
    conv_mma_kernel<32, 64, true><<<dim3(4, 256, 8), 128, SM2>>>(g1, be1, b2);    // 3
    patch_kernel<<<14, 256>>>(image, a_xy, p_xy, n_xy, out);                      // 4
    conv_mma_kernel<64, 128, false><<<dim3(4, 256, 16), 128, SM3>>>(g2, be2, b3); // 5
    encode_kernel<<<8, 128>>>(n_xy, g2, be2, b3, g3, be3, out);                   // 6
}

// round 13
// speedup vs baseline: 2.4077x; 1.1093x over previous
#include <cuda_runtime.h>
#include <cuda_bf16.h>
#include <cstdint>

#define H_IMG 256
#define W_IMG 256
#define B_SZ 8
#define NPIX (B_SZ * H_IMG * W_IMG)
#define BN_EPS 1e-5f

// -------- scratch (allocation-free) --------
__device__ float g_y1[B_SZ * 32 * H_IMG * W_IMG];
__device__ float g_y2[B_SZ * 64 * H_IMG * W_IMG];
__device__ __nv_bfloat16 g_a1[(size_t)B_SZ * H_IMG * W_IMG * 64];    // [b][y][x][hi32|lo32]
__device__ __nv_bfloat16 g_a2[(size_t)B_SZ * H_IMG * W_IMG * 128];   // [b][y][x][hi64|lo64]
__device__ float g_w1t[3 * 9 * 32];
__device__ float g_w2t[32 * 9 * 64];
__device__ float g_w3t[64 * 9 * 128];
__device__ uint2 g_wb2[9 * 1 * 2 * 2 * 8 * 32];
__device__ uint2 g_wb3[9 * 2 * 2 * 4 * 8 * 32];
__device__ float g_s1[2 * 32];
__device__ float g_s2[2 * 64];
__device__ float g_s3[2 * 128];

#define MMA_BF16(d, A0, A1, A2, A3, B0, B1) \
    asm volatile( \
        "mma.sync.aligned.m16n8k16.row.col.f32.bf16.bf16.f32 " \
        "{%0,%1,%2,%3}, {%4,%5,%6,%7}, {%8,%9}, {%0,%1,%2,%3};" \
        : "+f"(d[0]), "+f"(d[1]), "+f"(d[2]), "+f"(d[3]) \
        : "r"(A0), "r"(A1), "r"(A2), "r"(A3), "r"(B0), "r"(B1))

#define LDSM_X4(r0, r1, r2, r3, addr) \
    asm volatile("ldmatrix.sync.aligned.m8n8.x4.shared.b16 {%0,%1,%2,%3}, [%4];" \
        : "=r"(r0), "=r"(r1), "=r"(r2), "=r"(r3) : "r"(addr))

__device__ __forceinline__ uint32_t smem_u32(const void* p) {
    uint32_t a;
    asm("{ .reg .u64 t; cvta.to.shared.u64 t, %1; cvt.u32.u64 %0, t; }" : "=r"(a) : "l"(p));
    return a;
}
#define CP_ASYNC16(smaddr, gptr) \
    asm volatile("cp.async.cg.shared.global [%0], [%1], 16;" :: "r"(smaddr), "l"(gptr))
#define CP_COMMIT()  asm volatile("cp.async.commit_group;" ::: "memory")
#define CP_WAIT0()   asm volatile("cp.async.wait_group 0;" ::: "memory")

// ---------------- fused prep ----------------
template <int CIN, int COUT>
__device__ __forceinline__ void prep_wb_one(const float* __restrict__ w, int idx) {
    constexpr int KS = CIN / 16, NG = COUT / 64;
    uint2* wb = (CIN == 32) ? g_wb2 : g_wb3;
    int lane = idx & 31;
    int t = idx >> 5;
    int nb = t & 7; t >>= 3;
    int ks = t % KS; t /= KS;
    int part = t & 1; t >>= 1;
    int g = t % NG; int tap = t / NG;
    int o = g * 64 + nb * 8 + (lane >> 2);
    int k0 = ks * 16 + 2 * (lane & 3);
    auto enc = [&](int k) -> uint32_t {
        float x = w[(o * CIN + k) * 9 + tap];
        __nv_bfloat16 h = __float2bfloat16(x);
        __nv_bfloat16 v = h;
        if (part) v = __float2bfloat16(x - __bfloat162float(h));
        return (uint32_t)*reinterpret_cast<unsigned short*>(&v);
    };
    uint2 val;
    val.x = enc(k0) | (enc(k0 + 1) << 16);
    val.y = enc(k0 + 8) | (enc(k0 + 9) << 16);
    size_t BI = (size_t)((tap * NG + g) * 2 + part);
    wb[BI * (KS * 256) + (size_t)((ks * 4 + (nb >> 1)) * 32 + lane) * 2 + (nb & 1)] = val;
}

template <int CIN, int COUT>
__device__ __forceinline__ void transpose_one(const float* __restrict__ w, float* wt, int idx) {
    int o = idx % COUT;
    int r = idx / COUT;
    int ci = r / 9, t = r % 9;
    wt[idx] = w[(o * CIN + ci) * 9 + t];
}

__global__ void prep_all_kernel(const float* __restrict__ w1,
                                const float* __restrict__ w2,
                                const float* __restrict__ w3) {
    int idx = blockIdx.x * 256 + threadIdx.x;
    if (idx < 448) {
        if (idx < 64) g_s1[idx] = 0.f;
        else if (idx < 192) g_s2[idx - 64] = 0.f;
        else g_s3[idx - 192] = 0.f;
        return;
    }
    idx -= 448;
    if (idx < 864)  { transpose_one<3, 32>(w1, g_w1t, idx); return; }
    idx -= 864;
    if (idx < 18432) { transpose_one<32, 64>(w2, g_w2t, idx); return; }
    idx -= 18432;
    if (idx < 73728) { transpose_one<64, 128>(w3, g_w3t, idx); return; }
    idx -= 73728;
    if (idx < 9216)  { prep_wb_one<32, 64>(w2, idx); return; }
    idx -= 9216;
    if (idx < 36864) { prep_wb_one<64, 128>(w3, idx); return; }
}

// ---------------- BN+lrelu+bf16-split pre-pass: y -> a (pixel-major hi|lo) ----------------
template <int CIN>
__global__ void prepass_kernel(const float* __restrict__ gamma,
                               const float* __restrict__ beta) {
    const float* yin = (CIN == 32) ? g_y1 : g_y2;
    const float* st  = (CIN == 32) ? g_s1 : g_s2;
    __nv_bfloat16* aout = (CIN == 32) ? g_a1 : g_a2;
    extern __shared__ float tile[];   // [CIN][257]
    __shared__ float sc[CIN], sh[CIN];
    int row = blockIdx.x;             // b*256 + y
    int tid = threadIdx.x;
    if (tid < CIN) {
        float mean = st[tid] * (1.f / NPIX);
        float var  = st[CIN + tid] * (1.f / NPIX) - mean * mean;
        float is_  = rsqrtf(var + BN_EPS);
        float s    = gamma[tid] * is_;
        sc[tid] = s; sh[tid] = beta[tid] - mean * s;
    }
    __syncthreads();
    for (int i = tid; i < CIN * 256; i += 256) {
        int c = i >> 8, x = i & 255;
        float v = yin[(size_t)(row >> 8) * CIN * 65536 + (size_t)c * 65536
                      + ((row & 255) << 8) + x];
        v = fmaf(v, sc[c], sh[c]);
        v = v > 0.f ? v : 0.01f * v;
        tile[c * 257 + x] = v;
    }
    __syncthreads();
    uint32_t* ao = (uint32_t*)aout + (size_t)row * 256 * CIN;   // CIN uint32 per px
    for (int i = tid; i < 256 * (CIN / 2); i += 256) {
        int px = i / (CIN / 2), c2 = i % (CIN / 2);
        float v0 = tile[(2 * c2) * 257 + px];
        float v1 = tile[(2 * c2 + 1) * 257 + px];
        __nv_bfloat16 h0 = __float2bfloat16(v0), h1 = __float2bfloat16(v1);
        __nv_bfloat16 l0 = __float2bfloat16(v0 - __bfloat162float(h0));
        __nv_bfloat16 l1 = __float2bfloat16(v1 - __bfloat162float(h1));
        uint32_t hw = (uint32_t)*(unsigned short*)&h0 | ((uint32_t)*(unsigned short*)&h1 << 16);
        uint32_t lw = (uint32_t)*(unsigned short*)&l0 | ((uint32_t)*(unsigned short*)&l1 << 16);
        ao[(size_t)px * CIN + c2] = hw;
        ao[(size_t)px * CIN + CIN / 2 + c2] = lw;
    }
}

// ---------------- conv1: scalar (cin=3, tiny) ----------------
__global__ __launch_bounds__(256, 1) void conv1_kernel(const float* __restrict__ image,
                                                       const float* __restrict__ bias) {
    const int tx = threadIdx.x & 15, ty = threadIdx.x >> 4;
    const int tile_x = blockIdx.x * 16, tile_y = blockIdx.y * 64;
    const int b = blockIdx.z;
    __shared__ float s_in[3][66][18];
    __shared__ float s_w[3 * 9 * 32];
    float a0[32], a1[32], a2[32], a3[32];
#pragma unroll
    for (int o = 0; o < 32; o++) { a0[o] = a1[o] = a2[o] = a3[o] = 0.f; }
    for (int i = threadIdx.x; i < 3 * 66 * 18; i += 256) {
        int c = i / (66 * 18), r = i - c * (66 * 18);
        int yy = r / 18, xx = r - yy * 18;
        int gy = tile_y + yy - 1, gx = tile_x + xx - 1;
        float v = 0.f;
        if (gy >= 0 && gy < H_IMG && gx >= 0 && gx < W_IMG)
            v = image[((b * 3 + c) * H_IMG + gy) * W_IMG + gx];
        s_in[c][yy][xx] = v;
    }
    for (int i = threadIdx.x; i < 3 * 9 * 32; i += 256) s_w[i] = g_w1t[i];
    __syncthreads();
#pragma unroll 1
    for (int c = 0; c < 3; c++) {
#pragma unroll
        for (int t = 0; t < 9; t++) {
            float x0 = s_in[c][ty      + t / 3][tx + t % 3];
            float x1 = s_in[c][ty + 16 + t / 3][tx + t % 3];
            float x2 = s_in[c][ty + 32 + t / 3][tx + t % 3];
            float x3 = s_in[c][ty + 48 + t / 3][tx + t % 3];
            const float4* wv = (const float4*)&s_w[(c * 9 + t) * 32];
#pragma unroll
            for (int qq = 0; qq < 8; qq++) {
                float4 w4 = wv[qq];
                a0[qq*4+0]=fmaf(x0,w4.x,a0[qq*4+0]); a0[qq*4+1]=fmaf(x0,w4.y,a0[qq*4+1]);
                a0[qq*4+2]=fmaf(x0,w4.z,a0[qq*4+2]); a0[qq*4+3]=fmaf(x0,w4.w,a0[qq*4+3]);
                a1[qq*4+0]=fmaf(x1,w4.x,a1[qq*4+0]); a1[qq*4+1]=fmaf(x1,w4.y,a1[qq*4+1]);
                a1[qq*4+2]=fmaf(x1,w4.z,a1[qq*4+2]); a1[qq*4+3]=fmaf(x1,w4.w,a1[qq*4+3]);
                a2[qq*4+0]=fmaf(x2,w4.x,a2[qq*4+0]); a2[qq*4+1]=fmaf(x2,w4.y,a2[qq*4+1]);
                a2[qq*4+2]=fmaf(x2,w4.z,a2[qq*4+2]); a2[qq*4+3]=fmaf(x2,w4.w,a2[qq*4+3]);
                a3[qq*4+0]=fmaf(x3,w4.x,a3[qq*4+0]); a3[qq*4+1]=fmaf(x3,w4.y,a3[qq*4+1]);
                a3[qq*4+2]=fmaf(x3,w4.z,a3[qq*4+2]); a3[qq*4+3]=fmaf(x3,w4.w,a3[qq*4+3]);
            }
        }
    }
    int lane = threadIdx.x & 31;
#pragma unroll
    for (int o = 0; o < 32; o++) {
        float bv = bias[o];
        a0[o] += bv; a1[o] += bv; a2[o] += bv; a3[o] += bv;
        int p = ((b * 32 + o) * H_IMG + tile_y + ty) * W_IMG + tile_x + tx;
        g_y1[p] = a0[o]; g_y1[p + 16*W_IMG] = a1[o];
        g_y1[p + 32*W_IMG] = a2[o]; g_y1[p + 48*W_IMG] = a3[o];
        float v = a0[o]+a1[o]+a2[o]+a3[o];
        float v2 = a0[o]*a0[o]+a1[o]*a1[o]+a2[o]*a2[o]+a3[o]*a3[o];
#pragma unroll
        for (int s = 16; s > 0; s >>= 1) {
            v  += __shfl_down_sync(0xffffffffu, v, s);
            v2 += __shfl_down_sync(0xffffffffu, v2, s);
        }
        if (lane == 0) { atomicAdd(&g_s1[o], v); atomicAdd(&g_s1[32 + o], v2); }
    }
}

// ---------------- warp-MMA implicit-GEMM conv (conv2 / conv3) ----------------
// A comes pre-converted (g_a*): staging = pure cp.async. Epilogue scratch
// aliases the dead A+B smem region after the last MMA.
template <int CIN, int COUT, bool WRITE>
__global__ __launch_bounds__(128, 3)
void conv_mma_kernel(const float* __restrict__ in_gamma,
                     const float* __restrict__ in_beta,
                     const float* __restrict__ bias)
{
    constexpr int KS   = CIN / 16;
    constexpr int NG   = COUT / 64;
    constexpr int AROW = CIN * 4 + 16;
    constexpr int ABUF = 64 * AROW;
    constexpr int BTAP = 2 * KS * 8 * 32 * 8;
    constexpr int BBUF = 3 * BTAP;
    constexpr int HW   = H_IMG * W_IMG;

    const float* yfin = (CIN == 32) ? g_y1 : g_y2;     // fp32 (edge fixup only)
    const char* ain   = (const char*)((CIN == 32) ? (const void*)g_a1 : (const void*)g_a2);
    const float* ist  = (CIN == 32) ? g_s1 : g_s2;
    float* ost        = (CIN == 32) ? g_s2 : g_s3;
    const float* wt   = (CIN == 32) ? g_w2t : g_w3t;
    const uint2* wb   = (CIN == 32) ? g_wb2 : g_wb3;

    extern __shared__ char sm[];
    float* sScale = (float*)(sm + ABUF + BBUF);
    float* sShift = sScale + CIN;
    float* sEdge  = sShift + CIN;
    float* sL     = sEdge + 6 * CIN;
    float* sR     = sL + 64;
    float* sBias  = sR + 64;

    const int tid = threadIdx.x, wid = tid >> 5, lane = tid & 31;
    const int g8 = lane >> 2, q = lane & 3;
    const int mc = wid >> 1, nh = wid & 1;
    const int p0 = mc * 32;
    const int x0 = blockIdx.x * 64, y = blockIdx.y;
    const int b = blockIdx.z / NG, g = blockIdx.z % NG;

    if (tid < CIN) {
        float mean = ist[tid] * (1.f / NPIX);
        float var  = ist[CIN + tid] * (1.f / NPIX) - mean * mean;
        float is_  = rsqrtf(var + BN_EPS);
        float sc   = in_gamma[tid] * is_;
        sScale[tid] = sc; sShift[tid] = in_beta[tid] - mean * sc;
    }
    if (tid < 64) sBias[tid] = bias[g * 64 + tid];
    __syncthreads();

    // ---- edge activations + exact strip-boundary fixup (fp32 source) ----
    for (int i = tid; i < 6 * CIN; i += 128) {
        int side = i / (3 * CIN), rem = i % (3 * CIN);
        int dyy = rem / CIN, c = rem % CIN;
        int ydy = y + dyy - 1;
        int xx = side ? x0 + 64 : x0 - 1;
        float v = 0.f;
        if (ydy >= 0 && ydy < H_IMG && xx >= 0 && xx < W_IMG) {
            v = yfin[((size_t)b * CIN + c) * HW + (size_t)ydy * W_IMG + xx];
            v = fmaf(v, sScale[c], sShift[c]);
            v = v > 0.f ? v : 0.01f * v;
        }
        sEdge[i] = v;
    }
    __syncthreads();
    {
        int o = tid & 63, side = tid >> 6;
        float accf = 0.f;
        for (int dyy = 0; dyy < 3; dyy++)
            for (int c = 0; c < CIN; c++)
                accf = fmaf(sEdge[side * 3 * CIN + dyy * CIN + c],
                            wt[(c * 9 + dyy * 3 + (side ? 2 : 0)) * COUT + g * 64 + o], accf);
        (side ? sR : sL)[o] = accf;
    }

    float acc[2][3][4][4];
#pragma unroll
    for (int mt = 0; mt < 2; mt++)
#pragma unroll
        for (int dx = 0; dx < 3; dx++)
#pragma unroll
            for (int nb = 0; nb < 4; nb++)
#pragma unroll
                for (int r = 0; r < 4; r++) acc[mt][dx][nb][r] = 0.f;

    const int lrow = ((lane >> 3) & 1) * 8 + (lane & 7);
    const uint32_t aAddr0 = smem_u32(sm) + (uint32_t)(p0 + lrow) * AROW
                          + ((lane >> 4) & 1) * 16;
    const uint32_t aSm = smem_u32(sm);

    for (int dy = 0; dy < 3; dy++) {
        __syncthreads();   // WAR: previous MMA done before restaging
        // B tiles (3 dx taps)
        for (int t3 = 0; t3 < 3; t3++) {
            const char* gsrc = (const char*)wb + (size_t)((dy * 3 + t3) * NG + g) * BTAP;
            uint32_t dst = smem_u32(sm + ABUF + t3 * BTAP);
            for (int i = tid; i < BTAP / 16; i += 128)
                CP_ASYNC16(dst + i * 16, gsrc + i * 16);
        }
        // A row: pre-converted, contiguous per pixel -> pure cp.async
        int ydy = y + dy - 1;
        if (ydy < 0 || ydy >= H_IMG) {
            CP_COMMIT();
            for (int i = tid; i < ABUF / 16; i += 128) ((uint4*)sm)[i] = make_uint4(0, 0, 0, 0);
        } else {
            const char* src = ain + ((size_t)(b * H_IMG + ydy) * W_IMG + x0) * (size_t)(4 * CIN);
            for (int i = tid; i < 64 * (CIN / 4); i += 128) {
                int p = i / (CIN / 4), j = i % (CIN / 4);
                CP_ASYNC16(aSm + p * AROW + j * 16, src + p * 4 * CIN + j * 16);
            }
            CP_COMMIT();
        }
        CP_WAIT0();
        __syncthreads();

#pragma unroll
        for (int ks = 0; ks < KS; ks++) {
            uint32_t ah[2][4], al[2][4];
#pragma unroll
            for (int mt = 0; mt < 2; mt++) {
                uint32_t ad = aAddr0 + mt * 16 * AROW + 32 * ks;
                LDSM_X4(ah[mt][0], ah[mt][1], ah[mt][2], ah[mt][3], ad);
                LDSM_X4(al[mt][0], al[mt][1], al[mt][2], al[mt][3], ad + 2 * CIN);
            }
#pragma unroll
            for (int dx = 0; dx < 3; dx++) {
                const uint4* sB4 = (const uint4*)(sm + ABUF + dx * BTAP);
#pragma unroll
                for (int nbp = 0; nbp < 2; nbp++) {
                    uint4 bh = sB4[(ks * 4 + nh * 2 + nbp) * 32 + lane];
                    uint4 bl = sB4[(ks * 4 + nh * 2 + nbp) * 32 + lane + KS * 128];
#pragma unroll
                    for (int mt = 0; mt < 2; mt++) {
                        MMA_BF16(acc[mt][dx][2*nbp],   ah[mt][0], ah[mt][1], ah[mt][2], ah[mt][3], bh.x, bh.y);
                        MMA_BF16(acc[mt][dx][2*nbp],   ah[mt][0], ah[mt][1], ah[mt][2], ah[mt][3], bl.x, bl.y);
                        MMA_BF16(acc[mt][dx][2*nbp],   al[mt][0], al[mt][1], al[mt][2], al[mt][3], bh.x, bh.y);
                        MMA_BF16(acc[mt][dx][2*nbp+1], ah[mt][0], ah[mt][1], ah[mt][2], ah[mt][3], bh.z, bh.w);
                        MMA_BF16(acc[mt][dx][2*nbp+1], ah[mt][0], ah[mt][1], ah[mt][2], ah[mt][3], bl.z, bl.w);
                        MMA_BF16(acc[mt][dx][2*nbp+1], al[mt][0], al[mt][1], al[mt][2], al[mt][3], bh.z, bh.w);
                    }
                }
            }
        }
    }
    __syncthreads();

    // ---- epilogue (scratch aliases dead A+B region) ----
    float* S0 = (float*)sm;
    float* S2 = S0 + 64 * 65;
#pragma unroll
    for (int mt = 0; mt < 2; mt++)
#pragma unroll
        for (int nb = 0; nb < 4; nb++)
#pragma unroll
            for (int r = 0; r < 4; r++) {
                int p = p0 + mt * 16 + g8 + ((r >= 2) ? 8 : 0);
                int n = nh * 32 + nb * 8 + 2 * q + (r & 1);
                S0[p * 65 + n] = acc[mt][0][nb][r];
                S2[p * 65 + n] = acc[mt][2][nb][r];
            }
    __syncthreads();

#pragma unroll
    for (int nb = 0; nb < 4; nb++) {
        float se = 0.f, so = 0.f, qe = 0.f, qo = 0.f;
#pragma unroll
        for (int mt = 0; mt < 2; mt++) {
            float v[4];
#pragma unroll
            for (int r = 0; r < 4; r++) {
                int p = p0 + mt * 16 + g8 + ((r >= 2) ? 8 : 0);
                int n = nh * 32 + nb * 8 + 2 * q + (r & 1);
                float t = acc[mt][1][nb][r];
                t += (p > 0)  ? S0[(p - 1) * 65 + n] : sL[n];
                t += (p < 63) ? S2[(p + 1) * 65 + n] : sR[n];
                t += sBias[n];
                v[r] = t;
                if (WRITE)
                    g_y2[(((size_t)b * COUT + g * 64 + n) * H_IMG + y) * W_IMG + x0 + p] = t;
            }
            se += v[0] + v[2]; so += v[1] + v[3];
            qe += v[0]*v[0] + v[2]*v[2]; qo += v[1]*v[1] + v[3]*v[3];
        }
#pragma unroll
        for (int sh = 4; sh <= 16; sh <<= 1) {
            se += __shfl_xor_sync(0xffffffffu, se, sh);
            so += __shfl_xor_sync(0xffffffffu, so, sh);
            qe += __shfl_xor_sync(0xffffffffu, qe, sh);
            qo += __shfl_xor_sync(0xffffffffu, qo, sh);
        }
        if (lane < 4) {
            int ne = nh * 32 + nb * 8 + 2 * lane;
            atomicAdd(&ost[g * 64 + ne], se);
            atomicAdd(&ost[COUT + g * 64 + ne], qe);
            atomicAdd(&ost[g * 64 + ne + 1], so);
            atomicAdd(&ost[COUT + g * 64 + ne + 1], qo);
        }
    }
}

// ---------------- patch gather + encode ----------------
__global__ void patch_kernel(const float* __restrict__ image,
                             const int* __restrict__ a_xy, const int* __restrict__ p_xy,
                             const int* __restrict__ n_xy, float* __restrict__ out)
{
    int idx = blockIdx.x * blockDim.x + threadIdx.x;
    if (idx >= 3528) return;
    int which = idx / 1176;
    int r  = idx % 1176;
    int b  = r / 147, r2 = r % 147;
    int c  = r2 / 49, p = r2 % 49;
    int dy = p / 7, dx = p % 7;
    const int* xy = (which == 0) ? a_xy : (which == 1 ? p_xy : n_xy);
    int row = xy[b * 64 + 62], col = xy[b * 64 + 63];
    out[idx] = image[((b * 3 + c) * H_IMG + (row - 3 + dy)) * W_IMG + (col - 3 + dx)];
}

__global__ void encode_kernel(const int* __restrict__ n_xy,
                              const float* __restrict__ bn2_g, const float* __restrict__ bn2_b,
                              const float* __restrict__ conv3_b,
                              const float* __restrict__ bn3_g, const float* __restrict__ bn3_b,
                              float* __restrict__ out)
{
    int b = blockIdx.x, o = threadIdx.x;
    __shared__ float s_z2[576];
    int row = n_xy[b * 64 + 62], col = n_xy[b * 64 + 63];
    for (int i = threadIdx.x; i < 576; i += 128) {
        int c = i / 9, p = i % 9;
        int ky = p / 3 - 1, kx = p % 3 - 1;
        float mean = g_s2[c] * (1.f / NPIX);
        float var  = g_s2[64 + c] * (1.f / NPIX) - mean * mean;
        float is   = rsqrtf(var + BN_EPS);
        float sc   = bn2_g[c] * is;
        float sh   = bn2_b[c] - mean * sc;
        float v = g_y2[((b * 64 + c) * H_IMG + row + ky) * W_IMG + col + kx];
        v = v * sc + sh;
        v = v > 0.f ? v : 0.01f * v;
        s_z2[i] = v;
    }
    __syncthreads();
    float acc = conv3_b[o];
    for (int i = 0; i < 576; i++) acc = fmaf(s_z2[i], g_w3t[i * 128 + o], acc);
    float mean = g_s3[o] * (1.f / NPIX);
    float var  = g_s3[128 + o] * (1.f / NPIX) - mean * mean;
    float is   = rsqrtf(var + BN_EPS);
    float v = (acc - mean) * is * bn3_g[o] + bn3_b[o];
    v = v > 0.f ? v : 0.01f * v;
    out[3528 + b * 128 + o] = v;
}

extern "C" void kernel_launch(void* const* d_in, const int* in_sizes, int n_in,
                              void* d_out, int out_size) {
    const float* image = (const float*)d_in[0];
    const int*   a_xy  = (const int*)d_in[1];
    const int*   p_xy  = (const int*)d_in[2];
    const int*   n_xy  = (const int*)d_in[3];
    const float* w1  = (const float*)d_in[4];
    const float* b1  = (const float*)d_in[5];
    const float* g1  = (const float*)d_in[6];
    const float* be1 = (const float*)d_in[7];
    const float* w2  = (const float*)d_in[8];
    const float* b2  = (const float*)d_in[9];
    const float* g2  = (const float*)d_in[10];
    const float* be2 = (const float*)d_in[11];
    const float* w3  = (const float*)d_in[12];
    const float* b3  = (const float*)d_in[13];
    const float* g3  = (const float*)d_in[14];
    const float* be3 = (const float*)d_in[15];
    float* out = (float*)d_out;

    const int SM2 = 64*(32*4+16) + 3*(2*2*2048) + (8*32+192)*4;     // 35,584
    const int SM3 = 64*(64*4+16) + 3*(2*4*2048) + (8*64+192)*4;     // 69,376
    cudaFuncSetAttribute(conv_mma_kernel<32, 64, true>,
                         cudaFuncAttributeMaxDynamicSharedMemorySize, SM2);
    cudaFuncSetAttribute(conv_mma_kernel<64, 128, false>,
                         cudaFuncAttributeMaxDynamicSharedMemorySize, SM3);
    cudaFuncSetAttribute(prepass_kernel<32>,
                         cudaFuncAttributeMaxDynamicSharedMemorySize, 32 * 257 * 4);
    cudaFuncSetAttribute(prepass_kernel<64>,
                         cudaFuncAttributeMaxDynamicSharedMemorySize, 64 * 257 * 4);

    // conv_mma kernels at ncu-capture slots 3 and 5.
    prep_all_kernel<<<546, 256>>>(w1, w2, w3);                                    // 0
    conv1_kernel<<<dim3(16, 4, 8), 256>>>(image, b1);                             // 1
    prepass_kernel<32><<<2048, 256, 32 * 257 * 4>>>(g1, be1);                     // 2
    conv_mma_kernel<32, 64, true><<<dim3(4, 256, 8), 128, SM2>>>(g1, be1, b2);    // 3
    prepass_kernel<64><<<2048, 256, 64 * 257 * 4>>>(g2, be2);                     // 4
    conv_mma_kernel<64, 128, false><<<dim3(4, 256, 16), 128, SM3>>>(g2, be2, b3); // 5
    patch_kernel<<<14, 256>>>(image, a_xy, p_xy, n_xy, out);                      // 6
    encode_kernel<<<8, 128>>>(n_xy, g2, be2, b3, g3, be3, out);                   // 7
}

// round 14
// speedup vs baseline: 2.4848x; 1.0320x over previous
#include <cuda_runtime.h>
#include <cuda_bf16.h>
#include <cstdint>

#define H_IMG 256
#define W_IMG 256
#define B_SZ 8
#define NPIX (B_SZ * H_IMG * W_IMG)
#define BN_EPS 1e-5f

// -------- scratch (allocation-free) --------
__device__ float g_y1[B_SZ * 32 * H_IMG * W_IMG];
__device__ float g_y2[B_SZ * 64 * H_IMG * W_IMG];
__device__ __nv_bfloat16 g_a1[(size_t)B_SZ * H_IMG * W_IMG * 64];    // [b][y][x][hi32|lo32]
__device__ __nv_bfloat16 g_a2[(size_t)B_SZ * H_IMG * W_IMG * 128];   // [b][y][x][hi64|lo64]
__device__ float g_w1t[3 * 9 * 32];
__device__ float g_w2t[32 * 9 * 64];
__device__ float g_w3t[64 * 9 * 128];
__device__ uint2 g_wb2[9 * 1 * 2 * 2 * 8 * 32];
__device__ uint2 g_wb3[9 * 2 * 2 * 4 * 8 * 32];
__device__ float g_s1[2 * 32];
__device__ float g_s2[2 * 64];
__device__ float g_s3[2 * 128];

#define MMA_BF16(d, A0, A1, A2, A3, B0, B1) \
    asm volatile( \
        "mma.sync.aligned.m16n8k16.row.col.f32.bf16.bf16.f32 " \
        "{%0,%1,%2,%3}, {%4,%5,%6,%7}, {%8,%9}, {%0,%1,%2,%3};" \
        : "+f"(d[0]), "+f"(d[1]), "+f"(d[2]), "+f"(d[3]) \
        : "r"(A0), "r"(A1), "r"(A2), "r"(A3), "r"(B0), "r"(B1))

#define LDSM_X4(r0, r1, r2, r3, addr) \
    asm volatile("ldmatrix.sync.aligned.m8n8.x4.shared.b16 {%0,%1,%2,%3}, [%4];" \
        : "=r"(r0), "=r"(r1), "=r"(r2), "=r"(r3) : "r"(addr))

__device__ __forceinline__ uint32_t smem_u32(const void* p) {
    uint32_t a;
    asm("{ .reg .u64 t; cvta.to.shared.u64 t, %1; cvt.u32.u64 %0, t; }" : "=r"(a) : "l"(p));
    return a;
}
#define CP_ASYNC16(smaddr, gptr) \
    asm volatile("cp.async.cg.shared.global [%0], [%1], 16;" :: "r"(smaddr), "l"(gptr))
#define CP_COMMIT()  asm volatile("cp.async.commit_group;" ::: "memory")
#define CP_WAIT0()   asm volatile("cp.async.wait_group 0;" ::: "memory")
#define CP_WAIT1()   asm volatile("cp.async.wait_group 1;" ::: "memory")

// ---------------- fused prep ----------------
template <int CIN, int COUT>
__device__ __forceinline__ void prep_wb_one(const float* __restrict__ w, int idx) {
    constexpr int KS = CIN / 16, NG = COUT / 64;
    uint2* wb = (CIN == 32) ? g_wb2 : g_wb3;
    int lane = idx & 31;
    int t = idx >> 5;
    int nb = t & 7; t >>= 3;
    int ks = t % KS; t /= KS;
    int part = t & 1; t >>= 1;
    int g = t % NG; int tap = t / NG;
    int o = g * 64 + nb * 8 + (lane >> 2);
    int k0 = ks * 16 + 2 * (lane & 3);
    auto enc = [&](int k) -> uint32_t {
        float x = w[(o * CIN + k) * 9 + tap];
        __nv_bfloat16 h = __float2bfloat16(x);
        __nv_bfloat16 v = h;
        if (part) v = __float2bfloat16(x - __bfloat162float(h));
        return (uint32_t)*reinterpret_cast<unsigned short*>(&v);
    };
    uint2 val;
    val.x = enc(k0) | (enc(k0 + 1) << 16);
    val.y = enc(k0 + 8) | (enc(k0 + 9) << 16);
    size_t BI = (size_t)((tap * NG + g) * 2 + part);
    wb[BI * (KS * 256) + (size_t)((ks * 4 + (nb >> 1)) * 32 + lane) * 2 + (nb & 1)] = val;
}

template <int CIN, int COUT>
__device__ __forceinline__ void transpose_one(const float* __restrict__ w, float* wt, int idx) {
    int o = idx % COUT;
    int r = idx / COUT;
    int ci = r / 9, t = r % 9;
    wt[idx] = w[(o * CIN + ci) * 9 + t];
}

__global__ void prep_all_kernel(const float* __restrict__ w1,
                                const float* __restrict__ w2,
                                const float* __restrict__ w3) {
    int idx = blockIdx.x * 256 + threadIdx.x;
    if (idx < 448) {
        if (idx < 64) g_s1[idx] = 0.f;
        else if (idx < 192) g_s2[idx - 64] = 0.f;
        else g_s3[idx - 192] = 0.f;
        return;
    }
    idx -= 448;
    if (idx < 864)  { transpose_one<3, 32>(w1, g_w1t, idx); return; }
    idx -= 864;
    if (idx < 18432) { transpose_one<32, 64>(w2, g_w2t, idx); return; }
    idx -= 18432;
    if (idx < 73728) { transpose_one<64, 128>(w3, g_w3t, idx); return; }
    idx -= 73728;
    if (idx < 9216)  { prep_wb_one<32, 64>(w2, idx); return; }
    idx -= 9216;
    if (idx < 36864) { prep_wb_one<64, 128>(w3, idx); return; }
}

// ---------------- BN+lrelu+bf16-split pre-pass: y -> a (pixel-major hi|lo) ----------------
template <int CIN>
__global__ void prepass_kernel(const float* __restrict__ gamma,
                               const float* __restrict__ beta) {
    const float* yin = (CIN == 32) ? g_y1 : g_y2;
    const float* st  = (CIN == 32) ? g_s1 : g_s2;
    __nv_bfloat16* aout = (CIN == 32) ? g_a1 : g_a2;
    extern __shared__ float tile[];   // [CIN][257]
    __shared__ float sc[CIN], sh[CIN];
    int row = blockIdx.x;             // b*256 + y
    int tid = threadIdx.x;
    if (tid < CIN) {
        float mean = st[tid] * (1.f / NPIX);
        float var  = st[CIN + tid] * (1.f / NPIX) - mean * mean;
        float is_  = rsqrtf(var + BN_EPS);
        float s    = gamma[tid] * is_;
        sc[tid] = s; sh[tid] = beta[tid] - mean * s;
    }
    __syncthreads();
    for (int i = tid; i < CIN * 256; i += 256) {
        int c = i >> 8, x = i & 255;
        float v = yin[(size_t)(row >> 8) * CIN * 65536 + (size_t)c * 65536
                      + ((row & 255) << 8) + x];
        v = fmaf(v, sc[c], sh[c]);
        v = v > 0.f ? v : 0.01f * v;
        tile[c * 257 + x] = v;
    }
    __syncthreads();
    uint32_t* ao = (uint32_t*)aout + (size_t)row * 256 * CIN;   // CIN uint32 per px
    for (int i = tid; i < 256 * (CIN / 2); i += 256) {
        int px = i / (CIN / 2), c2 = i % (CIN / 2);
        float v0 = tile[(2 * c2) * 257 + px];
        float v1 = tile[(2 * c2 + 1) * 257 + px];
        __nv_bfloat16 h0 = __float2bfloat16(v0), h1 = __float2bfloat16(v1);
        __nv_bfloat16 l0 = __float2bfloat16(v0 - __bfloat162float(h0));
        __nv_bfloat16 l1 = __float2bfloat16(v1 - __bfloat162float(h1));
        uint32_t hw = (uint32_t)*(unsigned short*)&h0 | ((uint32_t)*(unsigned short*)&h1 << 16);
        uint32_t lw = (uint32_t)*(unsigned short*)&l0 | ((uint32_t)*(unsigned short*)&l1 << 16);
        ao[(size_t)px * CIN + c2] = hw;
        ao[(size_t)px * CIN + CIN / 2 + c2] = lw;
    }
}

// ---------------- conv1: scalar (cin=3, tiny) ----------------
__global__ __launch_bounds__(256, 1) void conv1_kernel(const float* __restrict__ image,
                                                       const float* __restrict__ bias) {
    const int tx = threadIdx.x & 15, ty = threadIdx.x >> 4;
    const int tile_x = blockIdx.x * 16, tile_y = blockIdx.y * 64;
    const int b = blockIdx.z;
    __shared__ float s_in[3][66][18];
    __shared__ float s_w[3 * 9 * 32];
    float a0[32], a1[32], a2[32], a3[32];
#pragma unroll
    for (int o = 0; o < 32; o++) { a0[o] = a1[o] = a2[o] = a3[o] = 0.f; }
    for (int i = threadIdx.x; i < 3 * 66 * 18; i += 256) {
        int c = i / (66 * 18), r = i - c * (66 * 18);
        int yy = r / 18, xx = r - yy * 18;
        int gy = tile_y + yy - 1, gx = tile_x + xx - 1;
        float v = 0.f;
        if (gy >= 0 && gy < H_IMG && gx >= 0 && gx < W_IMG)
            v = image[((b * 3 + c) * H_IMG + gy) * W_IMG + gx];
        s_in[c][yy][xx] = v;
    }
    for (int i = threadIdx.x; i < 3 * 9 * 32; i += 256) s_w[i] = g_w1t[i];
    __syncthreads();
#pragma unroll 1
    for (int c = 0; c < 3; c++) {
#pragma unroll
        for (int t = 0; t < 9; t++) {
            float x0 = s_in[c][ty      + t / 3][tx + t % 3];
            float x1 = s_in[c][ty + 16 + t / 3][tx + t % 3];
            float x2 = s_in[c][ty + 32 + t / 3][tx + t % 3];
            float x3 = s_in[c][ty + 48 + t / 3][tx + t % 3];
            const float4* wv = (const float4*)&s_w[(c * 9 + t) * 32];
#pragma unroll
            for (int qq = 0; qq < 8; qq++) {
                float4 w4 = wv[qq];
                a0[qq*4+0]=fmaf(x0,w4.x,a0[qq*4+0]); a0[qq*4+1]=fmaf(x0,w4.y,a0[qq*4+1]);
                a0[qq*4+2]=fmaf(x0,w4.z,a0[qq*4+2]); a0[qq*4+3]=fmaf(x0,w4.w,a0[qq*4+3]);
                a1[qq*4+0]=fmaf(x1,w4.x,a1[qq*4+0]); a1[qq*4+1]=fmaf(x1,w4.y,a1[qq*4+1]);
                a1[qq*4+2]=fmaf(x1,w4.z,a1[qq*4+2]); a1[qq*4+3]=fmaf(x1,w4.w,a1[qq*4+3]);
                a2[qq*4+0]=fmaf(x2,w4.x,a2[qq*4+0]); a2[qq*4+1]=fmaf(x2,w4.y,a2[qq*4+1]);
                a2[qq*4+2]=fmaf(x2,w4.z,a2[qq*4+2]); a2[qq*4+3]=fmaf(x2,w4.w,a2[qq*4+3]);
                a3[qq*4+0]=fmaf(x3,w4.x,a3[qq*4+0]); a3[qq*4+1]=fmaf(x3,w4.y,a3[qq*4+1]);
                a3[qq*4+2]=fmaf(x3,w4.z,a3[qq*4+2]); a3[qq*4+3]=fmaf(x3,w4.w,a3[qq*4+3]);
            }
        }
    }
    int lane = threadIdx.x & 31;
#pragma unroll
    for (int o = 0; o < 32; o++) {
        float bv = bias[o];
        a0[o] += bv; a1[o] += bv; a2[o] += bv; a3[o] += bv;
        int p = ((b * 32 + o) * H_IMG + tile_y + ty) * W_IMG + tile_x + tx;
        g_y1[p] = a0[o]; g_y1[p + 16*W_IMG] = a1[o];
        g_y1[p + 32*W_IMG] = a2[o]; g_y1[p + 48*W_IMG] = a3[o];
        float v = a0[o]+a1[o]+a2[o]+a3[o];
        float v2 = a0[o]*a0[o]+a1[o]*a1[o]+a2[o]*a2[o]+a3[o]*a3[o];
#pragma unroll
        for (int s = 16; s > 0; s >>= 1) {
            v  += __shfl_down_sync(0xffffffffu, v, s);
            v2 += __shfl_down_sync(0xffffffffu, v2, s);
        }
        if (lane == 0) { atomicAdd(&g_s1[o], v); atomicAdd(&g_s1[32 + o], v2); }
    }
}

// ---------------- warp-MMA implicit-GEMM conv (conv2 / conv3) ----------------
// Warp = 64M x 16N (mt 0..3, warp owns N-quarter): halves B smem reads, no dup.
// DB=true: double-buffered cp.async staging (stage dy+1 overlaps MMA dy).
template <int CIN, int COUT, bool WRITE, bool DB>
__global__ __launch_bounds__(128, 3)
void conv_mma_kernel(const float* __restrict__ in_gamma,
                     const float* __restrict__ in_beta,
                     const float* __restrict__ bias)
{
    constexpr int KS    = CIN / 16;
    constexpr int NG    = COUT / 64;
    constexpr int AROW  = CIN * 4 + 16;
    constexpr int ABUF  = 64 * AROW;
    constexpr int BTAP  = 2 * KS * 8 * 32 * 8;
    constexpr int BBUF  = 3 * BTAP;
    constexpr int STAGE = ABUF + BBUF;
    constexpr int NSTG  = DB ? 2 : 1;
    constexpr int HW    = H_IMG * W_IMG;

    const float* yfin = (CIN == 32) ? g_y1 : g_y2;
    const char* ain   = (const char*)((CIN == 32) ? (const void*)g_a1 : (const void*)g_a2);
    const float* ist  = (CIN == 32) ? g_s1 : g_s2;
    float* ost        = (CIN == 32) ? g_s2 : g_s3;
    const float* wt   = (CIN == 32) ? g_w2t : g_w3t;
    const uint2* wb   = (CIN == 32) ? g_wb2 : g_wb3;

    extern __shared__ char sm[];
    float* sScale = (float*)(sm + NSTG * STAGE);
    float* sShift = sScale + CIN;
    float* sEdge  = sShift + CIN;
    float* sL     = sEdge + 6 * CIN;
    float* sR     = sL + 64;
    float* sBias  = sR + 64;

    const int tid = threadIdx.x, wid = tid >> 5, lane = tid & 31;
    const int g8 = lane >> 2, q = lane & 3;
    const int x0 = blockIdx.x * 64, y = blockIdx.y;
    const int b = blockIdx.z / NG, g = blockIdx.z % NG;

    auto issue_stage = [&](int dy, int s) {
        char* base = sm + s * STAGE;
        uint32_t aSm = smem_u32(base);
        uint32_t bSm = aSm + ABUF;
        for (int t3 = 0; t3 < 3; t3++) {
            const char* gsrc = (const char*)wb + (size_t)((dy * 3 + t3) * NG + g) * BTAP;
            for (int i = tid; i < BTAP / 16; i += 128)
                CP_ASYNC16(bSm + t3 * BTAP + i * 16, gsrc + i * 16);
        }
        int ydy = y + dy - 1;
        if (ydy < 0 || ydy >= H_IMG) {
            for (int i = tid; i < ABUF / 16; i += 128)
                ((uint4*)base)[i] = make_uint4(0, 0, 0, 0);
        } else {
            const char* src = ain + ((size_t)(b * H_IMG + ydy) * W_IMG + x0) * (size_t)(4 * CIN);
            for (int i = tid; i < 64 * (CIN / 4); i += 128) {
                int p = i / (CIN / 4), j = i % (CIN / 4);
                CP_ASYNC16(aSm + p * AROW + j * 16, src + p * 4 * CIN + j * 16);
            }
        }
        CP_COMMIT();
    };

    issue_stage(0, 0);   // overlaps setup + fixup below

    if (tid < CIN) {
        float mean = ist[tid] * (1.f / NPIX);
        float var  = ist[CIN + tid] * (1.f / NPIX) - mean * mean;
        float is_  = rsqrtf(var + BN_EPS);
        float sc   = in_gamma[tid] * is_;
        sScale[tid] = sc; sShift[tid] = in_beta[tid] - mean * sc;
    }
    if (tid < 64) sBias[tid] = bias[g * 64 + tid];
    __syncthreads();

    // ---- edge activations + exact strip-boundary fixup (fp32 source) ----
    for (int i = tid; i < 6 * CIN; i += 128) {
        int side = i / (3 * CIN), rem = i % (3 * CIN);
        int dyy = rem / CIN, c = rem % CIN;
        int ydy = y + dyy - 1;
        int xx = side ? x0 + 64 : x0 - 1;
        float v = 0.f;
        if (ydy >= 0 && ydy < H_IMG && xx >= 0 && xx < W_IMG) {
            v = yfin[((size_t)b * CIN + c) * HW + (size_t)ydy * W_IMG + xx];
            v = fmaf(v, sScale[c], sShift[c]);
            v = v > 0.f ? v : 0.01f * v;
        }
        sEdge[i] = v;
    }
    __syncthreads();
    {
        int o = tid & 63, side = tid >> 6;
        float accf = 0.f;
        for (int dyy = 0; dyy < 3; dyy++)
            for (int c = 0; c < CIN; c++)
                accf = fmaf(sEdge[side * 3 * CIN + dyy * CIN + c],
                            wt[(c * 9 + dyy * 3 + (side ? 2 : 0)) * COUT + g * 64 + o], accf);
        (side ? sR : sL)[o] = accf;
    }

    float acc[4][3][2][4];
#pragma unroll
    for (int mt = 0; mt < 4; mt++)
#pragma unroll
        for (int dx = 0; dx < 3; dx++)
#pragma unroll
            for (int nb = 0; nb < 2; nb++)
#pragma unroll
                for (int r = 0; r < 4; r++) acc[mt][dx][nb][r] = 0.f;

    const int lrow = ((lane >> 3) & 1) * 8 + (lane & 7);
    const uint32_t aOff = (uint32_t)lrow * AROW + ((lane >> 4) & 1) * 16;

    for (int dy = 0; dy < 3; dy++) {
        __syncthreads();   // WAR: all warps done with previous MMA reads
        if (DB) {
            if (dy < 2) { issue_stage(dy + 1, (dy + 1) & 1); CP_WAIT1(); }
            else        { CP_WAIT0(); }
        } else {
            if (dy > 0) issue_stage(dy, 0);
            CP_WAIT0();
        }
        __syncthreads();

        char* base = sm + (DB ? (dy & 1) * STAGE : 0);
        const uint32_t aAddr0 = smem_u32(base) + aOff;
#pragma unroll
        for (int ks = 0; ks < KS; ks++) {
            uint32_t ah[4][4], al[4][4];
#pragma unroll
            for (int mt = 0; mt < 4; mt++) {
                uint32_t ad = aAddr0 + mt * 16 * AROW + 32 * ks;
                LDSM_X4(ah[mt][0], ah[mt][1], ah[mt][2], ah[mt][3], ad);
                LDSM_X4(al[mt][0], al[mt][1], al[mt][2], al[mt][3], ad + 2 * CIN);
            }
#pragma unroll
            for (int dx = 0; dx < 3; dx++) {
                const uint4* sB4 = (const uint4*)(base + ABUF + dx * BTAP);
                uint4 bh = sB4[(ks * 4 + wid) * 32 + lane];
                uint4 bl = sB4[(ks * 4 + wid) * 32 + lane + KS * 128];
#pragma unroll
                for (int mt = 0; mt < 4; mt++) {
                    MMA_BF16(acc[mt][dx][0], ah[mt][0], ah[mt][1], ah[mt][2], ah[mt][3], bh.x, bh.y);
                    MMA_BF16(acc[mt][dx][0], ah[mt][0], ah[mt][1], ah[mt][2], ah[mt][3], bl.x, bl.y);
                    MMA_BF16(acc[mt][dx][0], al[mt][0], al[mt][1], al[mt][2], al[mt][3], bh.x, bh.y);
                    MMA_BF16(acc[mt][dx][1], ah[mt][0], ah[mt][1], ah[mt][2], ah[mt][3], bh.z, bh.w);
                    MMA_BF16(acc[mt][dx][1], ah[mt][0], ah[mt][1], ah[mt][2], ah[mt][3], bl.z, bl.w);
                    MMA_BF16(acc[mt][dx][1], al[mt][0], al[mt][1], al[mt][2], al[mt][3], bh.z, bh.w);
                }
            }
        }
    }
    __syncthreads();

    // ---- epilogue (scratch aliases dead staging buffers) ----
    float* S0 = (float*)sm;
    float* S2 = S0 + 64 * 65;
#pragma unroll
    for (int mt = 0; mt < 4; mt++)
#pragma unroll
        for (int nb = 0; nb < 2; nb++)
#pragma unroll
            for (int r = 0; r < 4; r++) {
                int p = mt * 16 + g8 + ((r >= 2) ? 8 : 0);
                int n = wid * 16 + nb * 8 + 2 * q + (r & 1);
                S0[p * 65 + n] = acc[mt][0][nb][r];
                S2[p * 65 + n] = acc[mt][2][nb][r];
            }
    __syncthreads();

#pragma unroll
    for (int nb = 0; nb < 2; nb++) {
        float se = 0.f, so = 0.f, qe = 0.f, qo = 0.f;
#pragma unroll
        for (int mt = 0; mt < 4; mt++) {
            float v[4];
#pragma unroll
            for (int r = 0; r < 4; r++) {
                int p = mt * 16 + g8 + ((r >= 2) ? 8 : 0);
                int n = wid * 16 + nb * 8 + 2 * q + (r & 1);
                float t = acc[mt][1][nb][r];
                t += (p > 0)  ? S0[(p - 1) * 65 + n] : sL[n];
                t += (p < 63) ? S2[(p + 1) * 65 + n] : sR[n];
                t += sBias[n];
                v[r] = t;
                if (WRITE)
                    g_y2[(((size_t)b * COUT + g * 64 + n) * H_IMG + y) * W_IMG + x0 + p] = t;
            }
            se += v[0] + v[2]; so += v[1] + v[3];
            qe += v[0]*v[0] + v[2]*v[2]; qo += v[1]*v[1] + v[3]*v[3];
        }
#pragma unroll
        for (int sh = 4; sh <= 16; sh <<= 1) {
            se += __shfl_xor_sync(0xffffffffu, se, sh);
            so += __shfl_xor_sync(0xffffffffu, so, sh);
            qe += __shfl_xor_sync(0xffffffffu, qe, sh);
            qo += __shfl_xor_sync(0xffffffffu, qo, sh);
        }
        if (lane < 4) {
            int ne = wid * 16 + nb * 8 + 2 * lane;
            atomicAdd(&ost[g * 64 + ne], se);
            atomicAdd(&ost[COUT + g * 64 + ne], qe);
            atomicAdd(&ost[g * 64 + ne + 1], so);
            atomicAdd(&ost[COUT + g * 64 + ne + 1], qo);
        }
    }
}

// ---------------- patch gather + encode ----------------
__global__ void patch_kernel(const float* __restrict__ image,
                             const int* __restrict__ a_xy, const int* __restrict__ p_xy,
                             const int* __restrict__ n_xy, float* __restrict__ out)
{
    int idx = blockIdx.x * blockDim.x + threadIdx.x;
    if (idx >= 3528) return;
    int which = idx / 1176;
    int r  = idx % 1176;
    int b  = r / 147, r2 = r % 147;
    int c  = r2 / 49, p = r2 % 49;
    int dy = p / 7, dx = p % 7;
    const int* xy = (which == 0) ? a_xy : (which == 1 ? p_xy : n_xy);
    int row = xy[b * 64 + 62], col = xy[b * 64 + 63];
    out[idx] = image[((b * 3 + c) * H_IMG + (row - 3 + dy)) * W_IMG + (col - 3 + dx)];
}

__global__ void encode_kernel(const int* __restrict__ n_xy,
                              const float* __restrict__ bn2_g, const float* __restrict__ bn2_b,
                              const float* __restrict__ conv3_b,
                              const float* __restrict__ bn3_g, const float* __restrict__ bn3_b,
                              float* __restrict__ out)
{
    int b = blockIdx.x, o = threadIdx.x;
    __shared__ float s_z2[576];
    int row = n_xy[b * 64 + 62], col = n_xy[b * 64 + 63];
    for (int i = threadIdx.x; i < 576; i += 128) {
        int c = i / 9, p = i % 9;
        int ky = p / 3 - 1, kx = p % 3 - 1;
        float mean = g_s2[c] * (1.f / NPIX);
        float var  = g_s2[64 + c] * (1.f / NPIX) - mean * mean;
        float is   = rsqrtf(var + BN_EPS);
        float sc   = bn2_g[c] * is;
        float sh   = bn2_b[c] - mean * sc;
        float v = g_y2[((b * 64 + c) * H_IMG + row + ky) * W_IMG + col + kx];
        v = v * sc + sh;
        v = v > 0.f ? v : 0.01f * v;
        s_z2[i] = v;
    }
    __syncthreads();
    float acc = conv3_b[o];
    for (int i = 0; i < 576; i++) acc = fmaf(s_z2[i], g_w3t[i * 128 + o], acc);
    float mean = g_s3[o] * (1.f / NPIX);
    float var  = g_s3[128 + o] * (1.f / NPIX) - mean * mean;
    float is   = rsqrtf(var + BN_EPS);
    float v = (acc - mean) * is * bn3_g[o] + bn3_b[o];
    v = v > 0.f ? v : 0.01f * v;
    out[3528 + b * 128 + o] = v;
}

extern "C" void kernel_launch(void* const* d_in, const int* in_sizes, int n_in,
                              void* d_out, int out_size) {
    const float* image = (const float*)d_in[0];
    const int*   a_xy  = (const int*)d_in[1];
    const int*   p_xy  = (const int*)d_in[2];
    const int*   n_xy  = (const int*)d_in[3];
    const float* w1  = (const float*)d_in[4];
    const float* b1  = (const float*)d_in[5];
    const float* g1  = (const float*)d_in[6];
    const float* be1 = (const float*)d_in[7];
    const float* w2  = (const float*)d_in[8];
    const float* b2  = (const float*)d_in[9];
    const float* g2  = (const float*)d_in[10];
    const float* be2 = (const float*)d_in[11];
    const float* w3  = (const float*)d_in[12];
    const float* b3  = (const float*)d_in[13];
    const float* g3  = (const float*)d_in[14];
    const float* be3 = (const float*)d_in[15];
    float* out = (float*)d_out;

    // conv2: double-buffered (2 stages); conv3: single stage
    const int SM2 = 2 * (64*(32*4+16) + 3*(2*2*2048)) + (8*32+192)*4;   // 69,376
    const int SM3 = (64*(64*4+16) + 3*(2*4*2048)) + (8*64+192)*4;       // 69,376
    cudaFuncSetAttribute(conv_mma_kernel<32, 64, true, true>,
                         cudaFuncAttributeMaxDynamicSharedMemorySize, SM2);
    cudaFuncSetAttribute(conv_mma_kernel<64, 128, false, false>,
                         cudaFuncAttributeMaxDynamicSharedMemorySize, SM3);
    cudaFuncSetAttribute(prepass_kernel<32>,
                         cudaFuncAttributeMaxDynamicSharedMemorySize, 32 * 257 * 4);
    cudaFuncSetAttribute(prepass_kernel<64>,
                         cudaFuncAttributeMaxDynamicSharedMemorySize, 64 * 257 * 4);

    // conv_mma kernels at ncu-capture slots 3 and 5.
    prep_all_kernel<<<546, 256>>>(w1, w2, w3);                                           // 0
    conv1_kernel<<<dim3(16, 4, 8), 256>>>(image, b1);                                    // 1
    prepass_kernel<32><<<2048, 256, 32 * 257 * 4>>>(g1, be1);                            // 2
    conv_mma_kernel<32, 64, true, true><<<dim3(4, 256, 8), 128, SM2>>>(g1, be1, b2);     // 3
    prepass_kernel<64><<<2048, 256, 64 * 257 * 4>>>(g2, be2);                            // 4
    conv_mma_kernel<64, 128, false, false><<<dim3(4, 256, 16), 128, SM3>>>(g2, be2, b3); // 5
    patch_kernel<<<14, 256>>>(image, a_xy, p_xy, n_xy, out);                             // 6
    encode_kernel<<<8, 128>>>(n_xy, g2, be2, b3, g3, be3, out);                          // 7
}

// round 15
// speedup vs baseline: 2.5394x; 1.0220x over previous
#include <cuda_runtime.h>
#include <cuda_bf16.h>
#include <cstdint>

#define H_IMG 256
#define W_IMG 256
#define B_SZ 8
#define NPIX (B_SZ * H_IMG * W_IMG)
#define BN_EPS 1e-5f

// -------- scratch (allocation-free) --------
__device__ float g_y1[B_SZ * 32 * H_IMG * W_IMG];
__device__ float g_y2[B_SZ * 64 * H_IMG * W_IMG];
__device__ __nv_bfloat16 g_a1[(size_t)B_SZ * H_IMG * W_IMG * 64];    // [b][y][x][hi32|lo32]
__device__ __nv_bfloat16 g_a2[(size_t)B_SZ * H_IMG * W_IMG * 128];   // [b][y][x][hi64|lo64]
__device__ float g_w1t[3 * 9 * 32];
__device__ float g_w2t[32 * 9 * 64];
__device__ float g_w3t[64 * 9 * 128];
__device__ uint2 g_wb2[9 * 1 * 2 * 2 * 8 * 32];
__device__ uint2 g_wb3[9 * 2 * 2 * 4 * 8 * 32];
__device__ float g_s1[2 * 32];
__device__ float g_s2[2 * 64];
__device__ float g_s3[2 * 128];

#define MMA_BF16(d, A0, A1, A2, A3, B0, B1) \
    asm volatile( \
        "mma.sync.aligned.m16n8k16.row.col.f32.bf16.bf16.f32 " \
        "{%0,%1,%2,%3}, {%4,%5,%6,%7}, {%8,%9}, {%0,%1,%2,%3};" \
        : "+f"(d[0]), "+f"(d[1]), "+f"(d[2]), "+f"(d[3]) \
        : "r"(A0), "r"(A1), "r"(A2), "r"(A3), "r"(B0), "r"(B1))

#define LDSM_X4(r0, r1, r2, r3, addr) \
    asm volatile("ldmatrix.sync.aligned.m8n8.x4.shared.b16 {%0,%1,%2,%3}, [%4];" \
        : "=r"(r0), "=r"(r1), "=r"(r2), "=r"(r3) : "r"(addr))

__device__ __forceinline__ uint32_t smem_u32(const void* p) {
    uint32_t a;
    asm("{ .reg .u64 t; cvta.to.shared.u64 t, %1; cvt.u32.u64 %0, t; }" : "=r"(a) : "l"(p));
    return a;
}
#define CP_ASYNC16(smaddr, gptr) \
    asm volatile("cp.async.cg.shared.global [%0], [%1], 16;" :: "r"(smaddr), "l"(gptr))
#define CP_COMMIT()  asm volatile("cp.async.commit_group;" ::: "memory")
#define CP_WAIT0()   asm volatile("cp.async.wait_group 0;" ::: "memory")
#define CP_WAIT1()   asm volatile("cp.async.wait_group 1;" ::: "memory")

// ---------------- fused prep ----------------
template <int CIN, int COUT>
__device__ __forceinline__ void prep_wb_one(const float* __restrict__ w, int idx) {
    constexpr int KS = CIN / 16, NG = COUT / 64;
    uint2* wb = (CIN == 32) ? g_wb2 : g_wb3;
    int lane = idx & 31;
    int t = idx >> 5;
    int nb = t & 7; t >>= 3;
    int ks = t % KS; t /= KS;
    int part = t & 1; t >>= 1;
    int g = t % NG; int tap = t / NG;
    int o = g * 64 + nb * 8 + (lane >> 2);
    int k0 = ks * 16 + 2 * (lane & 3);
    auto enc = [&](int k) -> uint32_t {
        float x = w[(o * CIN + k) * 9 + tap];
        __nv_bfloat16 h = __float2bfloat16(x);
        __nv_bfloat16 v = h;
        if (part) v = __float2bfloat16(x - __bfloat162float(h));
        return (uint32_t)*reinterpret_cast<unsigned short*>(&v);
    };
    uint2 val;
    val.x = enc(k0) | (enc(k0 + 1) << 16);
    val.y = enc(k0 + 8) | (enc(k0 + 9) << 16);
    size_t BI = (size_t)((tap * NG + g) * 2 + part);
    wb[BI * (KS * 256) + (size_t)((ks * 4 + (nb >> 1)) * 32 + lane) * 2 + (nb & 1)] = val;
}

template <int CIN, int COUT>
__device__ __forceinline__ void transpose_one(const float* __restrict__ w, float* wt, int idx) {
    int o = idx % COUT;
    int r = idx / COUT;
    int ci = r / 9, t = r % 9;
    wt[idx] = w[(o * CIN + ci) * 9 + t];
}

__global__ void prep_all_kernel(const float* __restrict__ w1,
                                const float* __restrict__ w2,
                                const float* __restrict__ w3) {
    int idx = blockIdx.x * 256 + threadIdx.x;
    if (idx < 448) {
        if (idx < 64) g_s1[idx] = 0.f;
        else if (idx < 192) g_s2[idx - 64] = 0.f;
        else g_s3[idx - 192] = 0.f;
        return;
    }
    idx -= 448;
    if (idx < 864)  { transpose_one<3, 32>(w1, g_w1t, idx); return; }
    idx -= 864;
    if (idx < 18432) { transpose_one<32, 64>(w2, g_w2t, idx); return; }
    idx -= 18432;
    if (idx < 73728) { transpose_one<64, 128>(w3, g_w3t, idx); return; }
    idx -= 73728;
    if (idx < 9216)  { prep_wb_one<32, 64>(w2, idx); return; }
    idx -= 9216;
    if (idx < 36864) { prep_wb_one<64, 128>(w3, idx); return; }
}

// ---------------- BN+lrelu+bf16-split pre-pass ----------------
template <int CIN>
__global__ void prepass_kernel(const float* __restrict__ gamma,
                               const float* __restrict__ beta) {
    const float* yin = (CIN == 32) ? g_y1 : g_y2;
    const float* st  = (CIN == 32) ? g_s1 : g_s2;
    __nv_bfloat16* aout = (CIN == 32) ? g_a1 : g_a2;
    extern __shared__ float tile[];   // [CIN][257]
    __shared__ float sc[CIN], sh[CIN];
    int row = blockIdx.x;             // b*256 + y
    int tid = threadIdx.x;
    if (tid < CIN) {
        float mean = st[tid] * (1.f / NPIX);
        float var  = st[CIN + tid] * (1.f / NPIX) - mean * mean;
        float is_  = rsqrtf(var + BN_EPS);
        float s    = gamma[tid] * is_;
        sc[tid] = s; sh[tid] = beta[tid] - mean * s;
    }
    __syncthreads();
    for (int i = tid; i < CIN * 256; i += 256) {
        int c = i >> 8, x = i & 255;
        float v = yin[(size_t)(row >> 8) * CIN * 65536 + (size_t)c * 65536
                      + ((row & 255) << 8) + x];
        v = fmaf(v, sc[c], sh[c]);
        v = v > 0.f ? v : 0.01f * v;
        tile[c * 257 + x] = v;
    }
    __syncthreads();
    uint32_t* ao = (uint32_t*)aout + (size_t)row * 256 * CIN;
    for (int i = tid; i < 256 * (CIN / 2); i += 256) {
        int px = i / (CIN / 2), c2 = i % (CIN / 2);
        float v0 = tile[(2 * c2) * 257 + px];
        float v1 = tile[(2 * c2 + 1) * 257 + px];
        __nv_bfloat16 h0 = __float2bfloat16(v0), h1 = __float2bfloat16(v1);
        __nv_bfloat16 l0 = __float2bfloat16(v0 - __bfloat162float(h0));
        __nv_bfloat16 l1 = __float2bfloat16(v1 - __bfloat162float(h1));
        uint32_t hw = (uint32_t)*(unsigned short*)&h0 | ((uint32_t)*(unsigned short*)&h1 << 16);
        uint32_t lw = (uint32_t)*(unsigned short*)&l0 | ((uint32_t)*(unsigned short*)&l1 << 16);
        ao[(size_t)px * CIN + c2] = hw;
        ao[(size_t)px * CIN + CIN / 2 + c2] = lw;
    }
}

// ---------------- conv1: scalar (cin=3, tiny) ----------------
__global__ __launch_bounds__(256, 1) void conv1_kernel(const float* __restrict__ image,
                                                       const float* __restrict__ bias) {
    const int tx = threadIdx.x & 15, ty = threadIdx.x >> 4;
    const int tile_x = blockIdx.x * 16, tile_y = blockIdx.y * 64;
    const int b = blockIdx.z;
    __shared__ float s_in[3][66][18];
    __shared__ float s_w[3 * 9 * 32];
    float a0[32], a1[32], a2[32], a3[32];
#pragma unroll
    for (int o = 0; o < 32; o++) { a0[o] = a1[o] = a2[o] = a3[o] = 0.f; }
    for (int i = threadIdx.x; i < 3 * 66 * 18; i += 256) {
        int c = i / (66 * 18), r = i - c * (66 * 18);
        int yy = r / 18, xx = r - yy * 18;
        int gy = tile_y + yy - 1, gx = tile_x + xx - 1;
        float v = 0.f;
        if (gy >= 0 && gy < H_IMG && gx >= 0 && gx < W_IMG)
            v = image[((b * 3 + c) * H_IMG + gy) * W_IMG + gx];
        s_in[c][yy][xx] = v;
    }
    for (int i = threadIdx.x; i < 3 * 9 * 32; i += 256) s_w[i] = g_w1t[i];
    __syncthreads();
#pragma unroll 1
    for (int c = 0; c < 3; c++) {
#pragma unroll
        for (int t = 0; t < 9; t++) {
            float x0 = s_in[c][ty      + t / 3][tx + t % 3];
            float x1 = s_in[c][ty + 16 + t / 3][tx + t % 3];
            float x2 = s_in[c][ty + 32 + t / 3][tx + t % 3];
            float x3 = s_in[c][ty + 48 + t / 3][tx + t % 3];
            const float4* wv = (const float4*)&s_w[(c * 9 + t) * 32];
#pragma unroll
            for (int qq = 0; qq < 8; qq++) {
                float4 w4 = wv[qq];
                a0[qq*4+0]=fmaf(x0,w4.x,a0[qq*4+0]); a0[qq*4+1]=fmaf(x0,w4.y,a0[qq*4+1]);
                a0[qq*4+2]=fmaf(x0,w4.z,a0[qq*4+2]); a0[qq*4+3]=fmaf(x0,w4.w,a0[qq*4+3]);
                a1[qq*4+0]=fmaf(x1,w4.x,a1[qq*4+0]); a1[qq*4+1]=fmaf(x1,w4.y,a1[qq*4+1]);
                a1[qq*4+2]=fmaf(x1,w4.z,a1[qq*4+2]); a1[qq*4+3]=fmaf(x1,w4.w,a1[qq*4+3]);
                a2[qq*4+0]=fmaf(x2,w4.x,a2[qq*4+0]); a2[qq*4+1]=fmaf(x2,w4.y,a2[qq*4+1]);
                a2[qq*4+2]=fmaf(x2,w4.z,a2[qq*4+2]); a2[qq*4+3]=fmaf(x2,w4.w,a2[qq*4+3]);
                a3[qq*4+0]=fmaf(x3,w4.x,a3[qq*4+0]); a3[qq*4+1]=fmaf(x3,w4.y,a3[qq*4+1]);
                a3[qq*4+2]=fmaf(x3,w4.z,a3[qq*4+2]); a3[qq*4+3]=fmaf(x3,w4.w,a3[qq*4+3]);
            }
        }
    }
    int lane = threadIdx.x & 31;
#pragma unroll
    for (int o = 0; o < 32; o++) {
        float bv = bias[o];
        a0[o] += bv; a1[o] += bv; a2[o] += bv; a3[o] += bv;
        int p = ((b * 32 + o) * H_IMG + tile_y + ty) * W_IMG + tile_x + tx;
        g_y1[p] = a0[o]; g_y1[p + 16*W_IMG] = a1[o];
        g_y1[p + 32*W_IMG] = a2[o]; g_y1[p + 48*W_IMG] = a3[o];
        float v = a0[o]+a1[o]+a2[o]+a3[o];
        float v2 = a0[o]*a0[o]+a1[o]*a1[o]+a2[o]*a2[o]+a3[o]*a3[o];
#pragma unroll
        for (int s = 16; s > 0; s >>= 1) {
            v  += __shfl_down_sync(0xffffffffu, v, s);
            v2 += __shfl_down_sync(0xffffffffu, v2, s);
        }
        if (lane == 0) { atomicAdd(&g_s1[o], v); atomicAdd(&g_s1[32 + o], v2); }
    }
}

// ---------------- conv2: persistent-B, rolling-A, TY rows per CTA ----------------
// B: all 9 taps resident (72KB). A: 4-slot ring, each row loaded once, prefetch
// depth 1. Epilogue: register-only via warp shuffles (warp owns all 64 M px).
__global__ __launch_bounds__(128, 2)
void conv2_persist_kernel(const float* __restrict__ in_gamma,
                          const float* __restrict__ in_beta,
                          const float* __restrict__ bias)
{
    constexpr int CIN = 32, COUT = 64, KS = 2, TY = 8;
    constexpr int AROW = 144, ABUF = 64 * AROW;     // 9216
    constexpr int BTAP = 8192, BALL = 9 * BTAP;     // 73728
    constexpr int HW = H_IMG * W_IMG;

    extern __shared__ char sm[];
    char* smB  = sm;
    char* ring = sm + BALL;
    float* sScale = (float*)(sm + BALL + 4 * ABUF);
    float* sShift = sScale + CIN;
    float* sL     = sShift + CIN;
    float* sR     = sL + 64;
    float* sBias  = sR + 64;

    const int tid = threadIdx.x, wid = tid >> 5, lane = tid & 31;
    const int g8 = lane >> 2, q = lane & 3;
    const int x0 = blockIdx.x * 64, y0 = blockIdx.y * TY;
    const int b = blockIdx.z;
    const char* ain = (const char*)g_a1;

    auto issue_A = [&](int row, int slot) {
        char* base = ring + slot * ABUF;
        if (row < 0 || row >= H_IMG) {
            for (int i = tid; i < ABUF / 16; i += 128)
                ((uint4*)base)[i] = make_uint4(0, 0, 0, 0);
        } else {
            uint32_t aSm = smem_u32(base);
            const char* src = ain + ((size_t)(b * H_IMG + row) * W_IMG + x0) * 128;
            for (int i = tid; i < 64 * 8; i += 128) {
                int p = i >> 3, j = i & 7;
                CP_ASYNC16(aSm + p * AROW + j * 16, src + p * 128 + j * 16);
            }
        }
        CP_COMMIT();
    };

    // prologue: B all taps + first 3 A rows
    {
        const char* gB = (const char*)g_wb2;
        uint32_t dst = smem_u32(smB);
        for (int i = tid; i < BALL / 16; i += 128) CP_ASYNC16(dst + i * 16, gB + i * 16);
        CP_COMMIT();
    }
    issue_A(y0 - 1, 0);
    issue_A(y0,     1);
    issue_A(y0 + 1, 2);
    if (tid < CIN) {
        float mean = g_s1[tid] * (1.f / NPIX);
        float var  = g_s1[CIN + tid] * (1.f / NPIX) - mean * mean;
        float is_  = rsqrtf(var + BN_EPS);
        float sc   = in_gamma[tid] * is_;
        sScale[tid] = sc; sShift[tid] = in_beta[tid] - mean * sc;
    }
    if (tid < 64) sBias[tid] = bias[tid];

    const int lrow = ((lane >> 3) & 1) * 8 + (lane & 7);
    const uint32_t aOff = (uint32_t)lrow * AROW + ((lane >> 4) & 1) * 16;

    float rse[2] = {0.f, 0.f}, rso[2] = {0.f, 0.f};
    float rqe[2] = {0.f, 0.f}, rqo[2] = {0.f, 0.f};

    for (int t = 0; t < TY; t++) {
        int y = y0 + t;
        __syncthreads();                 // prev row reads done; prologue visible
        issue_A(y + 2, (t + 3) & 3);
        // edge fixup (straight from fp32 global, L1-hot)
        {
            int o = tid & 63, side = tid >> 6;
            float accf = 0.f;
            int xx = side ? x0 + 64 : x0 - 1;
            if (xx >= 0 && xx < W_IMG) {
                for (int dyy = 0; dyy < 3; dyy++) {
                    int ydy = y + dyy - 1;
                    if (ydy < 0 || ydy >= H_IMG) continue;
                    for (int c = 0; c < CIN; c++) {
                        float v = g_y1[((size_t)b * CIN + c) * HW + (size_t)ydy * W_IMG + xx];
                        v = fmaf(v, sScale[c], sShift[c]);
                        v = v > 0.f ? v : 0.01f * v;
                        accf = fmaf(v, g_w2t[(c * 9 + dyy * 3 + (side ? 2 : 0)) * COUT + o], accf);
                    }
                }
            }
            (side ? sR : sL)[o] = accf;
        }
        CP_WAIT1();
        __syncthreads();                 // A rows <= y+1 and sL/sR visible

        float acc[4][3][2][4];
#pragma unroll
        for (int mt = 0; mt < 4; mt++)
#pragma unroll
            for (int dx = 0; dx < 3; dx++)
#pragma unroll
                for (int nb = 0; nb < 2; nb++)
#pragma unroll
                    for (int r = 0; r < 4; r++) acc[mt][dx][nb][r] = 0.f;

#pragma unroll
        for (int dy = 0; dy < 3; dy++) {
            const uint32_t aAddr0 = smem_u32(ring + ((t + dy) & 3) * ABUF) + aOff;
#pragma unroll
            for (int ks = 0; ks < KS; ks++) {
                uint32_t ah[4][4], al[4][4];
#pragma unroll
                for (int mt = 0; mt < 4; mt++) {
                    uint32_t ad = aAddr0 + mt * 16 * AROW + 32 * ks;
                    LDSM_X4(ah[mt][0], ah[mt][1], ah[mt][2], ah[mt][3], ad);
                    LDSM_X4(al[mt][0], al[mt][1], al[mt][2], al[mt][3], ad + 2 * CIN);
                }
#pragma unroll
                for (int dx = 0; dx < 3; dx++) {
                    const uint4* sB4 = (const uint4*)(smB + (dy * 3 + dx) * BTAP);
                    uint4 bh = sB4[(ks * 4 + wid) * 32 + lane];
                    uint4 bl = sB4[(ks * 4 + wid) * 32 + lane + KS * 128];
#pragma unroll
                    for (int mt = 0; mt < 4; mt++) {
                        MMA_BF16(acc[mt][dx][0], ah[mt][0], ah[mt][1], ah[mt][2], ah[mt][3], bh.x, bh.y);
                        MMA_BF16(acc[mt][dx][0], ah[mt][0], ah[mt][1], ah[mt][2], ah[mt][3], bl.x, bl.y);
                        MMA_BF16(acc[mt][dx][0], al[mt][0], al[mt][1], al[mt][2], al[mt][3], bh.x, bh.y);
                        MMA_BF16(acc[mt][dx][1], ah[mt][0], ah[mt][1], ah[mt][2], ah[mt][3], bh.z, bh.w);
                        MMA_BF16(acc[mt][dx][1], ah[mt][0], ah[mt][1], ah[mt][2], ah[mt][3], bl.z, bl.w);
                        MMA_BF16(acc[mt][dx][1], al[mt][0], al[mt][1], al[mt][2], al[mt][3], bh.z, bh.w);
                    }
                }
            }
        }

        // ---- register-only epilogue: out[p] = D0[p-1] + D1[p] + D2[p+1] + bias ----
#pragma unroll
        for (int nb = 0; nb < 2; nb++) {
#pragma unroll
            for (int mt = 0; mt < 4; mt++) {
                float u[4], d[4], cx[4], ex[4];
#pragma unroll
                for (int r = 0; r < 4; r++) {
                    u[r] = __shfl_up_sync(0xffffffffu, acc[mt][0][nb][r], 4);
                    d[r] = __shfl_down_sync(0xffffffffu, acc[mt][2][nb][r], 4);
                }
                float pm2 = (mt > 0) ? acc[(mt > 0 ? mt - 1 : 0)][0][nb][2] : 0.f;
                float pm3 = (mt > 0) ? acc[(mt > 0 ? mt - 1 : 0)][0][nb][3] : 0.f;
                cx[0] = __shfl_sync(0xffffffffu, pm2, 28 + q);
                cx[1] = __shfl_sync(0xffffffffu, pm3, 28 + q);
                cx[2] = __shfl_sync(0xffffffffu, acc[mt][0][nb][0], 28 + q);
                cx[3] = __shfl_sync(0xffffffffu, acc[mt][0][nb][1], 28 + q);
                ex[0] = __shfl_sync(0xffffffffu, acc[mt][2][nb][2], q);
                ex[1] = __shfl_sync(0xffffffffu, acc[mt][2][nb][3], q);
                float nm0 = (mt < 3) ? acc[(mt < 3 ? mt + 1 : 3)][2][nb][0] : 0.f;
                float nm1 = (mt < 3) ? acc[(mt < 3 ? mt + 1 : 3)][2][nb][1] : 0.f;
                ex[2] = __shfl_sync(0xffffffffu, nm0, q);
                ex[3] = __shfl_sync(0xffffffffu, nm1, q);
                int n_e = wid * 16 + nb * 8 + 2 * q;
#pragma unroll
                for (int r = 0; r < 4; r++) {
                    int n = n_e + (r & 1);
                    float prev = g8 ? u[r] : ((mt == 0 && r < 2) ? sL[n] : cx[r]);
                    float nxt  = (g8 < 7) ? d[r] : ((mt == 3 && r >= 2) ? sR[n] : ex[r]);
                    float v = acc[mt][1][nb][r] + prev + nxt + sBias[n];
                    int p = mt * 16 + g8 + ((r >= 2) ? 8 : 0);
                    g_y2[(((size_t)b * COUT + n) * H_IMG + y) * W_IMG + x0 + p] = v;
                    if (r & 1) { rso[nb] += v; rqo[nb] += v * v; }
                    else       { rse[nb] += v; rqe[nb] += v * v; }
                }
            }
        }
    }

    // final stats atomics (amortized over TY rows)
#pragma unroll
    for (int nb = 0; nb < 2; nb++) {
        float se = rse[nb], so = rso[nb], qe = rqe[nb], qo = rqo[nb];
#pragma unroll
        for (int sh = 4; sh <= 16; sh <<= 1) {
            se += __shfl_xor_sync(0xffffffffu, se, sh);
            so += __shfl_xor_sync(0xffffffffu, so, sh);
            qe += __shfl_xor_sync(0xffffffffu, qe, sh);
            qo += __shfl_xor_sync(0xffffffffu, qo, sh);
        }
        if (lane < 4) {
            int ne = wid * 16 + nb * 8 + 2 * lane;
            atomicAdd(&g_s2[ne], se);
            atomicAdd(&g_s2[COUT + ne], qe);
            atomicAdd(&g_s2[ne + 1], so);
            atomicAdd(&g_s2[COUT + ne + 1], qo);
        }
    }
}

// ---------------- conv3: warp-MMA implicit GEMM (unchanged structure) ----------------
template <int CIN, int COUT, bool WRITE>
__global__ __launch_bounds__(128, 3)
void conv_mma_kernel(const float* __restrict__ in_gamma,
                     const float* __restrict__ in_beta,
                     const float* __restrict__ bias)
{
    constexpr int KS    = CIN / 16;
    constexpr int NG    = COUT / 64;
    constexpr int AROW  = CIN * 4 + 16;
    constexpr int ABUF  = 64 * AROW;
    constexpr int BTAP  = 2 * KS * 8 * 32 * 8;
    constexpr int BBUF  = 3 * BTAP;
    constexpr int STAGE = ABUF + BBUF;
    constexpr int HW    = H_IMG * W_IMG;

    const float* yfin = (CIN == 32) ? g_y1 : g_y2;
    const char* ain   = (const char*)((CIN == 32) ? (const void*)g_a1 : (const void*)g_a2);
    const float* ist  = (CIN == 32) ? g_s1 : g_s2;
    float* ost        = (CIN == 32) ? g_s2 : g_s3;
    const float* wt   = (CIN == 32) ? g_w2t : g_w3t;
    const uint2* wb   = (CIN == 32) ? g_wb2 : g_wb3;

    extern __shared__ char sm[];
    float* sScale = (float*)(sm + STAGE);
    float* sShift = sScale + CIN;
    float* sEdge  = sShift + CIN;
    float* sL     = sEdge + 6 * CIN;
    float* sR     = sL + 64;
    float* sBias  = sR + 64;

    const int tid = threadIdx.x, wid = tid >> 5, lane = tid & 31;
    const int g8 = lane >> 2, q = lane & 3;
    const int x0 = blockIdx.x * 64, y = blockIdx.y;
    const int b = blockIdx.z / NG, g = blockIdx.z % NG;

    auto issue_stage = [&](int dy) {
        uint32_t aSm = smem_u32(sm);
        uint32_t bSm = aSm + ABUF;
        for (int t3 = 0; t3 < 3; t3++) {
            const char* gsrc = (const char*)wb + (size_t)((dy * 3 + t3) * NG + g) * BTAP;
            for (int i = tid; i < BTAP / 16; i += 128)
                CP_ASYNC16(bSm + t3 * BTAP + i * 16, gsrc + i * 16);
        }
        int ydy = y + dy - 1;
        if (ydy < 0 || ydy >= H_IMG) {
            for (int i = tid; i < ABUF / 16; i += 128)
                ((uint4*)sm)[i] = make_uint4(0, 0, 0, 0);
        } else {
            const char* src = ain + ((size_t)(b * H_IMG + ydy) * W_IMG + x0) * (size_t)(4 * CIN);
            for (int i = tid; i < 64 * (CIN / 4); i += 128) {
                int p = i / (CIN / 4), j = i % (CIN / 4);
                CP_ASYNC16(aSm + p * AROW + j * 16, src + p * 4 * CIN + j * 16);
            }
        }
        CP_COMMIT();
    };

    issue_stage(0);

    if (tid < CIN) {
        float mean = ist[tid] * (1.f / NPIX);
        float var  = ist[CIN + tid] * (1.f / NPIX) - mean * mean;
        float is_  = rsqrtf(var + BN_EPS);
        float sc   = in_gamma[tid] * is_;
        sScale[tid] = sc; sShift[tid] = in_beta[tid] - mean * sc;
    }
    if (tid < 64) sBias[tid] = bias[g * 64 + tid];
    __syncthreads();

    for (int i = tid; i < 6 * CIN; i += 128) {
        int side = i / (3 * CIN), rem = i % (3 * CIN);
        int dyy = rem / CIN, c = rem % CIN;
        int ydy = y + dyy - 1;
        int xx = side ? x0 + 64 : x0 - 1;
        float v = 0.f;
        if (ydy >= 0 && ydy < H_IMG && xx >= 0 && xx < W_IMG) {
            v = yfin[((size_t)b * CIN + c) * HW + (size_t)ydy * W_IMG + xx];
            v = fmaf(v, sScale[c], sShift[c]);
            v = v > 0.f ? v : 0.01f * v;
        }
        sEdge[i] = v;
    }
    __syncthreads();
    {
        int o = tid & 63, side = tid >> 6;
        float accf = 0.f;
        for (int dyy = 0; dyy < 3; dyy++)
            for (int c = 0; c < CIN; c++)
                accf = fmaf(sEdge[side * 3 * CIN + dyy * CIN + c],
                            wt[(c * 9 + dyy * 3 + (side ? 2 : 0)) * COUT + g * 64 + o], accf);
        (side ? sR : sL)[o] = accf;
    }

    float acc[4][3][2][4];
#pragma unroll
    for (int mt = 0; mt < 4; mt++)
#pragma unroll
        for (int dx = 0; dx < 3; dx++)
#pragma unroll
            for (int nb = 0; nb < 2; nb++)
#pragma unroll
                for (int r = 0; r < 4; r++) acc[mt][dx][nb][r] = 0.f;

    const int lrow = ((lane >> 3) & 1) * 8 + (lane & 7);
    const uint32_t aOff = (uint32_t)lrow * AROW + ((lane >> 4) & 1) * 16;

    for (int dy = 0; dy < 3; dy++) {
        __syncthreads();
        if (dy > 0) issue_stage(dy);
        CP_WAIT0();
        __syncthreads();

        const uint32_t aAddr0 = smem_u32(sm) + aOff;
#pragma unroll
        for (int ks = 0; ks < KS; ks++) {
            uint32_t ah[4][4], al[4][4];
#pragma unroll
            for (int mt = 0; mt < 4; mt++) {
                uint32_t ad = aAddr0 + mt * 16 * AROW + 32 * ks;
                LDSM_X4(ah[mt][0], ah[mt][1], ah[mt][2], ah[mt][3], ad);
                LDSM_X4(al[mt][0], al[mt][1], al[mt][2], al[mt][3], ad + 2 * CIN);
            }
#pragma unroll
            for (int dx = 0; dx < 3; dx++) {
                const uint4* sB4 = (const uint4*)(sm + ABUF + dx * BTAP);
                uint4 bh = sB4[(ks * 4 + wid) * 32 + lane];
                uint4 bl = sB4[(ks * 4 + wid) * 32 + lane + KS * 128];
#pragma unroll
                for (int mt = 0; mt < 4; mt++) {
                    MMA_BF16(acc[mt][dx][0], ah[mt][0], ah[mt][1], ah[mt][2], ah[mt][3], bh.x, bh.y);
                    MMA_BF16(acc[mt][dx][0], ah[mt][0], ah[mt][1], ah[mt][2], ah[mt][3], bl.x, bl.y);
                    MMA_BF16(acc[mt][dx][0], al[mt][0], al[mt][1], al[mt][2], al[mt][3], bh.x, bh.y);
                    MMA_BF16(acc[mt][dx][1], ah[mt][0], ah[mt][1], ah[mt][2], ah[mt][3], bh.z, bh.w);
                    MMA_BF16(acc[mt][dx][1], ah[mt][0], ah[mt][1], ah[mt][2], ah[mt][3], bl.z, bl.w);
                    MMA_BF16(acc[mt][dx][1], al[mt][0], al[mt][1], al[mt][2], al[mt][3], bh.z, bh.w);
                }
            }
        }
    }
    __syncthreads();

    float* S0 = (float*)sm;
    float* S2 = S0 + 64 * 65;
#pragma unroll
    for (int mt = 0; mt < 4; mt++)
#pragma unroll
        for (int nb = 0; nb < 2; nb++)
#pragma unroll
            for (int r = 0; r < 4; r++) {
                int p = mt * 16 + g8 + ((r >= 2) ? 8 : 0);
                int n = wid * 16 + nb * 8 + 2 * q + (r & 1);
                S0[p * 65 + n] = acc[mt][0][nb][r];
                S2[p * 65 + n] = acc[mt][2][nb][r];
            }
    __syncthreads();

#pragma unroll
    for (int nb = 0; nb < 2; nb++) {
        float se = 0.f, so = 0.f, qe = 0.f, qo = 0.f;
#pragma unroll
        for (int mt = 0; mt < 4; mt++) {
            float v[4];
#pragma unroll
            for (int r = 0; r < 4; r++) {
                int p = mt * 16 + g8 + ((r >= 2) ? 8 : 0);
                int n = wid * 16 + nb * 8 + 2 * q + (r & 1);
                float t = acc[mt][1][nb][r];
                t += (p > 0)  ? S0[(p - 1) * 65 + n] : sL[n];
                t += (p < 63) ? S2[(p + 1) * 65 + n] : sR[n];
                t += sBias[n];
                v[r] = t;
                if (WRITE)
                    g_y2[(((size_t)b * COUT + g * 64 + n) * H_IMG + y) * W_IMG + x0 + p] = t;
            }
            se += v[0] + v[2]; so += v[1] + v[3];
            qe += v[0]*v[0] + v[2]*v[2]; qo += v[1]*v[1] + v[3]*v[3];
        }
#pragma unroll
        for (int sh = 4; sh <= 16; sh <<= 1) {
            se += __shfl_xor_sync(0xffffffffu, se, sh);
            so += __shfl_xor_sync(0xffffffffu, so, sh);
            qe += __shfl_xor_sync(0xffffffffu, qe, sh);
            qo += __shfl_xor_sync(0xffffffffu, qo, sh);
        }
        if (lane < 4) {
            int ne = wid * 16 + nb * 8 + 2 * lane;
            atomicAdd(&ost[g * 64 + ne], se);
            atomicAdd(&ost[COUT + g * 64 + ne], qe);
            atomicAdd(&ost[g * 64 + ne + 1], so);
            atomicAdd(&ost[COUT + g * 64 + ne + 1], qo);
        }
    }
}

// ---------------- patch gather + encode ----------------
__global__ void patch_kernel(const float* __restrict__ image,
                             const int* __restrict__ a_xy, const int* __restrict__ p_xy,
                             const int* __restrict__ n_xy, float* __restrict__ out)
{
    int idx = blockIdx.x * blockDim.x + threadIdx.x;
    if (idx >= 3528) return;
    int which = idx / 1176;
    int r  = idx % 1176;
    int b  = r / 147, r2 = r % 147;
    int c  = r2 / 49, p = r2 % 49;
    int dy = p / 7, dx = p % 7;
    const int* xy = (which == 0) ? a_xy : (which == 1 ? p_xy : n_xy);
    int row = xy[b * 64 + 62], col = xy[b * 64 + 63];
    out[idx] = image[((b * 3 + c) * H_IMG + (row - 3 + dy)) * W_IMG + (col - 3 + dx)];
}

__global__ void encode_kernel(const int* __restrict__ n_xy,
                              const float* __restrict__ bn2_g, const float* __restrict__ bn2_b,
                              const float* __restrict__ conv3_b,
                              const float* __restrict__ bn3_g, const float* __restrict__ bn3_b,
                              float* __restrict__ out)
{
    int b = blockIdx.x, o = threadIdx.x;
    __shared__ float s_z2[576];
    int row = n_xy[b * 64 + 62], col = n_xy[b * 64 + 63];
    for (int i = threadIdx.x; i < 576; i += 128) {
        int c = i / 9, p = i % 9;
        int ky = p / 3 - 1, kx = p % 3 - 1;
        float mean = g_s2[c] * (1.f / NPIX);
        float var  = g_s2[64 + c] * (1.f / NPIX) - mean * mean;
        float is   = rsqrtf(var + BN_EPS);
        float sc   = bn2_g[c] * is;
        float sh   = bn2_b[c] - mean * sc;
        float v = g_y2[((b * 64 + c) * H_IMG + row + ky) * W_IMG + col + kx];
        v = v * sc + sh;
        v = v > 0.f ? v : 0.01f * v;
        s_z2[i] = v;
    }
    __syncthreads();
    float acc = conv3_b[o];
    for (int i = 0; i < 576; i++) acc = fmaf(s_z2[i], g_w3t[i * 128 + o], acc);
    float mean = g_s3[o] * (1.f / NPIX);
    float var  = g_s3[128 + o] * (1.f / NPIX) - mean * mean;
    float is   = rsqrtf(var + BN_EPS);
    float v = (acc - mean) * is * bn3_g[o] + bn3_b[o];
    v = v > 0.f ? v : 0.01f * v;
    out[3528 + b * 128 + o] = v;
}

extern "C" void kernel_launch(void* const* d_in, const int* in_sizes, int n_in,
                              void* d_out, int out_size) {
    const float* image = (const float*)d_in[0];
    const int*   a_xy  = (const int*)d_in[1];
    const int*   p_xy  = (const int*)d_in[2];
    const int*   n_xy  = (const int*)d_in[3];
    const float* w1  = (const float*)d_in[4];
    const float* b1  = (const float*)d_in[5];
    const float* g1  = (const float*)d_in[6];
    const float* be1 = (const float*)d_in[7];
    const float* w2  = (const float*)d_in[8];
    const float* b2  = (const float*)d_in[9];
    const float* g2  = (const float*)d_in[10];
    const float* be2 = (const float*)d_in[11];
    const float* w3  = (const float*)d_in[12];
    const float* b3  = (const float*)d_in[13];
    const float* g3  = (const float*)d_in[14];
    const float* be3 = (const float*)d_in[15];
    float* out = (float*)d_out;

    const int SM2P = 73728 + 4 * 9216 + 1024;                       // 111,616
    const int SM3  = (64*(64*4+16) + 3*(2*4*2048)) + (8*64+192)*4;  // 69,376
    cudaFuncSetAttribute(conv2_persist_kernel,
                         cudaFuncAttributeMaxDynamicSharedMemorySize, SM2P);
    cudaFuncSetAttribute(conv_mma_kernel<64, 128, false>,
                         cudaFuncAttributeMaxDynamicSharedMemorySize, SM3);
    cudaFuncSetAttribute(prepass_kernel<32>,
                         cudaFuncAttributeMaxDynamicSharedMemorySize, 32 * 257 * 4);
    cudaFuncSetAttribute(prepass_kernel<64>,
                         cudaFuncAttributeMaxDynamicSharedMemorySize, 64 * 257 * 4);

    // conv kernels at ncu-capture slots 3 and 5.
    prep_all_kernel<<<546, 256>>>(w1, w2, w3);                                           // 0
    conv1_kernel<<<dim3(16, 4, 8), 256>>>(image, b1);                                    // 1
    prepass_kernel<32><<<2048, 256, 32 * 257 * 4>>>(g1, be1);                            // 2
    conv2_persist_kernel<<<dim3(4, 32, 8), 128, SM2P>>>(g1, be1, b2);                    // 3
    prepass_kernel<64><<<2048, 256, 64 * 257 * 4>>>(g2, be2);                            // 4
    conv_mma_kernel<64, 128, false><<<dim3(4, 256, 16), 128, SM3>>>(g2, be2, b3);        // 5
    patch_kernel<<<14, 256>>>(image, a_xy, p_xy, n_xy, out);                             // 6
    encode_kernel<<<8, 128>>>(n_xy, g2, be2, b3, g3, be3, out);                          // 7
}

// round 16
// speedup vs baseline: 2.7043x; 1.0649x over previous
#include <cuda_runtime.h>
#include <cuda_bf16.h>
#include <cstdint>

#define H_IMG 256
#define W_IMG 256
#define B_SZ 8
#define NPIX (B_SZ * H_IMG * W_IMG)
#define BN_EPS 1e-5f

// -------- scratch (allocation-free) --------
__device__ float g_y1[B_SZ * 32 * H_IMG * W_IMG];
__device__ float g_y2[B_SZ * 64 * H_IMG * W_IMG];
__device__ __nv_bfloat16 g_a1[(size_t)B_SZ * H_IMG * W_IMG * 64];    // [b][y][x][hi32|lo32]
__device__ __nv_bfloat16 g_a2[(size_t)B_SZ * H_IMG * W_IMG * 128];   // [b][y][x][hi64|lo64]
__device__ float g_w1t[3 * 9 * 32];
__device__ float g_w2t[32 * 9 * 64];
__device__ float g_w3t[64 * 9 * 128];
__device__ uint2 g_wb2[9 * 1 * 2 * 2 * 8 * 32];
__device__ uint2 g_wb3[9 * 2 * 2 * 4 * 8 * 32];
__device__ float g_fix2[(size_t)B_SZ * H_IMG * 18 * 64];    // [b*y][col*3+dyy][o]
__device__ float g_fix3[(size_t)B_SZ * H_IMG * 18 * 128];
__device__ float g_s1[2 * 32];
__device__ float g_s2[2 * 64];
__device__ float g_s3[2 * 128];

#define MMA_BF16(d, A0, A1, A2, A3, B0, B1) \
    asm volatile( \
        "mma.sync.aligned.m16n8k16.row.col.f32.bf16.bf16.f32 " \
        "{%0,%1,%2,%3}, {%4,%5,%6,%7}, {%8,%9}, {%0,%1,%2,%3};" \
        : "+f"(d[0]), "+f"(d[1]), "+f"(d[2]), "+f"(d[3]) \
        : "r"(A0), "r"(A1), "r"(A2), "r"(A3), "r"(B0), "r"(B1))

#define LDSM_X4(r0, r1, r2, r3, addr) \
    asm volatile("ldmatrix.sync.aligned.m8n8.x4.shared.b16 {%0,%1,%2,%3}, [%4];" \
        : "=r"(r0), "=r"(r1), "=r"(r2), "=r"(r3) : "r"(addr))

__device__ __forceinline__ uint32_t smem_u32(const void* p) {
    uint32_t a;
    asm("{ .reg .u64 t; cvta.to.shared.u64 t, %1; cvt.u32.u64 %0, t; }" : "=r"(a) : "l"(p));
    return a;
}
#define CP_ASYNC16(smaddr, gptr) \
    asm volatile("cp.async.cg.shared.global [%0], [%1], 16;" :: "r"(smaddr), "l"(gptr))
#define CP_COMMIT()  asm volatile("cp.async.commit_group;" ::: "memory")
#define CP_WAIT0()   asm volatile("cp.async.wait_group 0;" ::: "memory")
#define CP_WAIT1()   asm volatile("cp.async.wait_group 1;" ::: "memory")

// ---------------- fused prep ----------------
template <int CIN, int COUT>
__device__ __forceinline__ void prep_wb_one(const float* __restrict__ w, int idx) {
    constexpr int KS = CIN / 16, NG = COUT / 64;
    uint2* wb = (CIN == 32) ? g_wb2 : g_wb3;
    int lane = idx & 31;
    int t = idx >> 5;
    int nb = t & 7; t >>= 3;
    int ks = t % KS; t /= KS;
    int part = t & 1; t >>= 1;
    int g = t % NG; int tap = t / NG;
    int o = g * 64 + nb * 8 + (lane >> 2);
    int k0 = ks * 16 + 2 * (lane & 3);
    auto enc = [&](int k) -> uint32_t {
        float x = w[(o * CIN + k) * 9 + tap];
        __nv_bfloat16 h = __float2bfloat16(x);
        __nv_bfloat16 v = h;
        if (part) v = __float2bfloat16(x - __bfloat162float(h));
        return (uint32_t)*reinterpret_cast<unsigned short*>(&v);
    };
    uint2 val;
    val.x = enc(k0) | (enc(k0 + 1) << 16);
    val.y = enc(k0 + 8) | (enc(k0 + 9) << 16);
    size_t BI = (size_t)((tap * NG + g) * 2 + part);
    wb[BI * (KS * 256) + (size_t)((ks * 4 + (nb >> 1)) * 32 + lane) * 2 + (nb & 1)] = val;
}

template <int CIN, int COUT>
__device__ __forceinline__ void transpose_one(const float* __restrict__ w, float* wt, int idx) {
    int o = idx % COUT;
    int r = idx / COUT;
    int ci = r / 9, t = r % 9;
    wt[idx] = w[(o * CIN + ci) * 9 + t];
}

__global__ void prep_all_kernel(const float* __restrict__ w1,
                                const float* __restrict__ w2,
                                const float* __restrict__ w3) {
    int idx = blockIdx.x * 256 + threadIdx.x;
    if (idx < 448) {
        if (idx < 64) g_s1[idx] = 0.f;
        else if (idx < 192) g_s2[idx - 64] = 0.f;
        else g_s3[idx - 192] = 0.f;
        return;
    }
    idx -= 448;
    if (idx < 864)  { transpose_one<3, 32>(w1, g_w1t, idx); return; }
    idx -= 864;
    if (idx < 18432) { transpose_one<32, 64>(w2, g_w2t, idx); return; }
    idx -= 18432;
    if (idx < 73728) { transpose_one<64, 128>(w3, g_w3t, idx); return; }
    idx -= 73728;
    if (idx < 9216)  { prep_wb_one<32, 64>(w2, idx); return; }
    idx -= 9216;
    if (idx < 36864) { prep_wb_one<64, 128>(w3, idx); return; }
}

// ---------------- BN+lrelu+bf16-split pre-pass + edge-fixup partials ----------------
template <int CIN>
__global__ void prepass_kernel(const float* __restrict__ gamma,
                               const float* __restrict__ beta) {
    constexpr int FCOUT = (CIN == 32) ? 64 : 128;
    const float* yin = (CIN == 32) ? g_y1 : g_y2;
    const float* st  = (CIN == 32) ? g_s1 : g_s2;
    __nv_bfloat16* aout = (CIN == 32) ? g_a1 : g_a2;
    const float* wtf = (CIN == 32) ? g_w2t : g_w3t;
    float* fx = (CIN == 32) ? g_fix2 : g_fix3;
    extern __shared__ float tile[];   // [CIN][257]
    __shared__ float sc[CIN], sh[CIN];
    int row = blockIdx.x;             // b*256 + y
    int tid = threadIdx.x;
    if (tid < CIN) {
        float mean = st[tid] * (1.f / NPIX);
        float var  = st[CIN + tid] * (1.f / NPIX) - mean * mean;
        float is_  = rsqrtf(var + BN_EPS);
        float s    = gamma[tid] * is_;
        sc[tid] = s; sh[tid] = beta[tid] - mean * s;
    }
    __syncthreads();
    for (int i = tid; i < CIN * 256; i += 256) {
        int c = i >> 8, x = i & 255;
        float v = yin[(size_t)(row >> 8) * CIN * 65536 + (size_t)c * 65536
                      + ((row & 255) << 8) + x];
        v = fmaf(v, sc[c], sh[c]);
        v = v > 0.f ? v : 0.01f * v;
        tile[c * 257 + x] = v;
    }
    __syncthreads();
    uint32_t* ao = (uint32_t*)aout + (size_t)row * 256 * CIN;
    for (int i = tid; i < 256 * (CIN / 2); i += 256) {
        int px = i / (CIN / 2), c2 = i % (CIN / 2);
        float v0 = tile[(2 * c2) * 257 + px];
        float v1 = tile[(2 * c2 + 1) * 257 + px];
        __nv_bfloat16 h0 = __float2bfloat16(v0), h1 = __float2bfloat16(v1);
        __nv_bfloat16 l0 = __float2bfloat16(v0 - __bfloat162float(h0));
        __nv_bfloat16 l1 = __float2bfloat16(v1 - __bfloat162float(h1));
        uint32_t hw = (uint32_t)*(unsigned short*)&h0 | ((uint32_t)*(unsigned short*)&h1 << 16);
        uint32_t lw = (uint32_t)*(unsigned short*)&l0 | ((uint32_t)*(unsigned short*)&l1 << 16);
        ao[(size_t)px * CIN + c2] = hw;
        ao[(size_t)px * CIN + CIN / 2 + c2] = lw;
    }
    // edge-fixup partials: fx[row][j*3+dyy][o] = sum_c act[c][ecx[j]] * w[c][dyy][kx(j)]
    const int ecx[6] = {63, 64, 127, 128, 191, 192};
    for (int t2 = tid; t2 < 6 * 3 * FCOUT; t2 += 256) {
        int o = t2 % FCOUT;
        int rr = t2 / FCOUT;
        int dyy = rr % 3, j = rr / 3;
        int x = ecx[j];
        int kx = (j & 1) ? 2 : 0;
        float s = 0.f;
        for (int c = 0; c < CIN; c++)
            s = fmaf(tile[c * 257 + x], wtf[(c * 9 + dyy * 3 + kx) * FCOUT + o], s);
        fx[((size_t)row * 18 + j * 3 + dyy) * FCOUT + o] = s;
    }
}

// ---------------- conv1: scalar (cin=3, tiny) ----------------
__global__ __launch_bounds__(256, 1) void conv1_kernel(const float* __restrict__ image,
                                                       const float* __restrict__ bias) {
    const int tx = threadIdx.x & 15, ty = threadIdx.x >> 4;
    const int tile_x = blockIdx.x * 16, tile_y = blockIdx.y * 64;
    const int b = blockIdx.z;
    __shared__ float s_in[3][66][18];
    __shared__ float s_w[3 * 9 * 32];
    float a0[32], a1[32], a2[32], a3[32];
#pragma unroll
    for (int o = 0; o < 32; o++) { a0[o] = a1[o] = a2[o] = a3[o] = 0.f; }
    for (int i = threadIdx.x; i < 3 * 66 * 18; i += 256) {
        int c = i / (66 * 18), r = i - c * (66 * 18);
        int yy = r / 18, xx = r - yy * 18;
        int gy = tile_y + yy - 1, gx = tile_x + xx - 1;
        float v = 0.f;
        if (gy >= 0 && gy < H_IMG && gx >= 0 && gx < W_IMG)
            v = image[((b * 3 + c) * H_IMG + gy) * W_IMG + gx];
        s_in[c][yy][xx] = v;
    }
    for (int i = threadIdx.x; i < 3 * 9 * 32; i += 256) s_w[i] = g_w1t[i];
    __syncthreads();
#pragma unroll 1
    for (int c = 0; c < 3; c++) {
#pragma unroll
        for (int t = 0; t < 9; t++) {
            float x0 = s_in[c][ty      + t / 3][tx + t % 3];
            float x1 = s_in[c][ty + 16 + t / 3][tx + t % 3];
            float x2 = s_in[c][ty + 32 + t / 3][tx + t % 3];
            float x3 = s_in[c][ty + 48 + t / 3][tx + t % 3];
            const float4* wv = (const float4*)&s_w[(c * 9 + t) * 32];
#pragma unroll
            for (int qq = 0; qq < 8; qq++) {
                float4 w4 = wv[qq];
                a0[qq*4+0]=fmaf(x0,w4.x,a0[qq*4+0]); a0[qq*4+1]=fmaf(x0,w4.y,a0[qq*4+1]);
                a0[qq*4+2]=fmaf(x0,w4.z,a0[qq*4+2]); a0[qq*4+3]=fmaf(x0,w4.w,a0[qq*4+3]);
                a1[qq*4+0]=fmaf(x1,w4.x,a1[qq*4+0]); a1[qq*4+1]=fmaf(x1,w4.y,a1[qq*4+1]);
                a1[qq*4+2]=fmaf(x1,w4.z,a1[qq*4+2]); a1[qq*4+3]=fmaf(x1,w4.w,a1[qq*4+3]);
                a2[qq*4+0]=fmaf(x2,w4.x,a2[qq*4+0]); a2[qq*4+1]=fmaf(x2,w4.y,a2[qq*4+1]);
                a2[qq*4+2]=fmaf(x2,w4.z,a2[qq*4+2]); a2[qq*4+3]=fmaf(x2,w4.w,a2[qq*4+3]);
                a3[qq*4+0]=fmaf(x3,w4.x,a3[qq*4+0]); a3[qq*4+1]=fmaf(x3,w4.y,a3[qq*4+1]);
                a3[qq*4+2]=fmaf(x3,w4.z,a3[qq*4+2]); a3[qq*4+3]=fmaf(x3,w4.w,a3[qq*4+3]);
            }
        }
    }
    int lane = threadIdx.x & 31;
#pragma unroll
    for (int o = 0; o < 32; o++) {
        float bv = bias[o];
        a0[o] += bv; a1[o] += bv; a2[o] += bv; a3[o] += bv;
        int p = ((b * 32 + o) * H_IMG + tile_y + ty) * W_IMG + tile_x + tx;
        g_y1[p] = a0[o]; g_y1[p + 16*W_IMG] = a1[o];
        g_y1[p + 32*W_IMG] = a2[o]; g_y1[p + 48*W_IMG] = a3[o];
        float v = a0[o]+a1[o]+a2[o]+a3[o];
        float v2 = a0[o]*a0[o]+a1[o]*a1[o]+a2[o]*a2[o]+a3[o]*a3[o];
#pragma unroll
        for (int s = 16; s > 0; s >>= 1) {
            v  += __shfl_down_sync(0xffffffffu, v, s);
            v2 += __shfl_down_sync(0xffffffffu, v2, s);
        }
        if (lane == 0) { atomicAdd(&g_s1[o], v); atomicAdd(&g_s1[32 + o], v2); }
    }
}

// ---------------- conv2: persistent-B, rolling-A, TY=8 rows, fix preloaded ----------------
__global__ __launch_bounds__(128, 2)
void conv2_persist_kernel(const float* __restrict__ bias)
{
    constexpr int CIN = 32, COUT = 64, KS = 2, TY = 8;
    constexpr int AROW = 144, ABUF = 64 * AROW;
    constexpr int BTAP = 8192, BALL = 9 * BTAP;

    extern __shared__ char sm[];
    char* smB  = sm;
    char* ring = sm + BALL;
    float* sL    = (float*)(sm + BALL + 4 * ABUF);
    float* sR    = sL + 64;
    float* sBias = sR + 64;

    const int tid = threadIdx.x, wid = tid >> 5, lane = tid & 31;
    const int g8 = lane >> 2, q = lane & 3;
    const int strip = blockIdx.x;
    const int x0 = strip * 64, y0 = blockIdx.y * TY;
    const int b = blockIdx.z;
    const char* ain = (const char*)g_a1;

    auto issue_A = [&](int row, int slot) {
        char* base = ring + slot * ABUF;
        if (row < 0 || row >= H_IMG) {
            for (int i = tid; i < ABUF / 16; i += 128)
                ((uint4*)base)[i] = make_uint4(0, 0, 0, 0);
        } else {
            uint32_t aSm = smem_u32(base);
            const char* src = ain + ((size_t)(b * H_IMG + row) * W_IMG + x0) * 128;
            for (int i = tid; i < 64 * 8; i += 128) {
                int p = i >> 3, j = i & 7;
                CP_ASYNC16(aSm + p * AROW + j * 16, src + p * 128 + j * 16);
            }
        }
        CP_COMMIT();
    };

    {
        const char* gB = (const char*)g_wb2;
        uint32_t dst = smem_u32(smB);
        for (int i = tid; i < BALL / 16; i += 128) CP_ASYNC16(dst + i * 16, gB + i * 16);
        CP_COMMIT();
    }
    issue_A(y0 - 1, 0);
    issue_A(y0,     1);
    issue_A(y0 + 1, 2);
    if (tid < 64) sBias[tid] = bias[tid];

    const int lrow = ((lane >> 3) & 1) * 8 + (lane & 7);
    const uint32_t aOff = (uint32_t)lrow * AROW + ((lane >> 4) & 1) * 16;

    float rse[2] = {0.f, 0.f}, rso[2] = {0.f, 0.f};
    float rqe[2] = {0.f, 0.f}, rqo[2] = {0.f, 0.f};

    for (int t = 0; t < TY; t++) {
        int y = y0 + t;
        __syncthreads();
        issue_A(y + 2, (t + 3) & 3);
        // preloaded edge fixups
        {
            int o = tid & 63, side = tid >> 6;
            int colv = side ? (strip < 3 ? 2 * strip + 1 : -1)
                            : (strip > 0 ? 2 * (strip - 1) : -1);
            float s = 0.f;
            if (colv >= 0) {
#pragma unroll
                for (int dyy = 0; dyy < 3; dyy++) {
                    int r = y + dyy - 1;
                    if (r >= 0 && r < H_IMG)
                        s += g_fix2[((size_t)(b * H_IMG + r) * 18 + colv * 3 + dyy) * 64 + o];
                }
            }
            (side ? sR : sL)[o] = s;
        }
        CP_WAIT1();
        __syncthreads();

        float acc[4][3][2][4];
#pragma unroll
        for (int mt = 0; mt < 4; mt++)
#pragma unroll
            for (int dx = 0; dx < 3; dx++)
#pragma unroll
                for (int nb = 0; nb < 2; nb++)
#pragma unroll
                    for (int r = 0; r < 4; r++) acc[mt][dx][nb][r] = 0.f;

#pragma unroll
        for (int dy = 0; dy < 3; dy++) {
            const uint32_t aAddr0 = smem_u32(ring + ((t + dy) & 3) * ABUF) + aOff;
#pragma unroll
            for (int ks = 0; ks < KS; ks++) {
                uint32_t ah[4][4], al[4][4];
#pragma unroll
                for (int mt = 0; mt < 4; mt++) {
                    uint32_t ad = aAddr0 + mt * 16 * AROW + 32 * ks;
                    LDSM_X4(ah[mt][0], ah[mt][1], ah[mt][2], ah[mt][3], ad);
                    LDSM_X4(al[mt][0], al[mt][1], al[mt][2], al[mt][3], ad + 2 * CIN);
                }
#pragma unroll
                for (int dx = 0; dx < 3; dx++) {
                    const uint4* sB4 = (const uint4*)(smB + (dy * 3 + dx) * BTAP);
                    uint4 bh = sB4[(ks * 4 + wid) * 32 + lane];
                    uint4 bl = sB4[(ks * 4 + wid) * 32 + lane + KS * 128];
#pragma unroll
                    for (int mt = 0; mt < 4; mt++) {
                        MMA_BF16(acc[mt][dx][0], ah[mt][0], ah[mt][1], ah[mt][2], ah[mt][3], bh.x, bh.y);
                        MMA_BF16(acc[mt][dx][0], ah[mt][0], ah[mt][1], ah[mt][2], ah[mt][3], bl.x, bl.y);
                        MMA_BF16(acc[mt][dx][0], al[mt][0], al[mt][1], al[mt][2], al[mt][3], bh.x, bh.y);
                        MMA_BF16(acc[mt][dx][1], ah[mt][0], ah[mt][1], ah[mt][2], ah[mt][3], bh.z, bh.w);
                        MMA_BF16(acc[mt][dx][1], ah[mt][0], ah[mt][1], ah[mt][2], ah[mt][3], bl.z, bl.w);
                        MMA_BF16(acc[mt][dx][1], al[mt][0], al[mt][1], al[mt][2], al[mt][3], bh.z, bh.w);
                    }
                }
            }
        }

#pragma unroll
        for (int nb = 0; nb < 2; nb++) {
#pragma unroll
            for (int mt = 0; mt < 4; mt++) {
                float u[4], d[4], cx[4], ex[4];
#pragma unroll
                for (int r = 0; r < 4; r++) {
                    u[r] = __shfl_up_sync(0xffffffffu, acc[mt][0][nb][r], 4);
                    d[r] = __shfl_down_sync(0xffffffffu, acc[mt][2][nb][r], 4);
                }
                float pm2 = (mt > 0) ? acc[(mt > 0 ? mt - 1 : 0)][0][nb][2] : 0.f;
                float pm3 = (mt > 0) ? acc[(mt > 0 ? mt - 1 : 0)][0][nb][3] : 0.f;
                cx[0] = __shfl_sync(0xffffffffu, pm2, 28 + q);
                cx[1] = __shfl_sync(0xffffffffu, pm3, 28 + q);
                cx[2] = __shfl_sync(0xffffffffu, acc[mt][0][nb][0], 28 + q);
                cx[3] = __shfl_sync(0xffffffffu, acc[mt][0][nb][1], 28 + q);
                ex[0] = __shfl_sync(0xffffffffu, acc[mt][2][nb][2], q);
                ex[1] = __shfl_sync(0xffffffffu, acc[mt][2][nb][3], q);
                float nm0 = (mt < 3) ? acc[(mt < 3 ? mt + 1 : 3)][2][nb][0] : 0.f;
                float nm1 = (mt < 3) ? acc[(mt < 3 ? mt + 1 : 3)][2][nb][1] : 0.f;
                ex[2] = __shfl_sync(0xffffffffu, nm0, q);
                ex[3] = __shfl_sync(0xffffffffu, nm1, q);
                int n_e = wid * 16 + nb * 8 + 2 * q;
#pragma unroll
                for (int r = 0; r < 4; r++) {
                    int n = n_e + (r & 1);
                    float prev = g8 ? u[r] : ((mt == 0 && r < 2) ? sL[n] : cx[r]);
                    float nxt  = (g8 < 7) ? d[r] : ((mt == 3 && r >= 2) ? sR[n] : ex[r]);
                    float v = acc[mt][1][nb][r] + prev + nxt + sBias[n];
                    int p = mt * 16 + g8 + ((r >= 2) ? 8 : 0);
                    g_y2[(((size_t)b * COUT + n) * H_IMG + y) * W_IMG + x0 + p] = v;
                    if (r & 1) { rso[nb] += v; rqo[nb] += v * v; }
                    else       { rse[nb] += v; rqe[nb] += v * v; }
                }
            }
        }
    }

#pragma unroll
    for (int nb = 0; nb < 2; nb++) {
        float se = rse[nb], so = rso[nb], qe = rqe[nb], qo = rqo[nb];
#pragma unroll
        for (int sh = 4; sh <= 16; sh <<= 1) {
            se += __shfl_xor_sync(0xffffffffu, se, sh);
            so += __shfl_xor_sync(0xffffffffu, so, sh);
            qe += __shfl_xor_sync(0xffffffffu, qe, sh);
            qo += __shfl_xor_sync(0xffffffffu, qo, sh);
        }
        if (lane < 4) {
            int ne = wid * 16 + nb * 8 + 2 * lane;
            atomicAdd(&g_s2[ne], se);
            atomicAdd(&g_s2[COUT + ne], qe);
            atomicAdd(&g_s2[ne + 1], so);
            atomicAdd(&g_s2[COUT + ne + 1], qo);
        }
    }
}

// ---------------- conv3: persistent-B (all 9 taps, 147KB), rolling-A, TY=16 ----------------
// 256 threads, warp = 64M x 8N; stats only (no output write).
__global__ __launch_bounds__(256, 1)
void conv3_persist_kernel(const float* __restrict__ bias)
{
    constexpr int CIN = 64, COUT = 128, KS = 4, TY = 16;
    constexpr int AROW = 272, ABUF = 64 * AROW;      // 17408
    constexpr int BTAP = 16384, BALL = 9 * BTAP;     // 147456

    extern __shared__ char sm[];
    char* smB  = sm;
    char* ring = sm + BALL;
    float* sL    = (float*)(sm + BALL + 4 * ABUF);
    float* sR    = sL + 64;
    float* sBias = sR + 64;

    const int tid = threadIdx.x, wid = tid >> 5, lane = tid & 31;
    const int g8 = lane >> 2, q = lane & 3;
    const int strip = blockIdx.x;
    const int x0 = strip * 64, y0 = blockIdx.y * TY;
    const int b = blockIdx.z >> 1, g = blockIdx.z & 1;
    const char* ain = (const char*)g_a2;

    auto issue_A = [&](int row, int slot) {
        char* base = ring + slot * ABUF;
        if (row < 0 || row >= H_IMG) {
            for (int i = tid; i < ABUF / 16; i += 256)
                ((uint4*)base)[i] = make_uint4(0, 0, 0, 0);
        } else {
            uint32_t aSm = smem_u32(base);
            const char* src = ain + ((size_t)(b * H_IMG + row) * W_IMG + x0) * 256;
            for (int i = tid; i < 64 * 16; i += 256) {
                int p = i >> 4, j = i & 15;
                CP_ASYNC16(aSm + p * AROW + j * 16, src + p * 256 + j * 16);
            }
        }
        CP_COMMIT();
    };

    {   // B: 9 taps for this g
        uint32_t dst = smem_u32(smB);
        for (int i = tid; i < BALL / 16; i += 256) {
            int tap = i / (BTAP / 16), j = i % (BTAP / 16);
            const char* src = (const char*)g_wb3 + (size_t)(tap * 2 + g) * BTAP + j * 16;
            CP_ASYNC16(dst + tap * BTAP + j * 16, src);
        }
        CP_COMMIT();
    }
    issue_A(y0 - 1, 0);
    issue_A(y0,     1);
    issue_A(y0 + 1, 2);
    if (tid < 64) sBias[tid] = bias[g * 64 + tid];

    const int lrow = ((lane >> 3) & 1) * 8 + (lane & 7);
    const uint32_t aOff = (uint32_t)lrow * AROW + ((lane >> 4) & 1) * 16;

    float rse = 0.f, rso = 0.f, rqe = 0.f, rqo = 0.f;

    for (int t = 0; t < TY; t++) {
        int y = y0 + t;
        __syncthreads();
        issue_A(y + 2, (t + 3) & 3);
        if (tid < 128) {
            int o = tid & 63, side = tid >> 6;
            int colv = side ? (strip < 3 ? 2 * strip + 1 : -1)
                            : (strip > 0 ? 2 * (strip - 1) : -1);
            float s = 0.f;
            if (colv >= 0) {
#pragma unroll
                for (int dyy = 0; dyy < 3; dyy++) {
                    int r = y + dyy - 1;
                    if (r >= 0 && r < H_IMG)
                        s += g_fix3[((size_t)(b * H_IMG + r) * 18 + colv * 3 + dyy) * 128
                                    + g * 64 + o];
                }
            }
            (side ? sR : sL)[o] = s;
        }
        CP_WAIT1();
        __syncthreads();

        float acc[4][3][4];
#pragma unroll
        for (int mt = 0; mt < 4; mt++)
#pragma unroll
            for (int dx = 0; dx < 3; dx++)
#pragma unroll
                for (int r = 0; r < 4; r++) acc[mt][dx][r] = 0.f;

#pragma unroll
        for (int dy = 0; dy < 3; dy++) {
            const uint32_t aAddr0 = smem_u32(ring + ((t + dy) & 3) * ABUF) + aOff;
#pragma unroll
            for (int ks = 0; ks < KS; ks++) {
                uint32_t ah[4][4], al[4][4];
#pragma unroll
                for (int mt = 0; mt < 4; mt++) {
                    uint32_t ad = aAddr0 + mt * 16 * AROW + 32 * ks;
                    LDSM_X4(ah[mt][0], ah[mt][1], ah[mt][2], ah[mt][3], ad);
                    LDSM_X4(al[mt][0], al[mt][1], al[mt][2], al[mt][3], ad + 2 * CIN);
                }
#pragma unroll
                for (int dx = 0; dx < 3; dx++) {
                    const uint2* sB2 = (const uint2*)(smB + (dy * 3 + dx) * BTAP);
                    int bi = ((ks * 4 + (wid >> 1)) * 32 + lane) * 2 + (wid & 1);
                    uint2 bh = sB2[bi];
                    uint2 bl = sB2[bi + KS * 256];
#pragma unroll
                    for (int mt = 0; mt < 4; mt++) {
                        MMA_BF16(acc[mt][dx], ah[mt][0], ah[mt][1], ah[mt][2], ah[mt][3], bh.x, bh.y);
                        MMA_BF16(acc[mt][dx], ah[mt][0], ah[mt][1], ah[mt][2], ah[mt][3], bl.x, bl.y);
                        MMA_BF16(acc[mt][dx], al[mt][0], al[mt][1], al[mt][2], al[mt][3], bh.x, bh.y);
                    }
                }
            }
        }

        // register-only epilogue (stats only)
#pragma unroll
        for (int mt = 0; mt < 4; mt++) {
            float u[4], d[4], cx[4], ex[4];
#pragma unroll
            for (int r = 0; r < 4; r++) {
                u[r] = __shfl_up_sync(0xffffffffu, acc[mt][0][r], 4);
                d[r] = __shfl_down_sync(0xffffffffu, acc[mt][2][r], 4);
            }
            float pm2 = (mt > 0) ? acc[(mt > 0 ? mt - 1 : 0)][0][2] : 0.f;
            float pm3 = (mt > 0) ? acc[(mt > 0 ? mt - 1 : 0)][0][3] : 0.f;
            cx[0] = __shfl_sync(0xffffffffu, pm2, 28 + q);
            cx[1] = __shfl_sync(0xffffffffu, pm3, 28 + q);
            cx[2] = __shfl_sync(0xffffffffu, acc[mt][0][0], 28 + q);
            cx[3] = __shfl_sync(0xffffffffu, acc[mt][0][1], 28 + q);
            ex[0] = __shfl_sync(0xffffffffu, acc[mt][2][2], q);
            ex[1] = __shfl_sync(0xffffffffu, acc[mt][2][3], q);
            float nm0 = (mt < 3) ? acc[(mt < 3 ? mt + 1 : 3)][2][0] : 0.f;
            float nm1 = (mt < 3) ? acc[(mt < 3 ? mt + 1 : 3)][2][1] : 0.f;
            ex[2] = __shfl_sync(0xffffffffu, nm0, q);
            ex[3] = __shfl_sync(0xffffffffu, nm1, q);
            int n_e = wid * 8 + 2 * q;
#pragma unroll
            for (int r = 0; r < 4; r++) {
                int n = n_e + (r & 1);
                float prev = g8 ? u[r] : ((mt == 0 && r < 2) ? sL[n] : cx[r]);
                float nxt  = (g8 < 7) ? d[r] : ((mt == 3 && r >= 2) ? sR[n] : ex[r]);
                float v = acc[mt][1][r] + prev + nxt + sBias[n];
                if (r & 1) { rso += v; rqo += v * v; }
                else       { rse += v; rqe += v * v; }
            }
        }
    }

    {
        float se = rse, so = rso, qe = rqe, qo = rqo;
#pragma unroll
        for (int sh = 4; sh <= 16; sh <<= 1) {
            se += __shfl_xor_sync(0xffffffffu, se, sh);
            so += __shfl_xor_sync(0xffffffffu, so, sh);
            qe += __shfl_xor_sync(0xffffffffu, qe, sh);
            qo += __shfl_xor_sync(0xffffffffu, qo, sh);
        }
        if (lane < 4) {
            int ne = g * 64 + wid * 8 + 2 * lane;
            atomicAdd(&g_s3[ne], se);
            atomicAdd(&g_s3[COUT + ne], qe);
            atomicAdd(&g_s3[ne + 1], so);
            atomicAdd(&g_s3[COUT + ne + 1], qo);
        }
    }
}

// ---------------- patch gather + encode ----------------
__global__ void patch_kernel(const float* __restrict__ image,
                             const int* __restrict__ a_xy, const int* __restrict__ p_xy,
                             const int* __restrict__ n_xy, float* __restrict__ out)
{
    int idx = blockIdx.x * blockDim.x + threadIdx.x;
    if (idx >= 3528) return;
    int which = idx / 1176;
    int r  = idx % 1176;
    int b  = r / 147, r2 = r % 147;
    int c  = r2 / 49, p = r2 % 49;
    int dy = p / 7, dx = p % 7;
    const int* xy = (which == 0) ? a_xy : (which == 1 ? p_xy : n_xy);
    int row = xy[b * 64 + 62], col = xy[b * 64 + 63];
    out[idx] = image[((b * 3 + c) * H_IMG + (row - 3 + dy)) * W_IMG + (col - 3 + dx)];
}

__global__ void encode_kernel(const int* __restrict__ n_xy,
                              const float* __restrict__ bn2_g, const float* __restrict__ bn2_b,
                              const float* __restrict__ conv3_b,
                              const float* __restrict__ bn3_g, const float* __restrict__ bn3_b,
                              float* __restrict__ out)
{
    int b = blockIdx.x, o = threadIdx.x;
    __shared__ float s_z2[576];
    int row = n_xy[b * 64 + 62], col = n_xy[b * 64 + 63];
    for (int i = threadIdx.x; i < 576; i += 128) {
        int c = i / 9, p = i % 9;
        int ky = p / 3 - 1, kx = p % 3 - 1;
        float mean = g_s2[c] * (1.f / NPIX);
        float var  = g_s2[64 + c] * (1.f / NPIX) - mean * mean;
        float is   = rsqrtf(var + BN_EPS);
        float sc   = bn2_g[c] * is;
        float sh   = bn2_b[c] - mean * sc;
        float v = g_y2[((b * 64 + c) * H_IMG + row + ky) * W_IMG + col + kx];
        v = v * sc + sh;
        v = v > 0.f ? v : 0.01f * v;
        s_z2[i] = v;
    }
    __syncthreads();
    float acc = conv3_b[o];
    for (int i = 0; i < 576; i++) acc = fmaf(s_z2[i], g_w3t[i * 128 + o], acc);
    float mean = g_s3[o] * (1.f / NPIX);
    float var  = g_s3[128 + o] * (1.f / NPIX) - mean * mean;
    float is   = rsqrtf(var + BN_EPS);
    float v = (acc - mean) * is * bn3_g[o] + bn3_b[o];
    v = v > 0.f ? v : 0.01f * v;
    out[3528 + b * 128 + o] = v;
}

extern "C" void kernel_launch(void* const* d_in, const int* in_sizes, int n_in,
                              void* d_out, int out_size) {
    const float* image = (const float*)d_in[0];
    const int*   a_xy  = (const int*)d_in[1];
    const int*   p_xy  = (const int*)d_in[2];
    const int*   n_xy  = (const int*)d_in[3];
    const float* w1  = (const float*)d_in[4];
    const float* b1  = (const float*)d_in[5];
    const float* g1  = (const float*)d_in[6];
    const float* be1 = (const float*)d_in[7];
    const float* w2  = (const float*)d_in[8];
    const float* b2  = (const float*)d_in[9];
    const float* g2  = (const float*)d_in[10];
    const float* be2 = (const float*)d_in[11];
    const float* w3  = (const float*)d_in[12];
    const float* b3  = (const float*)d_in[13];
    const float* g3  = (const float*)d_in[14];
    const float* be3 = (const float*)d_in[15];
    float* out = (float*)d_out;

    const int SM2P = 73728 + 4 * 9216 + 768;                 // 111,360 -> 2 CTAs/SM
    const int SM3P = 147456 + 4 * 17408 + 768;               // 217,856 -> 1 CTA/SM
    cudaFuncSetAttribute(conv2_persist_kernel,
                         cudaFuncAttributeMaxDynamicSharedMemorySize, SM2P);
    cudaFuncSetAttribute(conv3_persist_kernel,
                         cudaFuncAttributeMaxDynamicSharedMemorySize, SM3P);
    cudaFuncSetAttribute(prepass_kernel<32>,
                         cudaFuncAttributeMaxDynamicSharedMemorySize, 32 * 257 * 4);
    cudaFuncSetAttribute(prepass_kernel<64>,
                         cudaFuncAttributeMaxDynamicSharedMemorySize, 64 * 257 * 4);

    // conv kernels at ncu-capture slots 3 and 5.
    prep_all_kernel<<<546, 256>>>(w1, w2, w3);                            // 0
    conv1_kernel<<<dim3(16, 4, 8), 256>>>(image, b1);                     // 1
    prepass_kernel<32><<<2048, 256, 32 * 257 * 4>>>(g1, be1);             // 2
    conv2_persist_kernel<<<dim3(4, 32, 8), 128, SM2P>>>(b2);              // 3
    prepass_kernel<64><<<2048, 256, 64 * 257 * 4>>>(g2, be2);             // 4
    conv3_persist_kernel<<<dim3(4, 16, 16), 256, SM3P>>>(b3);             // 5
    patch_kernel<<<14, 256>>>(image, a_xy, p_xy, n_xy, out);              // 6
    encode_kernel<<<8, 128>>>(n_xy, g2, be2, b3, g3, be3, out);           // 7
}